// round 8
// baseline (speedup 1.0000x reference)
#include <cuda_runtime.h>
#include <cuda_bf16.h>

#define LLEN 1024
#define NB   64

// ---- device scratch (no allocations allowed) ----
__device__ float g_cat [NB * 192 * LLEN];
__device__ float g_dec [NB * 192 * LLEN];
__device__ float g_encU[NB * 64  * LLEN];
__device__ int   g_ids [NB];

// ------------------------------------------------------------------
__global__ void ids_kernel(const float* __restrict__ x) {
    int b = threadIdx.x;
    if (b < NB) g_ids[b] = (int)x[(long)b * (LLEN + 1) + LLEN];
}

// ------------------------------------------------------------------
__device__ __forceinline__ void mma_bf16(float* c, const unsigned* a,
                                         unsigned b0, unsigned b1) {
    asm volatile(
        "mma.sync.aligned.m16n8k16.row.col.f32.bf16.bf16.f32 "
        "{%0,%1,%2,%3}, {%4,%5,%6,%7}, {%8,%9}, {%0,%1,%2,%3};\n"
        : "+f"(c[0]), "+f"(c[1]), "+f"(c[2]), "+f"(c[3])
        : "r"(a[0]), "r"(a[1]), "r"(a[2]), "r"(a[3]), "r"(b0), "r"(b1));
}
__device__ __forceinline__ void ldsm4(unsigned* r, unsigned addr) {
    asm volatile("ldmatrix.sync.aligned.m8n8.x4.shared.b16 {%0,%1,%2,%3}, [%4];\n"
                 : "=r"(r[0]), "=r"(r[1]), "=r"(r[2]), "=r"(r[3]) : "r"(addr));
}
__device__ __forceinline__ void ldsm2(unsigned* r, unsigned addr) {
    asm volatile("ldmatrix.sync.aligned.m8n8.x2.shared.b16 {%0,%1}, [%2];\n"
                 : "=r"(r[0]), "=r"(r[1]) : "r"(addr));
}
__device__ __forceinline__ unsigned su32(const void* p) {
    return (unsigned)__cvta_generic_to_shared(p);
}
__device__ __forceinline__ void split_bf16(float v, __nv_bfloat16& hi, __nv_bfloat16& lo) {
    hi = __float2bfloat16(v);
    lo = __float2bfloat16(v - __bfloat162float(hi));
}

// ------------------------------------------------------------------
// Fused TCN block, K-fused GEMM form (bf16 hi/lo split, fp32 accum):
//   conv1: CIN -> 128 (k=5, dil DIL): GEMM K = 5*CIN (t folded into K),
//          computed in NCH co-chunks of CO; weights staged once per chunk
//          (coalesced), x staged once.
//   conv2: 128 -> 32 (1x1), partial-accumulated after each chunk.
// 512 thr = 16 warps, 2 CTAs/SM.
// conv1 warp grid: WM m-groups (m16) x NWN n-groups (WN = 8 or 16 wide).
// ------------------------------------------------------------------
template<int CIN, int DIL, int TIL, int CO>
__global__ void __launch_bounds__(512, 2)
block_gemm_kernel(const float* __restrict__ xin, long iss, int ics,
                  const float* __restrict__ w1, const float* __restrict__ b1,
                  const float* __restrict__ w2, const float* __restrict__ b2,
                  float* __restrict__ yout, long oss,
                  const int* __restrict__ ids,
                  long w1_cs, long b1_cs, long w2_cs, long b2_cs)
{
    constexpr int CINP = (CIN < 16) ? 16 : CIN;
    constexpr int KCH  = (CINP < 32) ? CINP : 32;  // ci per staging round
    constexpr int NKR  = CINP / KCH;               // staging rounds (1 or 2)
    constexpr int NKC  = KCH / 16;                 // 16-chunks per tap
    constexpr int NKF  = 5 * NKC;                  // k-chunks per round
    constexpr int SB   = CINP + 8;                 // xt row stride
    constexpr int SA   = 5 * KCH + 8;              // wa row stride
    constexpr int SHS  = CO + 8;                   // hs row stride
    constexpr int S2   = 136;                      // w2 row stride
    constexpr int XW   = TIL + 4 * DIL;
    constexpr int NCH  = 128 / CO;                 // co chunks
    constexpr int WM   = CO / 16;                  // conv1 m-groups
    constexpr int NWN  = 16 / WM;                  // conv1 n-groups
    constexpr int WN   = TIL / NWN;                // conv1 n per warp (8|16)
    constexpr int NT   = WN / 8;
    constexpr int NT2  = TIL / 64;                 // conv2 n-tiles per warp
    constexpr int ROWF = KCH * 5;                  // floats per co per round

    extern __shared__ __nv_bfloat16 smb[];
    __nv_bfloat16* xtH = smb;
    __nv_bfloat16* xtL = xtH + XW * SB;
    __nv_bfloat16* waH = xtL + XW * SB;
    __nv_bfloat16* waL = waH + CO * SA;
    __nv_bfloat16* hH  = waL + CO * SA;
    __nv_bfloat16* hL  = hH  + TIL * SHS;
    __nv_bfloat16* w2H = hL  + TIL * SHS;
    __nv_bfloat16* w2L = w2H + 32 * S2;
    float* b1s = (float*)(w2L + 32 * S2);    // 128
    float* b2s = b1s + 128;                  // 32

    const int b    = blockIdx.y;
    const int l0   = blockIdx.x * TIL;
    const int tid  = threadIdx.x;
    const int warp = tid >> 5;
    const int ln   = tid & 31;
    const int lq   = ln & 3;
    const int lg   = ln >> 2;
    const int lr   = ln & 7;
    const int lt   = ln >> 3;

    const float* w1p = w1;
    const float* b1p = b1;
    const float* w2p = w2;
    const float* b2p = b2;
    if (ids) {
        int c = ids[b];
        w1p += (long)c * w1_cs;  b1p += (long)c * b1_cs;
        w2p += (long)c * w2_cs;  b2p += (long)c * b2_cs;
    }

    // ---- stage x (transposed, split) ----
    const float* xb = xin + (long)b * iss;
    for (int ci = warp; ci < CINP; ci += 16) {
        for (int r = ln; r < XW; r += 32) {
            int pos = l0 - 2 * DIL + r;
            float v = (ci < CIN && pos >= 0 && pos < LLEN)
                      ? xb[(long)ci * ics + pos] : 0.f;
            __nv_bfloat16 hv, lv; split_bf16(v, hv, lv);
            xtH[r * SB + ci] = hv;
            xtL[r * SB + ci] = lv;
        }
    }
    // ---- stage W2 (split) + biases ----
    for (int i = tid; i < 32 * 128; i += 512) {
        int co = i >> 7, k = i & 127;
        __nv_bfloat16 hv, lv; split_bf16(w2p[i], hv, lv);
        w2H[co * S2 + k] = hv;
        w2L[co * S2 + k] = lv;
    }
    if (tid < 128) b1s[tid] = b1p[tid];
    if (tid < 32)  b2s[tid] = b2p[tid];

    const int wm  = warp % WM;      // conv1 m-group
    const int wn  = warp / WM;      // conv1 n-group
    const int wm2 = warp & 1;       // conv2 m-group
    const int wn2 = warp >> 1;      // conv2 n-group

    float a2[NT2][4];
    #pragma unroll
    for (int nt = 0; nt < NT2; nt++)
        #pragma unroll
        for (int q = 0; q < 4; q++) a2[nt][q] = 0.f;

    #pragma unroll
    for (int ch = 0; ch < NCH; ch++) {
        float acc[NT][4];
        #pragma unroll
        for (int nt = 0; nt < NT; nt++)
            #pragma unroll
            for (int q = 0; q < 4; q++) acc[nt][q] = 0.f;

        #pragma unroll
        for (int r = 0; r < NKR; r++) {
            __syncthreads();   // wa reusable (prev mma done; ch=0: x staged)
            // ---- stage W1 chunk (coalesced LDG), layout [co][t*KCH+ci] ----
            if constexpr (CIN >= 32) {
                for (int i = tid; i < CO * ROWF; i += 512) {
                    int co = i / ROWF, j = i - co * ROWF;
                    float v = w1p[(long)(ch * CO + co) * (CIN * 5) + r * ROWF + j];
                    int ci = j / 5, t = j - ci * 5;
                    __nv_bfloat16 hv, lv; split_bf16(v, hv, lv);
                    waH[co * SA + t * KCH + ci] = hv;
                    waL[co * SA + t * KCH + ci] = lv;
                }
            } else {
                for (int i = tid; i < CO * ROWF; i += 512) {
                    int co = i / ROWF, jk = i - co * ROWF;
                    int t = jk >> 4, ci = jk & 15;
                    float v = (ci < CIN)
                        ? w1p[(long)(ch * CO + co) * (CIN * 5) + ci * 5 + t] : 0.f;
                    __nv_bfloat16 hv, lv; split_bf16(v, hv, lv);
                    waH[co * SA + jk] = hv;
                    waL[co * SA + jk] = lv;
                }
            }
            __syncthreads();

            // ---- conv1 mma: NKF unbroken k-chunks ----
            #pragma unroll
            for (int kc = 0; kc < NKF; kc++) {
                const int t   = kc / NKC;
                const int kci = kc - t * NKC;
                unsigned ah[4], al[4];
                {
                    int arow = wm * 16 + lr + (lt & 1) * 8;
                    int acol = t * KCH + kci * 16 + (lt >> 1) * 8;
                    ldsm4(ah, su32(waH + arow * SA + acol));
                    ldsm4(al, su32(waL + arow * SA + acol));
                }
                unsigned bh[4], bl[4];
                if (NT == 2) {
                    int brow = wn * 16 + lr + (lt & 1) * 8 + t * DIL;
                    int bcol = r * KCH + kci * 16 + (lt >> 1) * 8;
                    ldsm4(bh, su32(xtH + brow * SB + bcol));
                    ldsm4(bl, su32(xtL + brow * SB + bcol));
                } else {
                    int brow = wn * 8 + lr + t * DIL;
                    int bcol = r * KCH + kci * 16 + ((ln >> 3) & 1) * 8;
                    ldsm2(bh, su32(xtH + brow * SB + bcol));
                    ldsm2(bl, su32(xtL + brow * SB + bcol));
                }
                #pragma unroll
                for (int nt = 0; nt < NT; nt++) {
                    unsigned bh0 = (NT == 2) ? bh[nt] : bh[0];
                    unsigned bh1 = (NT == 2) ? bh[nt + 2] : bh[1];
                    unsigned bl0 = (NT == 2) ? bl[nt] : bl[0];
                    unsigned bl1 = (NT == 2) ? bl[nt + 2] : bl[1];
                    mma_bf16(acc[nt], ah, bh0, bh1);
                    mma_bf16(acc[nt], ah, bl0, bl1);
                    mma_bf16(acc[nt], al, bh0, bh1);
                }
            }
        }

        // ---- conv1 epilogue: bias + relu + split -> hs[n][m] ----
        __syncthreads();   // prev conv2 hs reads done
        {
            int m = wm * 16 + lg;
            float bb0 = b1s[ch * CO + m], bb1 = b1s[ch * CO + m + 8];
            #pragma unroll
            for (int nt = 0; nt < NT; nt++) {
                int n = wn * WN + nt * 8 + 2 * lq;
                float* a = acc[nt];
                float v00 = a[0] + bb0, v01 = a[1] + bb0;
                float v10 = a[2] + bb1, v11 = a[3] + bb1;
                v00 = v00 > 0.f ? v00 : 0.f;  v01 = v01 > 0.f ? v01 : 0.f;
                v10 = v10 > 0.f ? v10 : 0.f;  v11 = v11 > 0.f ? v11 : 0.f;
                __nv_bfloat16 hv, lv;
                split_bf16(v00, hv, lv); hH[n * SHS + m] = hv;           hL[n * SHS + m] = lv;
                split_bf16(v01, hv, lv); hH[(n + 1) * SHS + m] = hv;     hL[(n + 1) * SHS + m] = lv;
                split_bf16(v10, hv, lv); hH[n * SHS + m + 8] = hv;       hL[n * SHS + m + 8] = lv;
                split_bf16(v11, hv, lv); hH[(n + 1) * SHS + m + 8] = hv; hL[(n + 1) * SHS + m + 8] = lv;
            }
        }
        __syncthreads();

        // ---- conv2 partial (k over this chunk's CO channels) ----
        #pragma unroll
        for (int kc = 0; kc < CO / 16; kc++) {
            unsigned ah[4], al[4];
            {
                int arow = wm2 * 16 + lr + (lt & 1) * 8;
                int acol = ch * CO + kc * 16 + (lt >> 1) * 8;
                ldsm4(ah, su32(w2H + arow * S2 + acol));
                ldsm4(al, su32(w2L + arow * S2 + acol));
            }
            unsigned bh[4], bl[4];
            if (NT2 == 2) {
                int brow = wn2 * 16 + lr + (lt & 1) * 8;
                int bcol = kc * 16 + (lt >> 1) * 8;
                ldsm4(bh, su32(hH + brow * SHS + bcol));
                ldsm4(bl, su32(hL + brow * SHS + bcol));
            } else {
                int brow = wn2 * 8 + lr;
                int bcol = kc * 16 + ((ln >> 3) & 1) * 8;
                ldsm2(bh, su32(hH + brow * SHS + bcol));
                ldsm2(bl, su32(hL + brow * SHS + bcol));
            }
            #pragma unroll
            for (int nt = 0; nt < NT2; nt++) {
                unsigned bh0 = (NT2 == 2) ? bh[nt] : bh[0];
                unsigned bh1 = (NT2 == 2) ? bh[nt + 2] : bh[1];
                unsigned bl0 = (NT2 == 2) ? bl[nt] : bl[0];
                unsigned bl1 = (NT2 == 2) ? bl[nt + 2] : bl[1];
                mma_bf16(a2[nt], ah, bh0, bh1);
                mma_bf16(a2[nt], ah, bl0, bl1);
                mma_bf16(a2[nt], al, bh0, bh1);
            }
        }
    }

    // ---- conv2 epilogue: bias + relu -> global ----
    float* yb = yout + (long)b * oss;
    {
        int row = wm2 * 16 + lg;
        float bb0 = b2s[row], bb1 = b2s[row + 8];
        #pragma unroll
        for (int nt = 0; nt < NT2; nt++) {
            int col = wn2 * (NT2 * 8) + nt * 8 + 2 * lq;
            float v0 = a2[nt][0] + bb0, v1 = a2[nt][1] + bb0;
            float v2 = a2[nt][2] + bb1, v3 = a2[nt][3] + bb1;
            v0 = v0 > 0.f ? v0 : 0.f;  v1 = v1 > 0.f ? v1 : 0.f;
            v2 = v2 > 0.f ? v2 : 0.f;  v3 = v3 > 0.f ? v3 : 0.f;
            *(float2*)&yb[(long)row * LLEN + l0 + col]       = make_float2(v0, v1);
            *(float2*)&yb[(long)(row + 8) * LLEN + l0 + col] = make_float2(v2, v3);
        }
    }
}

// ------------------------------------------------------------------
// compress conv (192 -> 64, 1x1) + avgpool(2) + nearest-upsample(2),
// tensor-core version. CTA = 64 l, 512 thr, 2 CTA/SM.
// warps: 4m(16) x 4n(16). Pool pairs are adjacent accumulator columns.
// ------------------------------------------------------------------
#define CTILE 64
__global__ void __launch_bounds__(512, 2)
comp_mma_kernel(const float* __restrict__ cat, const float* __restrict__ cw,
                const float* __restrict__ cb, float* __restrict__ out)
{
    constexpr int SA = 200;   // row stride (bf16) for both xt and wa (k = 192 + 8)

    extern __shared__ __nv_bfloat16 smb[];
    __nv_bfloat16* xtH = smb;                  // [64 l][200]
    __nv_bfloat16* xtL = xtH + 64 * SA;
    __nv_bfloat16* waH = xtL + 64 * SA;        // [64 co][200]
    __nv_bfloat16* waL = waH + 64 * SA;
    float* cbs = (float*)(waL + 64 * SA);      // 64

    const int b    = blockIdx.y;
    const int l0   = blockIdx.x * CTILE;
    const int tid  = threadIdx.x;
    const int warp = tid >> 5;
    const int ln   = tid & 31;
    const int lq   = ln & 3;
    const int lg   = ln >> 2;
    const int lr   = ln & 7;
    const int lt   = ln >> 3;
    const int wm   = warp & 3;
    const int wn   = warp >> 2;

    const float* catb = cat + (long)b * 192 * LLEN;
    for (int i = tid; i < 192 * CTILE; i += 512) {
        int ch = i >> 6, j = i & 63;
        float v = catb[(long)ch * LLEN + l0 + j];
        __nv_bfloat16 hv, lv; split_bf16(v, hv, lv);
        xtH[j * SA + ch] = hv;
        xtL[j * SA + ch] = lv;
    }
    for (int i = tid; i < 64 * 192; i += 512) {
        int co = i / 192, k = i - co * 192;
        __nv_bfloat16 hv, lv; split_bf16(cw[i], hv, lv);
        waH[co * SA + k] = hv;
        waL[co * SA + k] = lv;
    }
    if (tid < 64) cbs[tid] = cb[tid];
    __syncthreads();

    float acc[2][4];
    #pragma unroll
    for (int nt = 0; nt < 2; nt++)
        #pragma unroll
        for (int q = 0; q < 4; q++) acc[nt][q] = 0.f;

    #pragma unroll
    for (int kc = 0; kc < 12; kc++) {
        unsigned ah[4], al[4];
        {
            int arow = wm * 16 + lr + (lt & 1) * 8;
            int acol = kc * 16 + (lt >> 1) * 8;
            ldsm4(ah, su32(waH + arow * SA + acol));
            ldsm4(al, su32(waL + arow * SA + acol));
        }
        unsigned bh[4], bl[4];
        {
            int brow = wn * 16 + lr + (lt & 1) * 8;
            int bcol = kc * 16 + (lt >> 1) * 8;
            ldsm4(bh, su32(xtH + brow * SA + bcol));
            ldsm4(bl, su32(xtL + brow * SA + bcol));
        }
        #pragma unroll
        for (int nt = 0; nt < 2; nt++) {
            mma_bf16(acc[nt], ah, bh[nt], bh[nt + 2]);
            mma_bf16(acc[nt], ah, bl[nt], bl[nt + 2]);
            mma_bf16(acc[nt], al, bh[nt], bh[nt + 2]);
        }
    }

    // epilogue: bias, pool adjacent columns, write duplicated pair
    float* ob = out + (long)b * 64 * LLEN;
    {
        int m = wm * 16 + lg;
        float bb0 = cbs[m], bb1 = cbs[m + 8];
        #pragma unroll
        for (int nt = 0; nt < 2; nt++) {
            int n = wn * 16 + nt * 8 + 2 * lq;   // even
            float* a = acc[nt];
            float p0 = 0.5f * ((a[0] + bb0) + (a[1] + bb0));
            float p1 = 0.5f * ((a[2] + bb1) + (a[3] + bb1));
            *(float2*)&ob[(long)m * LLEN + l0 + n]       = make_float2(p0, p0);
            *(float2*)&ob[(long)(m + 8) * LLEN + l0 + n] = make_float2(p1, p1);
        }
    }
}

// ------------------------------------------------------------------
// final per-sample 1x1 conv: 192 -> 1. Grid (4, NB), 256 thr.
// ------------------------------------------------------------------
__global__ void __launch_bounds__(256, 1)
final_kernel(const float* __restrict__ dec, const float* __restrict__ cw,
             const float* __restrict__ cbv, float* __restrict__ out)
{
    __shared__ float ws[192];
    const int b   = blockIdx.y;
    const int tid = threadIdx.x;
    const int l   = blockIdx.x * 256 + tid;
    const int c   = g_ids[b];
    if (tid < 192) ws[tid] = cw[(long)c * 192 + tid];
    __syncthreads();
    float s = cbv[c];
    const float* db = dec + (long)b * 192 * LLEN + l;
    #pragma unroll 8
    for (int ch = 0; ch < 192; ch++) s = fmaf(ws[ch], db[(long)ch * LLEN], s);
    out[(long)b * LLEN + l] = s;
}

// ------------------------------------------------------------------
static constexpr int smem_gemm(int cin, int dil, int til, int co) {
    int cinp = cin < 16 ? 16 : cin;
    int kch  = cinp < 32 ? cinp : 32;
    int sb   = cinp + 8;
    int sa   = 5 * kch + 8;
    int shs  = co + 8;
    int xw   = til + 4 * dil;
    int elems = 2 * xw * sb + 2 * co * sa + 2 * til * shs + 2 * 32 * 136;
    return elems * 2 + 768;
}
static constexpr int SMEM_C = (4 * 64 * 200) * 2 + 256;

template<int CIN, int DIL, int TIL, int CO>
static void launch_block(const float* xin, long iss, int ics,
                         const float* w1, const float* b1,
                         const float* w2, const float* b2,
                         float* yout, long oss,
                         const int* ids, long w1cs, long b1cs, long w2cs, long b2cs)
{
    static bool attr_done = false;
    if (!attr_done) {
        cudaFuncSetAttribute(block_gemm_kernel<CIN, DIL, TIL, CO>,
                             cudaFuncAttributeMaxDynamicSharedMemorySize,
                             smem_gemm(CIN, DIL, TIL, CO));
        attr_done = true;
    }
    dim3 grid(LLEN / TIL, NB);
    block_gemm_kernel<CIN, DIL, TIL, CO><<<grid, 512, smem_gemm(CIN, DIL, TIL, CO)>>>(
        xin, iss, ics, w1, b1, w2, b2, yout, oss, ids, w1cs, b1cs, w2cs, b2cs);
}

extern "C" void kernel_launch(void* const* d_in, const int* in_sizes, int n_in,
                              void* d_out, int out_size)
{
    const float* x        = (const float*)d_in[0];
    const float* enc0_w1  = (const float*)d_in[1];
    const float* enc0_b1  = (const float*)d_in[2];
    const float* enc0_w2  = (const float*)d_in[3];
    const float* enc0_b2  = (const float*)d_in[4];
    const float* enc_w1   = (const float*)d_in[5];
    const float* enc_b1   = (const float*)d_in[6];
    const float* enc_w2   = (const float*)d_in[7];
    const float* enc_b2   = (const float*)d_in[8];
    const float* comp_w   = (const float*)d_in[9];
    const float* comp_b   = (const float*)d_in[10];
    const float* decf0_w1 = (const float*)d_in[11];
    const float* decf0_b1 = (const float*)d_in[12];
    const float* decf0_w2 = (const float*)d_in[13];
    const float* decf0_b2 = (const float*)d_in[14];
    const float* decf_w1  = (const float*)d_in[15];
    const float* decf_b1  = (const float*)d_in[16];
    const float* decf_w2  = (const float*)d_in[17];
    const float* decf_b2  = (const float*)d_in[18];
    const float* decv_w1  = (const float*)d_in[19];
    const float* decv_b1  = (const float*)d_in[20];
    const float* decv_w2  = (const float*)d_in[21];
    const float* decv_b2  = (const float*)d_in[22];
    const float* decv_cw  = (const float*)d_in[23];
    const float* decv_cb  = (const float*)d_in[24];
    float* out = (float*)d_out;

    float *cat, *dec, *encU;
    int* idsp;
    cudaGetSymbolAddress((void**)&cat,  g_cat);
    cudaGetSymbolAddress((void**)&dec,  g_dec);
    cudaGetSymbolAddress((void**)&encU, g_encU);
    cudaGetSymbolAddress((void**)&idsp, g_ids);

    static bool comp_attr = false;
    if (!comp_attr) {
        cudaFuncSetAttribute(comp_mma_kernel,
                             cudaFuncAttributeMaxDynamicSharedMemorySize, SMEM_C);
        comp_attr = true;
    }

    const long SS = (long)192 * LLEN;

    ids_kernel<<<1, 64>>>(x);

    // ---- encoder ----
    launch_block<1, 1, 128, 32>(x, (long)(LLEN + 1), 0,
                                enc0_w1, enc0_b1, enc0_w2, enc0_b2,
                                cat, SS, nullptr, 0, 0, 0, 0);
    launch_block<32, 2, 128, 32>(cat + 0 * 32 * LLEN, SS, LLEN,
                                 enc_w1 + 0 * 20480, enc_b1 + 0 * 128, enc_w2 + 0 * 4096, enc_b2 + 0 * 32,
                                 cat + 1 * 32 * LLEN, SS, nullptr, 0, 0, 0, 0);
    launch_block<32, 4, 128, 32>(cat + 1 * 32 * LLEN, SS, LLEN,
                                 enc_w1 + 1 * 20480, enc_b1 + 1 * 128, enc_w2 + 1 * 4096, enc_b2 + 1 * 32,
                                 cat + 2 * 32 * LLEN, SS, nullptr, 0, 0, 0, 0);
    launch_block<32, 8, 128, 32>(cat + 2 * 32 * LLEN, SS, LLEN,
                                 enc_w1 + 2 * 20480, enc_b1 + 2 * 128, enc_w2 + 2 * 4096, enc_b2 + 2 * 32,
                                 cat + 3 * 32 * LLEN, SS, nullptr, 0, 0, 0, 0);
    launch_block<32, 16, 128, 32>(cat + 3 * 32 * LLEN, SS, LLEN,
                                  enc_w1 + 3 * 20480, enc_b1 + 3 * 128, enc_w2 + 3 * 4096, enc_b2 + 3 * 32,
                                  cat + 4 * 32 * LLEN, SS, nullptr, 0, 0, 0, 0);
    launch_block<32, 32, 64, 64>(cat + 4 * 32 * LLEN, SS, LLEN,
                                 enc_w1 + 4 * 20480, enc_b1 + 4 * 128, enc_w2 + 4 * 4096, enc_b2 + 4 * 32,
                                 cat + 5 * 32 * LLEN, SS, nullptr, 0, 0, 0, 0);

    // ---- compress + pool + upsample (tensor cores) ----
    {
        dim3 grid(LLEN / CTILE, NB);
        comp_mma_kernel<<<grid, 512, SMEM_C>>>(cat, comp_w, comp_b, encU);
    }

    // ---- fixed decoder ----
    launch_block<64, 32, 64, 32>(encU, (long)64 * LLEN, LLEN,
                                 decf0_w1, decf0_b1, decf0_w2, decf0_b2,
                                 dec, SS, nullptr, 0, 0, 0, 0);
    launch_block<32, 16, 128, 32>(dec + 0 * 32 * LLEN, SS, LLEN,
                                  decf_w1 + 0 * 20480, decf_b1 + 0 * 128, decf_w2 + 0 * 4096, decf_b2 + 0 * 32,
                                  dec + 1 * 32 * LLEN, SS, nullptr, 0, 0, 0, 0);
    launch_block<32, 8, 128, 32>(dec + 1 * 32 * LLEN, SS, LLEN,
                                 decf_w1 + 1 * 20480, decf_b1 + 1 * 128, decf_w2 + 1 * 4096, decf_b2 + 1 * 32,
                                 dec + 2 * 32 * LLEN, SS, nullptr, 0, 0, 0, 0);
    launch_block<32, 4, 128, 32>(dec + 2 * 32 * LLEN, SS, LLEN,
                                 decf_w1 + 2 * 20480, decf_b1 + 2 * 128, decf_w2 + 2 * 4096, decf_b2 + 2 * 32,
                                 dec + 3 * 32 * LLEN, SS, nullptr, 0, 0, 0, 0);

    // ---- variable decoder: per-sample selected combination ----
    launch_block<32, 2, 128, 32>(dec + 3 * 32 * LLEN, SS, LLEN,
                                 decv_w1 + 0 * 20480, decv_b1 + 0 * 128, decv_w2 + 0 * 4096, decv_b2 + 0 * 32,
                                 dec + 4 * 32 * LLEN, SS,
                                 idsp, 40960, 256, 8192, 64);
    launch_block<32, 1, 128, 32>(dec + 4 * 32 * LLEN, SS, LLEN,
                                 decv_w1 + 1 * 20480, decv_b1 + 1 * 128, decv_w2 + 1 * 4096, decv_b2 + 1 * 32,
                                 dec + 5 * 32 * LLEN, SS,
                                 idsp, 40960, 256, 8192, 64);

    // ---- final 1x1 conv (per-sample weights) ----
    {
        dim3 grid(4, NB);
        final_kernel<<<grid, 256>>>(dec, decv_cw, decv_cb, out);
    }
}

// round 9
// speedup vs baseline: 1.1873x; 1.1873x over previous
#include <cuda_runtime.h>
#include <cuda_bf16.h>

#define LLEN 1024
#define NB   64

// ---- device scratch (no allocations allowed) ----
__device__ float g_cat [NB * 192 * LLEN];
__device__ float g_dec [NB * 192 * LLEN];
__device__ float g_encU[NB * 64  * LLEN];
__device__ int   g_ids [NB];

// ------------------------------------------------------------------
__global__ void ids_kernel(const float* __restrict__ x) {
    int b = threadIdx.x;
    if (b < NB) g_ids[b] = (int)x[(long)b * (LLEN + 1) + LLEN];
}

// ------------------------------------------------------------------
__device__ __forceinline__ void mma_bf16(float* c, const unsigned* a,
                                         unsigned b0, unsigned b1) {
    asm volatile(
        "mma.sync.aligned.m16n8k16.row.col.f32.bf16.bf16.f32 "
        "{%0,%1,%2,%3}, {%4,%5,%6,%7}, {%8,%9}, {%0,%1,%2,%3};\n"
        : "+f"(c[0]), "+f"(c[1]), "+f"(c[2]), "+f"(c[3])
        : "r"(a[0]), "r"(a[1]), "r"(a[2]), "r"(a[3]), "r"(b0), "r"(b1));
}
__device__ __forceinline__ void ldsm4(unsigned* r, unsigned addr) {
    asm volatile("ldmatrix.sync.aligned.m8n8.x4.shared.b16 {%0,%1,%2,%3}, [%4];\n"
                 : "=r"(r[0]), "=r"(r[1]), "=r"(r[2]), "=r"(r[3]) : "r"(addr));
}
__device__ __forceinline__ void ldsm2(unsigned* r, unsigned addr) {
    asm volatile("ldmatrix.sync.aligned.m8n8.x2.shared.b16 {%0,%1}, [%2];\n"
                 : "=r"(r[0]), "=r"(r[1]) : "r"(addr));
}
__device__ __forceinline__ unsigned su32(const void* p) {
    return (unsigned)__cvta_generic_to_shared(p);
}
__device__ __forceinline__ void split_bf16(float v, __nv_bfloat16& hi, __nv_bfloat16& lo) {
    hi = __float2bfloat16(v);
    lo = __float2bfloat16(v - __bfloat162float(hi));
}
__device__ __forceinline__ constexpr int ilog2c(int v) {
    return (v == 16) ? 4 : (v == 32) ? 5 : 6;
}

// ------------------------------------------------------------------
// Fused TCN block via tensor cores (bf16 hi/lo split, fp32 accum, LDSM,
// software-pipelined weight staging):
//   conv1: CIN -> 128 (k=5, dil DIL) + bias + relu, two co-halves of 64
//   conv2: 128 -> 32 (1x1) + bias + relu (accumulated across halves)
// CTA = TIL l, 512 thr = 16 warps, 2 CTAs/SM.
// ------------------------------------------------------------------
template<int CIN, int DIL, int TIL>
__global__ void __launch_bounds__(512, 2)
block_mma_kernel(const float* __restrict__ xin, long iss, int ics,
                 const float* __restrict__ w1, const float* __restrict__ b1,
                 const float* __restrict__ w2, const float* __restrict__ b2,
                 float* __restrict__ yout, long oss,
                 const int* __restrict__ ids,
                 long w1_cs, long b1_cs, long w2_cs, long b2_cs)
{
    constexpr int CINP = (CIN < 16) ? 16 : CIN;
    constexpr int LC   = ilog2c(CINP);
    constexpr int NK   = CINP / 16;
    constexpr int XW   = TIL + 4 * DIL;
    constexpr int SB   = CINP + 8;       // xt / wa row stride (bf16)
    constexpr int SH   = 72;             // hT row stride
    constexpr int S2   = 136;            // w2 row stride
    constexpr int NT   = TIL / 64;       // n-tiles per warp
    constexpr bool DBUF = (CIN <= 32);   // double-buffer weights?
    constexpr int NBUF = DBUF ? 2 : 1;
    constexpr int WBUF = 64 * SB;        // wa elems per plane per buffer
    constexpr int PW   = (64 * CINP) / 512;  // prefetch floats per thread

    extern __shared__ __nv_bfloat16 smb[];
    __nv_bfloat16* xtH = smb;
    __nv_bfloat16* xtL = xtH + XW * SB;
    __nv_bfloat16* waB = xtL + XW * SB;               // H planes then L planes
    __nv_bfloat16* hH  = waB + 2 * NBUF * WBUF;
    __nv_bfloat16* hL  = hH  + TIL * SH;
    __nv_bfloat16* w2H = hL  + TIL * SH;
    __nv_bfloat16* w2L = w2H + 32 * S2;
    float* b1s = (float*)(w2L + 32 * S2);    // 128
    float* b2s = b1s + 128;                  // 32

    const int b    = blockIdx.y;
    const int l0   = blockIdx.x * TIL;
    const int tid  = threadIdx.x;
    const int warp = tid >> 5;
    const int ln   = tid & 31;
    const int lq   = ln & 3;
    const int lg   = ln >> 2;
    const int lr   = ln & 7;
    const int lt   = ln >> 3;

    const float* w1p = w1;
    const float* b1p = b1;
    const float* w2p = w2;
    const float* b2p = b2;
    if (ids) {
        int c = ids[b];
        w1p += (long)c * w1_cs;  b1p += (long)c * b1_cs;
        w2p += (long)c * w2_cs;  b2p += (long)c * b2_cs;
    }

    // prefetch lane decode (same for every t)
    int pco[PW], pci[PW];
    #pragma unroll
    for (int j = 0; j < PW; j++) {
        int i = tid + j * 512;
        pco[j] = i >> LC;
        pci[j] = i & (CINP - 1);
    }

    // ---- stage x (transposed, split) ----
    const float* xb = xin + (long)b * iss;
    for (int ci = warp; ci < CINP; ci += 16) {
        for (int r = ln; r < XW; r += 32) {
            int pos = l0 - 2 * DIL + r;
            float v = (ci < CIN && pos >= 0 && pos < LLEN)
                      ? xb[(long)ci * ics + pos] : 0.f;
            __nv_bfloat16 hv, lv; split_bf16(v, hv, lv);
            xtH[r * SB + ci] = hv;
            xtL[r * SB + ci] = lv;
        }
    }
    // ---- stage W2 (split) + biases ----
    for (int i = tid; i < 32 * 128; i += 512) {
        int co = i >> 7, k = i & 127;
        __nv_bfloat16 hv, lv; split_bf16(w2p[i], hv, lv);
        w2H[co * S2 + k] = hv;
        w2L[co * S2 + k] = lv;
    }
    if (tid < 128) b1s[tid] = b1p[tid];
    if (tid < 32)  b2s[tid] = b2p[tid];

    const int wm  = warp >> 3;
    const int wn  = warp & 7;
    const int wm2 = warp & 1;
    const int wn2 = warp >> 1;

    float a2[NT][4];
    #pragma unroll
    for (int nt = 0; nt < NT; nt++)
        #pragma unroll
        for (int q = 0; q < 4; q++) a2[nt][q] = 0.f;

    #pragma unroll
    for (int half = 0; half < 2; half++) {
        const int coB = half * 64;

        float acc[2][NT][4];
        #pragma unroll
        for (int mt = 0; mt < 2; mt++)
            #pragma unroll
            for (int nt = 0; nt < NT; nt++)
                #pragma unroll
                for (int q = 0; q < 4; q++) acc[mt][nt][q] = 0.f;

        // ---- preload t=0 weights ----
        {
            float pre[PW];
            #pragma unroll
            for (int j = 0; j < PW; j++)
                pre[j] = (pci[j] < CIN)
                    ? w1p[(long)(coB + pco[j]) * (CIN * 5) + pci[j] * 5 + 0] : 0.f;
            __syncthreads();   // wa[buf0] reusable (prev half / prev conv2 done)
            #pragma unroll
            for (int j = 0; j < PW; j++) {
                __nv_bfloat16 hv, lv; split_bf16(pre[j], hv, lv);
                waB[pco[j] * SB + pci[j]] = hv;
                waB[NBUF * WBUF + pco[j] * SB + pci[j]] = lv;
            }
            __syncthreads();
        }

        #pragma unroll
        for (int t = 0; t < 5; t++) {
            // prefetch next tap's weights into registers (overlaps mma)
            float nxt[PW];
            if (t < 4) {
                #pragma unroll
                for (int j = 0; j < PW; j++)
                    nxt[j] = (pci[j] < CIN)
                        ? w1p[(long)(coB + pco[j]) * (CIN * 5) + pci[j] * 5 + (t + 1)]
                        : 0.f;
            }

            const __nv_bfloat16* wH = waB + (DBUF ? (t & 1) * WBUF : 0);
            const __nv_bfloat16* wL = wH + NBUF * WBUF;

            #pragma unroll
            for (int kc = 0; kc < NK; kc++) {
                unsigned ah[2][4], al[2][4];
                #pragma unroll
                for (int mt = 0; mt < 2; mt++) {
                    int arow = wm * 32 + mt * 16 + lr + (lt & 1) * 8;
                    int acol = kc * 16 + (lt >> 1) * 8;
                    ldsm4(ah[mt], su32(wH + arow * SB + acol));
                    ldsm4(al[mt], su32(wL + arow * SB + acol));
                }
                unsigned bh[4], bl[4];
                if (NT == 2) {
                    int brow = wn * 16 + lr + (lt & 1) * 8 + t * DIL;
                    int bcol = kc * 16 + (lt >> 1) * 8;
                    ldsm4(bh, su32(xtH + brow * SB + bcol));
                    ldsm4(bl, su32(xtL + brow * SB + bcol));
                } else {
                    int brow = wn * 8 + lr + t * DIL;
                    int bcol = kc * 16 + ((ln >> 3) & 1) * 8;
                    ldsm2(bh, su32(xtH + brow * SB + bcol));
                    ldsm2(bl, su32(xtL + brow * SB + bcol));
                }
                #pragma unroll
                for (int nt = 0; nt < NT; nt++) {
                    unsigned bh0 = (NT == 2) ? bh[nt] : bh[0];
                    unsigned bh1 = (NT == 2) ? bh[nt + 2] : bh[1];
                    unsigned bl0 = (NT == 2) ? bl[nt] : bl[0];
                    unsigned bl1 = (NT == 2) ? bl[nt + 2] : bl[1];
                    #pragma unroll
                    for (int mt = 0; mt < 2; mt++) {
                        mma_bf16(acc[mt][nt], ah[mt], bh0, bh1);
                        mma_bf16(acc[mt][nt], ah[mt], bl0, bl1);
                        mma_bf16(acc[mt][nt], al[mt], bh0, bh1);
                    }
                }
            }

            if (t < 4) {
                if (!DBUF) __syncthreads();   // single buffer: wait for readers
                __nv_bfloat16* dH = waB + (DBUF ? ((t + 1) & 1) * WBUF : 0);
                __nv_bfloat16* dL = dH + NBUF * WBUF;
                #pragma unroll
                for (int j = 0; j < PW; j++) {
                    __nv_bfloat16 hv, lv; split_bf16(nxt[j], hv, lv);
                    dH[pco[j] * SB + pci[j]] = hv;
                    dL[pco[j] * SB + pci[j]] = lv;
                }
                __syncthreads();
            }
        }

        // ---- conv1 epilogue: bias + relu + split -> hT (l-major) ----
        __syncthreads();   // all mma done before hT overwrite (hT read last half)
        #pragma unroll
        for (int mt = 0; mt < 2; mt++) {
            int m = wm * 32 + mt * 16 + lg;
            float bb0 = b1s[coB + m], bb1 = b1s[coB + m + 8];
            #pragma unroll
            for (int nt = 0; nt < NT; nt++) {
                int n = ((NT == 2) ? wn * 16 + nt * 8 : wn * 8) + 2 * lq;
                float* a = acc[mt][nt];
                float v00 = a[0] + bb0, v01 = a[1] + bb0;
                float v10 = a[2] + bb1, v11 = a[3] + bb1;
                v00 = v00 > 0.f ? v00 : 0.f;  v01 = v01 > 0.f ? v01 : 0.f;
                v10 = v10 > 0.f ? v10 : 0.f;  v11 = v11 > 0.f ? v11 : 0.f;
                __nv_bfloat16 hv, lv;
                split_bf16(v00, hv, lv); hH[n * SH + m] = hv;           hL[n * SH + m] = lv;
                split_bf16(v01, hv, lv); hH[(n + 1) * SH + m] = hv;     hL[(n + 1) * SH + m] = lv;
                split_bf16(v10, hv, lv); hH[n * SH + m + 8] = hv;       hL[n * SH + m + 8] = lv;
                split_bf16(v11, hv, lv); hH[(n + 1) * SH + m + 8] = hv; hL[(n + 1) * SH + m + 8] = lv;
            }
        }
        __syncthreads();

        // ---- conv2 partial (k over this half's 64 channels) ----
        #pragma unroll
        for (int kc = 0; kc < 4; kc++) {
            unsigned ah[4], al[4];
            {
                int arow = wm2 * 16 + lr + (lt & 1) * 8;
                int acol = coB + kc * 16 + (lt >> 1) * 8;
                ldsm4(ah, su32(w2H + arow * S2 + acol));
                ldsm4(al, su32(w2L + arow * S2 + acol));
            }
            unsigned bh[4], bl[4];
            if (NT == 2) {
                int brow = wn2 * 16 + lr + (lt & 1) * 8;
                int bcol = kc * 16 + (lt >> 1) * 8;
                ldsm4(bh, su32(hH + brow * SH + bcol));
                ldsm4(bl, su32(hL + brow * SH + bcol));
            } else {
                int brow = wn2 * 8 + lr;
                int bcol = kc * 16 + ((ln >> 3) & 1) * 8;
                ldsm2(bh, su32(hH + brow * SH + bcol));
                ldsm2(bl, su32(hL + brow * SH + bcol));
            }
            #pragma unroll
            for (int nt = 0; nt < NT; nt++) {
                unsigned bh0 = (NT == 2) ? bh[nt] : bh[0];
                unsigned bh1 = (NT == 2) ? bh[nt + 2] : bh[1];
                unsigned bl0 = (NT == 2) ? bl[nt] : bl[0];
                unsigned bl1 = (NT == 2) ? bl[nt + 2] : bl[1];
                mma_bf16(a2[nt], ah, bh0, bh1);
                mma_bf16(a2[nt], ah, bl0, bl1);
                mma_bf16(a2[nt], al, bh0, bh1);
            }
        }
    }

    // ---- conv2 epilogue: bias + relu -> global ----
    float* yb = yout + (long)b * oss;
    {
        int row = wm2 * 16 + lg;
        float bb0 = b2s[row], bb1 = b2s[row + 8];
        #pragma unroll
        for (int nt = 0; nt < NT; nt++) {
            int col = ((NT == 2) ? wn2 * 16 + nt * 8 : wn2 * 8) + 2 * lq;
            float v0 = a2[nt][0] + bb0, v1 = a2[nt][1] + bb0;
            float v2 = a2[nt][2] + bb1, v3 = a2[nt][3] + bb1;
            v0 = v0 > 0.f ? v0 : 0.f;  v1 = v1 > 0.f ? v1 : 0.f;
            v2 = v2 > 0.f ? v2 : 0.f;  v3 = v3 > 0.f ? v3 : 0.f;
            *(float2*)&yb[(long)row * LLEN + l0 + col]       = make_float2(v0, v1);
            *(float2*)&yb[(long)(row + 8) * LLEN + l0 + col] = make_float2(v2, v3);
        }
    }
}

// ------------------------------------------------------------------
// compress conv (192 -> 64, 1x1) + avgpool(2) + nearest-upsample(2),
// tensor-core version. CTA = 64 l, 512 thr, 2 CTA/SM.
// warps: 4m(16) x 4n(16). Pool pairs are adjacent accumulator columns.
// ------------------------------------------------------------------
#define CTILE 64
__global__ void __launch_bounds__(512, 2)
comp_mma_kernel(const float* __restrict__ cat, const float* __restrict__ cw,
                const float* __restrict__ cb, float* __restrict__ out)
{
    constexpr int SA = 200;   // row stride (bf16): k = 192 + 8

    extern __shared__ __nv_bfloat16 smb[];
    __nv_bfloat16* xtH = smb;                  // [64 l][200]
    __nv_bfloat16* xtL = xtH + 64 * SA;
    __nv_bfloat16* waH = xtL + 64 * SA;        // [64 co][200]
    __nv_bfloat16* waL = waH + 64 * SA;
    float* cbs = (float*)(waL + 64 * SA);      // 64

    const int b    = blockIdx.y;
    const int l0   = blockIdx.x * CTILE;
    const int tid  = threadIdx.x;
    const int warp = tid >> 5;
    const int ln   = tid & 31;
    const int lq   = ln & 3;
    const int lg   = ln >> 2;
    const int lr   = ln & 7;
    const int lt   = ln >> 3;
    const int wm   = warp & 3;
    const int wn   = warp >> 2;

    const float* catb = cat + (long)b * 192 * LLEN;
    for (int i = tid; i < 192 * CTILE; i += 512) {
        int ch = i >> 6, j = i & 63;
        float v = catb[(long)ch * LLEN + l0 + j];
        __nv_bfloat16 hv, lv; split_bf16(v, hv, lv);
        xtH[j * SA + ch] = hv;
        xtL[j * SA + ch] = lv;
    }
    for (int i = tid; i < 64 * 192; i += 512) {
        int co = i / 192, k = i - co * 192;
        __nv_bfloat16 hv, lv; split_bf16(cw[i], hv, lv);
        waH[co * SA + k] = hv;
        waL[co * SA + k] = lv;
    }
    if (tid < 64) cbs[tid] = cb[tid];
    __syncthreads();

    float acc[2][4];
    #pragma unroll
    for (int nt = 0; nt < 2; nt++)
        #pragma unroll
        for (int q = 0; q < 4; q++) acc[nt][q] = 0.f;

    #pragma unroll
    for (int kc = 0; kc < 12; kc++) {
        unsigned ah[4], al[4];
        {
            int arow = wm * 16 + lr + (lt & 1) * 8;
            int acol = kc * 16 + (lt >> 1) * 8;
            ldsm4(ah, su32(waH + arow * SA + acol));
            ldsm4(al, su32(waL + arow * SA + acol));
        }
        unsigned bh[4], bl[4];
        {
            int brow = wn * 16 + lr + (lt & 1) * 8;
            int bcol = kc * 16 + (lt >> 1) * 8;
            ldsm4(bh, su32(xtH + brow * SA + bcol));
            ldsm4(bl, su32(xtL + brow * SA + bcol));
        }
        #pragma unroll
        for (int nt = 0; nt < 2; nt++) {
            mma_bf16(acc[nt], ah, bh[nt], bh[nt + 2]);
            mma_bf16(acc[nt], ah, bl[nt], bl[nt + 2]);
            mma_bf16(acc[nt], al, bh[nt], bh[nt + 2]);
        }
    }

    // epilogue: bias, pool adjacent columns, write duplicated pair
    float* ob = out + (long)b * 64 * LLEN;
    {
        int m = wm * 16 + lg;
        float bb0 = cbs[m], bb1 = cbs[m + 8];
        #pragma unroll
        for (int nt = 0; nt < 2; nt++) {
            int n = wn * 16 + nt * 8 + 2 * lq;   // even
            float* a = acc[nt];
            float p0 = 0.5f * ((a[0] + bb0) + (a[1] + bb0));
            float p1 = 0.5f * ((a[2] + bb1) + (a[3] + bb1));
            *(float2*)&ob[(long)m * LLEN + l0 + n]       = make_float2(p0, p0);
            *(float2*)&ob[(long)(m + 8) * LLEN + l0 + n] = make_float2(p1, p1);
        }
    }
}

// ------------------------------------------------------------------
// final per-sample 1x1 conv: 192 -> 1. Grid (4, NB), 256 thr.
// ------------------------------------------------------------------
__global__ void __launch_bounds__(256, 1)
final_kernel(const float* __restrict__ dec, const float* __restrict__ cw,
             const float* __restrict__ cbv, float* __restrict__ out)
{
    __shared__ float ws[192];
    const int b   = blockIdx.y;
    const int tid = threadIdx.x;
    const int l   = blockIdx.x * 256 + tid;
    const int c   = g_ids[b];
    if (tid < 192) ws[tid] = cw[(long)c * 192 + tid];
    __syncthreads();
    float s = cbv[c];
    const float* db = dec + (long)b * 192 * LLEN + l;
    #pragma unroll 8
    for (int ch = 0; ch < 192; ch++) s = fmaf(ws[ch], db[(long)ch * LLEN], s);
    out[(long)b * LLEN + l] = s;
}

// ------------------------------------------------------------------
static constexpr int smem_mma(int cin, int dil, int til) {
    int cinp = cin < 16 ? 16 : cin;
    int sb   = cinp + 8;
    int nbuf = (cin <= 32) ? 2 : 1;
    int xw   = til + 4 * dil;
    int elems = 2 * xw * sb + 2 * nbuf * 64 * sb + 2 * til * 72 + 2 * 32 * 136;
    return elems * 2 + 160 * 4;
}
static constexpr int SMEM_C = (4 * 64 * 200) * 2 + 256;

template<int CIN, int DIL, int TIL>
static void launch_block(const float* xin, long iss, int ics,
                         const float* w1, const float* b1,
                         const float* w2, const float* b2,
                         float* yout, long oss,
                         const int* ids, long w1cs, long b1cs, long w2cs, long b2cs)
{
    static bool attr_done = false;
    if (!attr_done) {
        cudaFuncSetAttribute(block_mma_kernel<CIN, DIL, TIL>,
                             cudaFuncAttributeMaxDynamicSharedMemorySize,
                             smem_mma(CIN, DIL, TIL));
        attr_done = true;
    }
    dim3 grid(LLEN / TIL, NB);
    block_mma_kernel<CIN, DIL, TIL><<<grid, 512, smem_mma(CIN, DIL, TIL)>>>(
        xin, iss, ics, w1, b1, w2, b2, yout, oss, ids, w1cs, b1cs, w2cs, b2cs);
}

extern "C" void kernel_launch(void* const* d_in, const int* in_sizes, int n_in,
                              void* d_out, int out_size)
{
    const float* x        = (const float*)d_in[0];
    const float* enc0_w1  = (const float*)d_in[1];
    const float* enc0_b1  = (const float*)d_in[2];
    const float* enc0_w2  = (const float*)d_in[3];
    const float* enc0_b2  = (const float*)d_in[4];
    const float* enc_w1   = (const float*)d_in[5];
    const float* enc_b1   = (const float*)d_in[6];
    const float* enc_w2   = (const float*)d_in[7];
    const float* enc_b2   = (const float*)d_in[8];
    const float* comp_w   = (const float*)d_in[9];
    const float* comp_b   = (const float*)d_in[10];
    const float* decf0_w1 = (const float*)d_in[11];
    const float* decf0_b1 = (const float*)d_in[12];
    const float* decf0_w2 = (const float*)d_in[13];
    const float* decf0_b2 = (const float*)d_in[14];
    const float* decf_w1  = (const float*)d_in[15];
    const float* decf_b1  = (const float*)d_in[16];
    const float* decf_w2  = (const float*)d_in[17];
    const float* decf_b2  = (const float*)d_in[18];
    const float* decv_w1  = (const float*)d_in[19];
    const float* decv_b1  = (const float*)d_in[20];
    const float* decv_w2  = (const float*)d_in[21];
    const float* decv_b2  = (const float*)d_in[22];
    const float* decv_cw  = (const float*)d_in[23];
    const float* decv_cb  = (const float*)d_in[24];
    float* out = (float*)d_out;

    float *cat, *dec, *encU;
    int* idsp;
    cudaGetSymbolAddress((void**)&cat,  g_cat);
    cudaGetSymbolAddress((void**)&dec,  g_dec);
    cudaGetSymbolAddress((void**)&encU, g_encU);
    cudaGetSymbolAddress((void**)&idsp, g_ids);

    static bool comp_attr = false;
    if (!comp_attr) {
        cudaFuncSetAttribute(comp_mma_kernel,
                             cudaFuncAttributeMaxDynamicSharedMemorySize, SMEM_C);
        comp_attr = true;
    }

    const long SS = (long)192 * LLEN;

    ids_kernel<<<1, 64>>>(x);

    // ---- encoder ----
    launch_block<1, 1, 128>(x, (long)(LLEN + 1), 0,
                            enc0_w1, enc0_b1, enc0_w2, enc0_b2,
                            cat, SS, nullptr, 0, 0, 0, 0);
    launch_block<32, 2, 128>(cat + 0 * 32 * LLEN, SS, LLEN,
                             enc_w1 + 0 * 20480, enc_b1 + 0 * 128, enc_w2 + 0 * 4096, enc_b2 + 0 * 32,
                             cat + 1 * 32 * LLEN, SS, nullptr, 0, 0, 0, 0);
    launch_block<32, 4, 128>(cat + 1 * 32 * LLEN, SS, LLEN,
                             enc_w1 + 1 * 20480, enc_b1 + 1 * 128, enc_w2 + 1 * 4096, enc_b2 + 1 * 32,
                             cat + 2 * 32 * LLEN, SS, nullptr, 0, 0, 0, 0);
    launch_block<32, 8, 128>(cat + 2 * 32 * LLEN, SS, LLEN,
                             enc_w1 + 2 * 20480, enc_b1 + 2 * 128, enc_w2 + 2 * 4096, enc_b2 + 2 * 32,
                             cat + 3 * 32 * LLEN, SS, nullptr, 0, 0, 0, 0);
    launch_block<32, 16, 128>(cat + 3 * 32 * LLEN, SS, LLEN,
                              enc_w1 + 3 * 20480, enc_b1 + 3 * 128, enc_w2 + 3 * 4096, enc_b2 + 3 * 32,
                              cat + 4 * 32 * LLEN, SS, nullptr, 0, 0, 0, 0);
    launch_block<32, 32, 64>(cat + 4 * 32 * LLEN, SS, LLEN,
                             enc_w1 + 4 * 20480, enc_b1 + 4 * 128, enc_w2 + 4 * 4096, enc_b2 + 4 * 32,
                             cat + 5 * 32 * LLEN, SS, nullptr, 0, 0, 0, 0);

    // ---- compress + pool + upsample (tensor cores) ----
    {
        dim3 grid(LLEN / CTILE, NB);
        comp_mma_kernel<<<grid, 512, SMEM_C>>>(cat, comp_w, comp_b, encU);
    }

    // ---- fixed decoder ----
    launch_block<64, 32, 64>(encU, (long)64 * LLEN, LLEN,
                             decf0_w1, decf0_b1, decf0_w2, decf0_b2,
                             dec, SS, nullptr, 0, 0, 0, 0);
    launch_block<32, 16, 128>(dec + 0 * 32 * LLEN, SS, LLEN,
                              decf_w1 + 0 * 20480, decf_b1 + 0 * 128, decf_w2 + 0 * 4096, decf_b2 + 0 * 32,
                              dec + 1 * 32 * LLEN, SS, nullptr, 0, 0, 0, 0);
    launch_block<32, 8, 128>(dec + 1 * 32 * LLEN, SS, LLEN,
                             decf_w1 + 1 * 20480, decf_b1 + 1 * 128, decf_w2 + 1 * 4096, decf_b2 + 1 * 32,
                             dec + 2 * 32 * LLEN, SS, nullptr, 0, 0, 0, 0);
    launch_block<32, 4, 128>(dec + 2 * 32 * LLEN, SS, LLEN,
                             decf_w1 + 2 * 20480, decf_b1 + 2 * 128, decf_w2 + 2 * 4096, decf_b2 + 2 * 32,
                             dec + 3 * 32 * LLEN, SS, nullptr, 0, 0, 0, 0);

    // ---- variable decoder: per-sample selected combination ----
    launch_block<32, 2, 128>(dec + 3 * 32 * LLEN, SS, LLEN,
                             decv_w1 + 0 * 20480, decv_b1 + 0 * 128, decv_w2 + 0 * 4096, decv_b2 + 0 * 32,
                             dec + 4 * 32 * LLEN, SS,
                             idsp, 40960, 256, 8192, 64);
    launch_block<32, 1, 128>(dec + 4 * 32 * LLEN, SS, LLEN,
                             decv_w1 + 1 * 20480, decv_b1 + 1 * 128, decv_w2 + 1 * 4096, decv_b2 + 1 * 32,
                             dec + 5 * 32 * LLEN, SS,
                             idsp, 40960, 256, 8192, 64);

    // ---- final 1x1 conv (per-sample weights) ----
    {
        dim3 grid(4, NB);
        final_kernel<<<grid, 256>>>(dec, decv_cw, decv_cb, out);
    }
}

// round 10
// speedup vs baseline: 1.3543x; 1.1407x over previous
#include <cuda_runtime.h>
#include <cuda_bf16.h>

#define LLEN 1024
#define NB   64
#define PLN  (LLEN * 32)          // one 32-ch plane, elems
#define SS32 (6 * PLN)            // cat/dec sample stride (elems)
#define SSU  (LLEN * 64)          // encU sample stride

// ---- device scratch (no allocations allowed) ----
__device__ __nv_bfloat16 g_catH[NB * SS32], g_catL[NB * SS32];
__device__ __nv_bfloat16 g_decH[NB * SS32], g_decL[NB * SS32];
__device__ __nv_bfloat16 g_encUH[NB * SSU], g_encUL[NB * SSU];
__device__ __nv_bfloat16 g_w1H[378880], g_w1L[378880];
__device__ __nv_bfloat16 g_w2H[86016],  g_w2L[86016];
__device__ int g_ids[NB];

__constant__ int c_OFF1[18] = {
    0, 10240, 30720, 51200, 71680, 92160, 112640,
    153600, 174080, 194560,
    215040, 235520, 256000, 276480, 296960, 317440, 337920, 358400};

// ------------------------------------------------------------------
__global__ void ids_kernel(const float* __restrict__ x) {
    int b = threadIdx.x;
    if (b < NB) g_ids[b] = (int)x[(long)b * (LLEN + 1) + LLEN];
}

__device__ __forceinline__ void mma_bf16(float* c, const unsigned* a,
                                         unsigned b0, unsigned b1) {
    asm volatile(
        "mma.sync.aligned.m16n8k16.row.col.f32.bf16.bf16.f32 "
        "{%0,%1,%2,%3}, {%4,%5,%6,%7}, {%8,%9}, {%0,%1,%2,%3};\n"
        : "+f"(c[0]), "+f"(c[1]), "+f"(c[2]), "+f"(c[3])
        : "r"(a[0]), "r"(a[1]), "r"(a[2]), "r"(a[3]), "r"(b0), "r"(b1));
}
__device__ __forceinline__ void ldsm4(unsigned* r, unsigned addr) {
    asm volatile("ldmatrix.sync.aligned.m8n8.x4.shared.b16 {%0,%1,%2,%3}, [%4];\n"
                 : "=r"(r[0]), "=r"(r[1]), "=r"(r[2]), "=r"(r[3]) : "r"(addr));
}
__device__ __forceinline__ void ldsm2(unsigned* r, unsigned addr) {
    asm volatile("ldmatrix.sync.aligned.m8n8.x2.shared.b16 {%0,%1}, [%2];\n"
                 : "=r"(r[0]), "=r"(r[1]) : "r"(addr));
}
__device__ __forceinline__ unsigned su32(const void* p) {
    return (unsigned)__cvta_generic_to_shared(p);
}
__device__ __forceinline__ void split_bf16(float v, __nv_bfloat16& hi, __nv_bfloat16& lo) {
    hi = __float2bfloat16(v);
    lo = __float2bfloat16(v - __bfloat162float(hi));
}
__device__ __forceinline__ constexpr int ilog2c(int v) {
    return (v == 8) ? 3 : (v == 16) ? 4 : (v == 32) ? 5 : 6;
}

// ------------------------------------------------------------------
// prep kernels: split all weights into bf16 hi/lo planes, staging layout
// w1 layout per layer: e = ((half*5 + t)*64 + co)*CINP + ci
// ------------------------------------------------------------------
__global__ void prep_w1(const float* __restrict__ enc0, const float* __restrict__ enc,
                        const float* __restrict__ decf0, const float* __restrict__ decf,
                        const float* __restrict__ decv)
{
    int L = blockIdx.y;
    int cinv = (L == 0) ? 1 : ((L == 6) ? 64 : 32);
    int cinp = cinv < 16 ? 16 : cinv;
    int total = 640 * cinp;
    int e = blockIdx.x * 256 + threadIdx.x;
    if (e >= total) return;
    int ci  = e % cinp;
    int tmp = e / cinp;
    int co  = tmp & 63;  tmp >>= 6;
    int t   = tmp % 5, half = tmp / 5;
    const float* src;
    if (L == 0) src = enc0;
    else if (L <= 5) src = enc + (L - 1) * 20480;
    else if (L == 6) src = decf0;
    else if (L <= 9) src = decf + (L - 7) * 20480;
    else src = decv + (L - 10) * 20480;
    float v = (ci < cinv) ? src[(long)(half * 64 + co) * (cinv * 5) + ci * 5 + t] : 0.f;
    __nv_bfloat16 h, l; split_bf16(v, h, l);
    g_w1H[c_OFF1[L] + e] = h;
    g_w1L[c_OFF1[L] + e] = l;
}

__global__ void prep_w2(const float* __restrict__ enc0, const float* __restrict__ enc,
                        const float* __restrict__ decf0, const float* __restrict__ decf,
                        const float* __restrict__ decv, const float* __restrict__ comp)
{
    int L = blockIdx.y;
    int sz = (L == 18) ? 12288 : 4096;
    int e = blockIdx.x * 256 + threadIdx.x;
    if (e >= sz) return;
    const float* src;
    if (L == 0) src = enc0;
    else if (L <= 5) src = enc + (L - 1) * 4096;
    else if (L == 6) src = decf0;
    else if (L <= 9) src = decf + (L - 7) * 4096;
    else if (L <= 17) src = decv + (L - 10) * 4096;
    else src = comp;
    long off = (L == 18) ? 73728 : (long)L * 4096;
    __nv_bfloat16 h, l; split_bf16(src[e], h, l);
    g_w2H[off + e] = h;
    g_w2L[off + e] = l;
}

// ------------------------------------------------------------------
// Fused TCN block (bf16 hi/lo planes end-to-end, LDSM, pipelined staging):
//   conv1: CIN -> 128 (k=5, dil DIL) + bias + relu, two co-halves of 64
//   conv2: 128 -> 32 (1x1) + bias + relu
// x/y and weights are PRE-SPLIT bf16 planes; staging = pure word copies.
// 512 thr = 16 warps, 2 CTAs/SM.
// ------------------------------------------------------------------
template<int CIN, int DIL, int TIL>
__global__ void __launch_bounds__(512, 2)
block_mma_kernel(const void* __restrict__ xHv, const void* __restrict__ xLv, long xss,
                 const __nv_bfloat16* __restrict__ w1Hg, const __nv_bfloat16* __restrict__ w1Lg,
                 const __nv_bfloat16* __restrict__ w2Hg, const __nv_bfloat16* __restrict__ w2Lg,
                 const float* __restrict__ b1, const float* __restrict__ b2,
                 __nv_bfloat16* __restrict__ yH, __nv_bfloat16* __restrict__ yL, long yss,
                 const int* __restrict__ ids,
                 long w1_cs, long b1_cs, long w2_cs, long b2_cs)
{
    constexpr int CINP = (CIN < 16) ? 16 : CIN;
    constexpr int XW   = TIL + 4 * DIL;
    constexpr int NK   = CINP / 16;
    constexpr int SB   = CINP + 8;       // xt / wa row stride (bf16)
    constexpr int SH   = 72;             // hT row stride
    constexpr int S2   = 136;            // w2 row stride
    constexpr int NT   = TIL / 64;
    constexpr bool DBUF = (CIN <= 32);
    constexpr int NBUF = DBUF ? 2 : 1;
    constexpr int WBUF = 64 * SB;
    constexpr int WW   = 64 * CINP / 2;      // words per tap per half
    constexpr int PW   = (WW + 511) / 512;   // words per thread
    constexpr int WRW  = CINP / 2;           // words per co row
    constexpr int LWR  = ilog2c(WRW);

    extern __shared__ __nv_bfloat16 smb[];
    __nv_bfloat16* xtH = smb;
    __nv_bfloat16* xtL = xtH + XW * SB;
    __nv_bfloat16* waB = xtL + XW * SB;      // H bufs then L bufs
    __nv_bfloat16* hH  = waB + 2 * NBUF * WBUF;
    __nv_bfloat16* hL  = hH  + TIL * SH;
    __nv_bfloat16* w2H = hL  + TIL * SH;
    __nv_bfloat16* w2L = w2H + 32 * S2;
    float* b1s = (float*)(w2L + 32 * S2);
    float* b2s = b1s + 128;

    const int b    = blockIdx.y;
    const int l0   = blockIdx.x * TIL;
    const int tid  = threadIdx.x;
    const int warp = tid >> 5;
    const int ln   = tid & 31;
    const int lq   = ln & 3;
    const int lg   = ln >> 2;
    const int lr   = ln & 7;
    const int lt   = ln >> 3;

    const __nv_bfloat16* w1Hp = w1Hg;
    const __nv_bfloat16* w1Lp = w1Lg;
    const __nv_bfloat16* w2Hp = w2Hg;
    const __nv_bfloat16* w2Lp = w2Lg;
    const float* b1p = b1;
    const float* b2p = b2;
    if (ids) {
        int c = ids[b];
        w1Hp += (long)c * w1_cs;  w1Lp += (long)c * w1_cs;
        w2Hp += (long)c * w2_cs;  w2Lp += (long)c * w2_cs;
        b1p  += (long)c * b1_cs;  b2p  += (long)c * b2_cs;
    }

    // ---- stage x ----
    if constexpr (CIN == 1) {
        const float* xf = (const float*)xHv + (long)b * xss;
        for (int ci = warp; ci < CINP; ci += 16) {
            for (int r = ln; r < XW; r += 32) {
                int pos = l0 - 2 * DIL + r;
                float v = (ci < CIN && pos >= 0 && pos < LLEN) ? xf[pos] : 0.f;
                __nv_bfloat16 hv, lv; split_bf16(v, hv, lv);
                xtH[r * SB + ci] = hv;
                xtL[r * SB + ci] = lv;
            }
        }
    } else {
        constexpr int WR = CIN / 2;
        const unsigned* xbH = (const unsigned*)((const __nv_bfloat16*)xHv + (long)b * xss);
        const unsigned* xbL = (const unsigned*)((const __nv_bfloat16*)xLv + (long)b * xss);
        for (int i = tid; i < XW * WR; i += 512) {
            int r = i / WR, w = i - r * WR;
            int pos = l0 - 2 * DIL + r;
            unsigned vh = 0, vl = 0;
            if (pos >= 0 && pos < LLEN) { vh = xbH[pos * WR + w]; vl = xbL[pos * WR + w]; }
            ((unsigned*)(xtH + r * SB))[w] = vh;
            ((unsigned*)(xtL + r * SB))[w] = vl;
        }
    }
    // ---- stage W2 (pre-split copy) + biases ----
    {
        const unsigned* s2H = (const unsigned*)w2Hp;
        const unsigned* s2L = (const unsigned*)w2Lp;
        for (int i = tid; i < 2048; i += 512) {
            int co = i >> 6, kw = i & 63;
            ((unsigned*)(w2H + co * S2))[kw] = s2H[i];
            ((unsigned*)(w2L + co * S2))[kw] = s2L[i];
        }
    }
    if (tid < 128) b1s[tid] = b1p[tid];
    if (tid < 32)  b2s[tid] = b2p[tid];

    const int wm  = warp >> 3;
    const int wn  = warp & 7;
    const int wm2 = warp & 1;
    const int wn2 = warp >> 1;

    float a2[NT][4];
    #pragma unroll
    for (int nt = 0; nt < NT; nt++)
        #pragma unroll
        for (int q = 0; q < 4; q++) a2[nt][q] = 0.f;

    #pragma unroll
    for (int half = 0; half < 2; half++) {
        const int coB = half * 64;
        const unsigned* w1Hh = (const unsigned*)w1Hp + (long)half * 5 * WW;
        const unsigned* w1Lh = (const unsigned*)w1Lp + (long)half * 5 * WW;

        float acc[2][NT][4];
        #pragma unroll
        for (int mt = 0; mt < 2; mt++)
            #pragma unroll
            for (int nt = 0; nt < NT; nt++)
                #pragma unroll
                for (int q = 0; q < 4; q++) acc[mt][nt][q] = 0.f;

        // ---- preload t=0 weights ----
        {
            unsigned ph[PW], pl[PW];
            #pragma unroll
            for (int j = 0; j < PW; j++) {
                int i = tid + j * 512;
                ph[j] = (i < WW) ? w1Hh[i] : 0u;
                pl[j] = (i < WW) ? w1Lh[i] : 0u;
            }
            __syncthreads();   // wa[buf0] reusable
            #pragma unroll
            for (int j = 0; j < PW; j++) {
                int i = tid + j * 512;
                if (i < WW) {
                    int co = i >> LWR, w = i & (WRW - 1);
                    ((unsigned*)(waB + co * SB))[w] = ph[j];
                    ((unsigned*)(waB + NBUF * WBUF + co * SB))[w] = pl[j];
                }
            }
            __syncthreads();
        }

        #pragma unroll
        for (int t = 0; t < 5; t++) {
            unsigned nh[PW], nl[PW];
            if (t < 4) {
                #pragma unroll
                for (int j = 0; j < PW; j++) {
                    int i = tid + j * 512;
                    nh[j] = (i < WW) ? w1Hh[(t + 1) * WW + i] : 0u;
                    nl[j] = (i < WW) ? w1Lh[(t + 1) * WW + i] : 0u;
                }
            }

            const __nv_bfloat16* wH = waB + (DBUF ? (t & 1) * WBUF : 0);
            const __nv_bfloat16* wL = wH + NBUF * WBUF;

            #pragma unroll
            for (int kc = 0; kc < NK; kc++) {
                unsigned ah[2][4], al[2][4];
                #pragma unroll
                for (int mt = 0; mt < 2; mt++) {
                    int arow = wm * 32 + mt * 16 + lr + (lt & 1) * 8;
                    int acol = kc * 16 + (lt >> 1) * 8;
                    ldsm4(ah[mt], su32(wH + arow * SB + acol));
                    ldsm4(al[mt], su32(wL + arow * SB + acol));
                }
                unsigned bh[4], bl[4];
                if (NT == 2) {
                    int brow = wn * 16 + lr + (lt & 1) * 8 + t * DIL;
                    int bcol = kc * 16 + (lt >> 1) * 8;
                    ldsm4(bh, su32(xtH + brow * SB + bcol));
                    ldsm4(bl, su32(xtL + brow * SB + bcol));
                } else {
                    int brow = wn * 8 + lr + t * DIL;
                    int bcol = kc * 16 + ((ln >> 3) & 1) * 8;
                    ldsm2(bh, su32(xtH + brow * SB + bcol));
                    ldsm2(bl, su32(xtL + brow * SB + bcol));
                }
                #pragma unroll
                for (int nt = 0; nt < NT; nt++) {
                    unsigned bh0 = (NT == 2) ? bh[nt] : bh[0];
                    unsigned bh1 = (NT == 2) ? bh[nt + 2] : bh[1];
                    unsigned bl0 = (NT == 2) ? bl[nt] : bl[0];
                    unsigned bl1 = (NT == 2) ? bl[nt + 2] : bl[1];
                    #pragma unroll
                    for (int mt = 0; mt < 2; mt++) {
                        mma_bf16(acc[mt][nt], ah[mt], bh0, bh1);
                        mma_bf16(acc[mt][nt], ah[mt], bl0, bl1);
                        mma_bf16(acc[mt][nt], al[mt], bh0, bh1);
                    }
                }
            }

            if (t < 4) {
                if (!DBUF) __syncthreads();
                __nv_bfloat16* dH = waB + (DBUF ? ((t + 1) & 1) * WBUF : 0);
                __nv_bfloat16* dL = dH + NBUF * WBUF;
                #pragma unroll
                for (int j = 0; j < PW; j++) {
                    int i = tid + j * 512;
                    if (i < WW) {
                        int co = i >> LWR, w = i & (WRW - 1);
                        ((unsigned*)(dH + co * SB))[w] = nh[j];
                        ((unsigned*)(dL + co * SB))[w] = nl[j];
                    }
                }
                __syncthreads();
            }
        }

        // ---- conv1 epilogue: bias + relu + split -> hT (l-major) ----
        __syncthreads();
        #pragma unroll
        for (int mt = 0; mt < 2; mt++) {
            int m = wm * 32 + mt * 16 + lg;
            float bb0 = b1s[coB + m], bb1 = b1s[coB + m + 8];
            #pragma unroll
            for (int nt = 0; nt < NT; nt++) {
                int n = ((NT == 2) ? wn * 16 + nt * 8 : wn * 8) + 2 * lq;
                float* a = acc[mt][nt];
                float v00 = a[0] + bb0, v01 = a[1] + bb0;
                float v10 = a[2] + bb1, v11 = a[3] + bb1;
                v00 = v00 > 0.f ? v00 : 0.f;  v01 = v01 > 0.f ? v01 : 0.f;
                v10 = v10 > 0.f ? v10 : 0.f;  v11 = v11 > 0.f ? v11 : 0.f;
                __nv_bfloat16 hv, lv;
                split_bf16(v00, hv, lv); hH[n * SH + m] = hv;           hL[n * SH + m] = lv;
                split_bf16(v01, hv, lv); hH[(n + 1) * SH + m] = hv;     hL[(n + 1) * SH + m] = lv;
                split_bf16(v10, hv, lv); hH[n * SH + m + 8] = hv;       hL[n * SH + m + 8] = lv;
                split_bf16(v11, hv, lv); hH[(n + 1) * SH + m + 8] = hv; hL[(n + 1) * SH + m + 8] = lv;
            }
        }
        __syncthreads();

        // ---- conv2 partial ----
        #pragma unroll
        for (int kc = 0; kc < 4; kc++) {
            unsigned ah[4], al[4];
            {
                int arow = wm2 * 16 + lr + (lt & 1) * 8;
                int acol = coB + kc * 16 + (lt >> 1) * 8;
                ldsm4(ah, su32(w2H + arow * S2 + acol));
                ldsm4(al, su32(w2L + arow * S2 + acol));
            }
            unsigned bh[4], bl[4];
            if (NT == 2) {
                int brow = wn2 * 16 + lr + (lt & 1) * 8;
                int bcol = kc * 16 + (lt >> 1) * 8;
                ldsm4(bh, su32(hH + brow * SH + bcol));
                ldsm4(bl, su32(hL + brow * SH + bcol));
            } else {
                int brow = wn2 * 8 + lr;
                int bcol = kc * 16 + ((ln >> 3) & 1) * 8;
                ldsm2(bh, su32(hH + brow * SH + bcol));
                ldsm2(bl, su32(hL + brow * SH + bcol));
            }
            #pragma unroll
            for (int nt = 0; nt < NT; nt++) {
                unsigned bh0 = (NT == 2) ? bh[nt] : bh[0];
                unsigned bh1 = (NT == 2) ? bh[nt + 2] : bh[1];
                unsigned bl0 = (NT == 2) ? bl[nt] : bl[0];
                unsigned bl1 = (NT == 2) ? bl[nt + 2] : bl[1];
                mma_bf16(a2[nt], ah, bh0, bh1);
                mma_bf16(a2[nt], ah, bl0, bl1);
                mma_bf16(a2[nt], al, bh0, bh1);
            }
        }
    }

    // ---- conv2 epilogue: bias + relu + split -> y planes [l][co] ----
    __nv_bfloat16* yHb = yH + (long)b * yss;
    __nv_bfloat16* yLb = yL + (long)b * yss;
    {
        int row = wm2 * 16 + lg;
        float bb0 = b2s[row], bb1 = b2s[row + 8];
        #pragma unroll
        for (int nt = 0; nt < NT; nt++) {
            int col = ((NT == 2) ? wn2 * 16 + nt * 8 : wn2 * 8) + 2 * lq;
            float v0 = a2[nt][0] + bb0, v1 = a2[nt][1] + bb0;
            float v2 = a2[nt][2] + bb1, v3 = a2[nt][3] + bb1;
            v0 = v0 > 0.f ? v0 : 0.f;  v1 = v1 > 0.f ? v1 : 0.f;
            v2 = v2 > 0.f ? v2 : 0.f;  v3 = v3 > 0.f ? v3 : 0.f;
            __nv_bfloat16 hv, lv;
            split_bf16(v0, hv, lv);
            yHb[(long)(l0 + col) * 32 + row] = hv;       yLb[(long)(l0 + col) * 32 + row] = lv;
            split_bf16(v1, hv, lv);
            yHb[(long)(l0 + col + 1) * 32 + row] = hv;   yLb[(long)(l0 + col + 1) * 32 + row] = lv;
            split_bf16(v2, hv, lv);
            yHb[(long)(l0 + col) * 32 + row + 8] = hv;   yLb[(long)(l0 + col) * 32 + row + 8] = lv;
            split_bf16(v3, hv, lv);
            yHb[(long)(l0 + col + 1) * 32 + row + 8] = hv; yLb[(long)(l0 + col + 1) * 32 + row + 8] = lv;
        }
    }
}

// ------------------------------------------------------------------
// compress conv (192 -> 64) + avgpool(2) + nearest-upsample(2), mma.
// CTA = 64 l, 512 thr, 2 CTA/SM. Input: cat planes; output: encU planes.
// ------------------------------------------------------------------
#define CTILE 64
__global__ void __launch_bounds__(512, 2)
comp_mma_kernel(const __nv_bfloat16* __restrict__ catH, const __nv_bfloat16* __restrict__ catL,
                const float* __restrict__ cb,
                __nv_bfloat16* __restrict__ uH, __nv_bfloat16* __restrict__ uL)
{
    constexpr int SA = 200;

    extern __shared__ __nv_bfloat16 smb[];
    __nv_bfloat16* xtH = smb;                  // [64 l][200]
    __nv_bfloat16* xtL = xtH + 64 * SA;
    __nv_bfloat16* waH = xtL + 64 * SA;        // [64 co][200]
    __nv_bfloat16* waL = waH + 64 * SA;
    float* cbs = (float*)(waL + 64 * SA);

    const int b    = blockIdx.y;
    const int l0   = blockIdx.x * CTILE;
    const int tid  = threadIdx.x;
    const int warp = tid >> 5;
    const int ln   = tid & 31;
    const int lq   = ln & 3;
    const int lg   = ln >> 2;
    const int lr   = ln & 7;
    const int lt   = ln >> 3;
    const int wm   = warp & 3;
    const int wn   = warp >> 2;

    // stage x: copy 6 plane tiles -> [l][ch]
    const unsigned* cbH = (const unsigned*)(catH + (long)b * SS32);
    const unsigned* cbL = (const unsigned*)(catL + (long)b * SS32);
    for (int i = tid; i < 64 * 96; i += 512) {
        int r = i / 96, w = i - r * 96;
        int plane = w >> 4, wi = w & 15;
        long src = (long)plane * (PLN / 2) + (long)(l0 + r) * 16 + wi;
        ((unsigned*)(xtH + r * SA))[w] = cbH[src];
        ((unsigned*)(xtL + r * SA))[w] = cbL[src];
    }
    // stage weights (pre-split, [co][192])
    {
        const unsigned* sH = (const unsigned*)(g_w2H + 73728);
        const unsigned* sL = (const unsigned*)(g_w2L + 73728);
        for (int i = tid; i < 64 * 96; i += 512) {
            int co = i / 96, w = i - co * 96;
            ((unsigned*)(waH + co * SA))[w] = sH[i];
            ((unsigned*)(waL + co * SA))[w] = sL[i];
        }
    }
    if (tid < 64) cbs[tid] = cb[tid];
    __syncthreads();

    float acc[2][4];
    #pragma unroll
    for (int nt = 0; nt < 2; nt++)
        #pragma unroll
        for (int q = 0; q < 4; q++) acc[nt][q] = 0.f;

    #pragma unroll
    for (int kc = 0; kc < 12; kc++) {
        unsigned ah[4], al[4];
        {
            int arow = wm * 16 + lr + (lt & 1) * 8;
            int acol = kc * 16 + (lt >> 1) * 8;
            ldsm4(ah, su32(waH + arow * SA + acol));
            ldsm4(al, su32(waL + arow * SA + acol));
        }
        unsigned bh[4], bl[4];
        {
            int brow = wn * 16 + lr + (lt & 1) * 8;
            int bcol = kc * 16 + (lt >> 1) * 8;
            ldsm4(bh, su32(xtH + brow * SA + bcol));
            ldsm4(bl, su32(xtL + brow * SA + bcol));
        }
        #pragma unroll
        for (int nt = 0; nt < 2; nt++) {
            mma_bf16(acc[nt], ah, bh[nt], bh[nt + 2]);
            mma_bf16(acc[nt], ah, bl[nt], bl[nt + 2]);
            mma_bf16(acc[nt], al, bh[nt], bh[nt + 2]);
        }
    }

    // epilogue: bias, pool adjacent cols, write pair to encU planes [l][64]
    __nv_bfloat16* uHb = uH + (long)b * SSU;
    __nv_bfloat16* uLb = uL + (long)b * SSU;
    {
        int m = wm * 16 + lg;
        float bb0 = cbs[m], bb1 = cbs[m + 8];
        #pragma unroll
        for (int nt = 0; nt < 2; nt++) {
            int n = wn * 16 + nt * 8 + 2 * lq;   // even
            float* a = acc[nt];
            float p0 = 0.5f * ((a[0] + bb0) + (a[1] + bb0));
            float p1 = 0.5f * ((a[2] + bb1) + (a[3] + bb1));
            __nv_bfloat16 hv, lv;
            split_bf16(p0, hv, lv);
            uHb[(long)(l0 + n) * 64 + m] = hv;      uHb[(long)(l0 + n + 1) * 64 + m] = hv;
            uLb[(long)(l0 + n) * 64 + m] = lv;      uLb[(long)(l0 + n + 1) * 64 + m] = lv;
            split_bf16(p1, hv, lv);
            uHb[(long)(l0 + n) * 64 + m + 8] = hv;  uHb[(long)(l0 + n + 1) * 64 + m + 8] = hv;
            uLb[(long)(l0 + n) * 64 + m + 8] = lv;  uLb[(long)(l0 + n + 1) * 64 + m + 8] = lv;
        }
    }
}

// ------------------------------------------------------------------
// final per-sample 1x1 conv: 192 -> 1, from dec planes. Grid (4, NB).
// ------------------------------------------------------------------
__global__ void __launch_bounds__(256, 1)
final_kernel(const __nv_bfloat16* __restrict__ decH, const __nv_bfloat16* __restrict__ decL,
             const float* __restrict__ cw, const float* __restrict__ cbv,
             float* __restrict__ out)
{
    __shared__ float ws[192];
    const int b   = blockIdx.y;
    const int tid = threadIdx.x;
    const int l   = blockIdx.x * 256 + tid;
    const int c   = g_ids[b];
    if (tid < 192) ws[tid] = cw[(long)c * 192 + tid];
    __syncthreads();
    float s = cbv[c];
    #pragma unroll
    for (int plane = 0; plane < 6; plane++) {
        const unsigned* pH = (const unsigned*)(decH + (long)b * SS32 + (long)plane * PLN + (long)l * 32);
        const unsigned* pL = (const unsigned*)(decL + (long)b * SS32 + (long)plane * PLN + (long)l * 32);
        #pragma unroll
        for (int w = 0; w < 16; w++) {
            unsigned uh = pH[w], ul = pL[w];
            float2 fh = __bfloat1622float2(*(const __nv_bfloat162*)&uh);
            float2 fl = __bfloat1622float2(*(const __nv_bfloat162*)&ul);
            s = fmaf(ws[plane * 32 + 2 * w],     fh.x + fl.x, s);
            s = fmaf(ws[plane * 32 + 2 * w + 1], fh.y + fl.y, s);
        }
    }
    out[(long)b * LLEN + l] = s;
}

// ------------------------------------------------------------------
static constexpr int smem_mma(int cin, int dil, int til) {
    int cinp = cin < 16 ? 16 : cin;
    int sb   = cinp + 8;
    int nbuf = (cin <= 32) ? 2 : 1;
    int xw   = til + 4 * dil;
    int elems = 2 * xw * sb + 2 * nbuf * 64 * sb + 2 * til * 72 + 2 * 32 * 136;
    return elems * 2 + 160 * 4;
}
static constexpr int SMEM_C = (4 * 64 * 200) * 2 + 256;

template<int CIN, int DIL, int TIL>
static void launch_block(const void* xH, const void* xL, long xss,
                         const __nv_bfloat16* w1H, const __nv_bfloat16* w1L,
                         const __nv_bfloat16* w2H, const __nv_bfloat16* w2L,
                         const float* b1, const float* b2,
                         __nv_bfloat16* yH, __nv_bfloat16* yL, long yss,
                         const int* ids, long w1cs, long b1cs, long w2cs, long b2cs)
{
    static bool attr_done = false;
    if (!attr_done) {
        cudaFuncSetAttribute(block_mma_kernel<CIN, DIL, TIL>,
                             cudaFuncAttributeMaxDynamicSharedMemorySize,
                             smem_mma(CIN, DIL, TIL));
        attr_done = true;
    }
    dim3 grid(LLEN / TIL, NB);
    block_mma_kernel<CIN, DIL, TIL><<<grid, 512, smem_mma(CIN, DIL, TIL)>>>(
        xH, xL, xss, w1H, w1L, w2H, w2L, b1, b2, yH, yL, yss,
        ids, w1cs, b1cs, w2cs, b2cs);
}

extern "C" void kernel_launch(void* const* d_in, const int* in_sizes, int n_in,
                              void* d_out, int out_size)
{
    const float* x        = (const float*)d_in[0];
    const float* enc0_b1  = (const float*)d_in[2];
    const float* enc0_b2  = (const float*)d_in[4];
    const float* enc_b1   = (const float*)d_in[6];
    const float* enc_b2   = (const float*)d_in[8];
    const float* comp_b   = (const float*)d_in[10];
    const float* decf0_b1 = (const float*)d_in[12];
    const float* decf0_b2 = (const float*)d_in[14];
    const float* decf_b1  = (const float*)d_in[16];
    const float* decf_b2  = (const float*)d_in[18];
    const float* decv_b1  = (const float*)d_in[20];
    const float* decv_b2  = (const float*)d_in[22];
    const float* decv_cw  = (const float*)d_in[23];
    const float* decv_cb  = (const float*)d_in[24];
    float* out = (float*)d_out;

    __nv_bfloat16 *catH, *catL, *decH, *decL, *uH, *uL, *w1H, *w1L, *w2H, *w2L;
    int* idsp;
    cudaGetSymbolAddress((void**)&catH, g_catH);
    cudaGetSymbolAddress((void**)&catL, g_catL);
    cudaGetSymbolAddress((void**)&decH, g_decH);
    cudaGetSymbolAddress((void**)&decL, g_decL);
    cudaGetSymbolAddress((void**)&uH,   g_encUH);
    cudaGetSymbolAddress((void**)&uL,   g_encUL);
    cudaGetSymbolAddress((void**)&w1H,  g_w1H);
    cudaGetSymbolAddress((void**)&w1L,  g_w1L);
    cudaGetSymbolAddress((void**)&w2H,  g_w2H);
    cudaGetSymbolAddress((void**)&w2L,  g_w2L);
    cudaGetSymbolAddress((void**)&idsp, g_ids);

    static bool comp_attr = false;
    if (!comp_attr) {
        cudaFuncSetAttribute(comp_mma_kernel,
                             cudaFuncAttributeMaxDynamicSharedMemorySize, SMEM_C);
        comp_attr = true;
    }

    ids_kernel<<<1, 64>>>(x);
    {   // pre-split all weights
        dim3 g1(160, 18);
        prep_w1<<<g1, 256>>>((const float*)d_in[1], (const float*)d_in[5],
                             (const float*)d_in[11], (const float*)d_in[15],
                             (const float*)d_in[19]);
        dim3 g2(48, 19);
        prep_w2<<<g2, 256>>>((const float*)d_in[3], (const float*)d_in[7],
                             (const float*)d_in[13], (const float*)d_in[17],
                             (const float*)d_in[21], (const float*)d_in[9]);
    }

    static const int OFF1[18] = {
        0, 10240, 30720, 51200, 71680, 92160, 112640,
        153600, 174080, 194560,
        215040, 235520, 256000, 276480, 296960, 317440, 337920, 358400};

    // ---- encoder ----
    launch_block<1, 1, 128>(x, nullptr, (long)(LLEN + 1),
                            w1H + OFF1[0], w1L + OFF1[0], w2H + 0, w2L + 0,
                            enc0_b1, enc0_b2,
                            catH, catL, SS32, nullptr, 0, 0, 0, 0);
    launch_block<32, 2, 128>(catH + 0 * PLN, catL + 0 * PLN, SS32,
                             w1H + OFF1[1], w1L + OFF1[1], w2H + 1 * 4096, w2L + 1 * 4096,
                             enc_b1 + 0 * 128, enc_b2 + 0 * 32,
                             catH + 1 * PLN, catL + 1 * PLN, SS32, nullptr, 0, 0, 0, 0);
    launch_block<32, 4, 128>(catH + 1 * PLN, catL + 1 * PLN, SS32,
                             w1H + OFF1[2], w1L + OFF1[2], w2H + 2 * 4096, w2L + 2 * 4096,
                             enc_b1 + 1 * 128, enc_b2 + 1 * 32,
                             catH + 2 * PLN, catL + 2 * PLN, SS32, nullptr, 0, 0, 0, 0);
    launch_block<32, 8, 128>(catH + 2 * PLN, catL + 2 * PLN, SS32,
                             w1H + OFF1[3], w1L + OFF1[3], w2H + 3 * 4096, w2L + 3 * 4096,
                             enc_b1 + 2 * 128, enc_b2 + 2 * 32,
                             catH + 3 * PLN, catL + 3 * PLN, SS32, nullptr, 0, 0, 0, 0);
    launch_block<32, 16, 128>(catH + 3 * PLN, catL + 3 * PLN, SS32,
                              w1H + OFF1[4], w1L + OFF1[4], w2H + 4 * 4096, w2L + 4 * 4096,
                              enc_b1 + 3 * 128, enc_b2 + 3 * 32,
                              catH + 4 * PLN, catL + 4 * PLN, SS32, nullptr, 0, 0, 0, 0);
    launch_block<32, 32, 64>(catH + 4 * PLN, catL + 4 * PLN, SS32,
                             w1H + OFF1[5], w1L + OFF1[5], w2H + 5 * 4096, w2L + 5 * 4096,
                             enc_b1 + 4 * 128, enc_b2 + 4 * 32,
                             catH + 5 * PLN, catL + 5 * PLN, SS32, nullptr, 0, 0, 0, 0);

    // ---- compress + pool + upsample ----
    {
        dim3 grid(LLEN / CTILE, NB);
        comp_mma_kernel<<<grid, 512, SMEM_C>>>(catH, catL, comp_b, uH, uL);
    }

    // ---- fixed decoder ----
    launch_block<64, 32, 64>(uH, uL, (long)SSU,
                             w1H + OFF1[6], w1L + OFF1[6], w2H + 6 * 4096, w2L + 6 * 4096,
                             decf0_b1, decf0_b2,
                             decH, decL, SS32, nullptr, 0, 0, 0, 0);
    launch_block<32, 16, 128>(decH + 0 * PLN, decL + 0 * PLN, SS32,
                              w1H + OFF1[7], w1L + OFF1[7], w2H + 7 * 4096, w2L + 7 * 4096,
                              decf_b1 + 0 * 128, decf_b2 + 0 * 32,
                              decH + 1 * PLN, decL + 1 * PLN, SS32, nullptr, 0, 0, 0, 0);
    launch_block<32, 8, 128>(decH + 1 * PLN, decL + 1 * PLN, SS32,
                             w1H + OFF1[8], w1L + OFF1[8], w2H + 8 * 4096, w2L + 8 * 4096,
                             decf_b1 + 1 * 128, decf_b2 + 1 * 32,
                             decH + 2 * PLN, decL + 2 * PLN, SS32, nullptr, 0, 0, 0, 0);
    launch_block<32, 4, 128>(decH + 2 * PLN, decL + 2 * PLN, SS32,
                             w1H + OFF1[9], w1L + OFF1[9], w2H + 9 * 4096, w2L + 9 * 4096,
                             decf_b1 + 2 * 128, decf_b2 + 2 * 32,
                             decH + 3 * PLN, decL + 3 * PLN, SS32, nullptr, 0, 0, 0, 0);

    // ---- variable decoder: per-sample selected combination ----
    // w1 slots for (c, j): OFF1[10] + (c*2 + j)*20480 ; w2: (10 + c*2 + j)*4096
    launch_block<32, 2, 128>(decH + 3 * PLN, decL + 3 * PLN, SS32,
                             w1H + OFF1[10], w1L + OFF1[10],
                             w2H + 10 * 4096, w2L + 10 * 4096,
                             decv_b1 + 0 * 128, decv_b2 + 0 * 32,
                             decH + 4 * PLN, decL + 4 * PLN, SS32,
                             idsp, 40960, 256, 8192, 64);
    launch_block<32, 1, 128>(decH + 4 * PLN, decL + 4 * PLN, SS32,
                             w1H + OFF1[10] + 20480, w1L + OFF1[10] + 20480,
                             w2H + 11 * 4096, w2L + 11 * 4096,
                             decv_b1 + 1 * 128, decv_b2 + 1 * 32,
                             decH + 5 * PLN, decL + 5 * PLN, SS32,
                             idsp, 40960, 256, 8192, 64);

    // ---- final 1x1 conv (per-sample weights) ----
    {
        dim3 grid(4, NB);
        final_kernel<<<grid, 256>>>(decH, decL, decv_cw, decv_cb, out);
    }
}

// round 11
// speedup vs baseline: 1.3595x; 1.0039x over previous
#include <cuda_runtime.h>
#include <cuda_bf16.h>

#define LLEN 1024
#define NB   64
#define PLN  (LLEN * 32)          // one 32-ch plane, elems
#define SS32 (6 * PLN)            // cat/dec sample stride (elems)
#define SSU  (LLEN * 64)          // encU sample stride

// ---- device scratch (no allocations allowed) ----
__device__ __nv_bfloat16 g_catH[NB * SS32], g_catL[NB * SS32];
__device__ __nv_bfloat16 g_decH[NB * SS32], g_decL[NB * SS32];
__device__ __nv_bfloat16 g_encUH[NB * SSU], g_encUL[NB * SSU];
__device__ __nv_bfloat16 g_w1H[378880], g_w1L[378880];
__device__ __nv_bfloat16 g_w2H[86016],  g_w2L[86016];
__device__ int g_ids[NB];

__constant__ int c_OFF1[18] = {
    0, 10240, 30720, 51200, 71680, 92160, 112640,
    153600, 174080, 194560,
    215040, 235520, 256000, 276480, 296960, 317440, 337920, 358400};

// ------------------------------------------------------------------
__global__ void ids_kernel(const float* __restrict__ x) {
    int b = threadIdx.x;
    if (b < NB) g_ids[b] = (int)x[(long)b * (LLEN + 1) + LLEN];
}

__device__ __forceinline__ void mma_bf16(float* c, const unsigned* a,
                                         unsigned b0, unsigned b1) {
    asm volatile(
        "mma.sync.aligned.m16n8k16.row.col.f32.bf16.bf16.f32 "
        "{%0,%1,%2,%3}, {%4,%5,%6,%7}, {%8,%9}, {%0,%1,%2,%3};\n"
        : "+f"(c[0]), "+f"(c[1]), "+f"(c[2]), "+f"(c[3])
        : "r"(a[0]), "r"(a[1]), "r"(a[2]), "r"(a[3]), "r"(b0), "r"(b1));
}
__device__ __forceinline__ void ldsm4(unsigned* r, unsigned addr) {
    asm volatile("ldmatrix.sync.aligned.m8n8.x4.shared.b16 {%0,%1,%2,%3}, [%4];\n"
                 : "=r"(r[0]), "=r"(r[1]), "=r"(r[2]), "=r"(r[3]) : "r"(addr));
}
__device__ __forceinline__ void ldsm2(unsigned* r, unsigned addr) {
    asm volatile("ldmatrix.sync.aligned.m8n8.x2.shared.b16 {%0,%1}, [%2];\n"
                 : "=r"(r[0]), "=r"(r[1]) : "r"(addr));
}
__device__ __forceinline__ unsigned su32(const void* p) {
    return (unsigned)__cvta_generic_to_shared(p);
}
__device__ __forceinline__ void cpa16(unsigned dst, const void* src) {
    asm volatile("cp.async.ca.shared.global [%0], [%1], 16;\n"
                 :: "r"(dst), "l"(src));
}
#define CP_COMMIT() asm volatile("cp.async.commit_group;\n" ::: "memory")
#define CP_WAIT0()  asm volatile("cp.async.wait_group 0;\n"  ::: "memory")

__device__ __forceinline__ void split_bf16(float v, __nv_bfloat16& hi, __nv_bfloat16& lo) {
    hi = __float2bfloat16(v);
    lo = __float2bfloat16(v - __bfloat162float(hi));
}

// ------------------------------------------------------------------
// prep kernels: split weights into bf16 hi/lo planes, staging layout
//  L==0 (FOLD): e = (half*64 + co)*16 + k, k=t (k>=5 zero)
//  else:        e = ((half*5 + t)*64 + co)*CINP + ci
// ------------------------------------------------------------------
__global__ void prep_w1(const float* __restrict__ enc0, const float* __restrict__ enc,
                        const float* __restrict__ decf0, const float* __restrict__ decf,
                        const float* __restrict__ decv)
{
    int L = blockIdx.y;
    int e = blockIdx.x * 256 + threadIdx.x;
    if (L == 0) {
        if (e >= 2048) return;
        int k = e & 15, tmp = e >> 4;
        int co = tmp & 63, half = tmp >> 6;
        float v = (k < 5) ? enc0[(long)(half * 64 + co) * 5 + k] : 0.f;
        __nv_bfloat16 h, l; split_bf16(v, h, l);
        g_w1H[e] = h;  g_w1L[e] = l;
        return;
    }
    int cinv = (L == 6) ? 64 : 32;
    int cinp = cinv;
    int total = 640 * cinp;
    if (e >= total) return;
    int ci  = e % cinp;
    int tmp = e / cinp;
    int co  = tmp & 63;  tmp >>= 6;
    int t   = tmp % 5, half = tmp / 5;
    const float* src;
    if (L <= 5) src = enc + (L - 1) * 20480;
    else if (L == 6) src = decf0;
    else if (L <= 9) src = decf + (L - 7) * 20480;
    else src = decv + (L - 10) * 20480;
    float v = src[(long)(half * 64 + co) * (cinv * 5) + ci * 5 + t];
    __nv_bfloat16 h, l; split_bf16(v, h, l);
    g_w1H[c_OFF1[L] + e] = h;
    g_w1L[c_OFF1[L] + e] = l;
}

__global__ void prep_w2(const float* __restrict__ enc0, const float* __restrict__ enc,
                        const float* __restrict__ decf0, const float* __restrict__ decf,
                        const float* __restrict__ decv, const float* __restrict__ comp)
{
    int L = blockIdx.y;
    int sz = (L == 18) ? 12288 : 4096;
    int e = blockIdx.x * 256 + threadIdx.x;
    if (e >= sz) return;
    const float* src;
    if (L == 0) src = enc0;
    else if (L <= 5) src = enc + (L - 1) * 4096;
    else if (L == 6) src = decf0;
    else if (L <= 9) src = decf + (L - 7) * 4096;
    else if (L <= 17) src = decv + (L - 10) * 4096;
    else src = comp;
    long off = (L == 18) ? 73728 : (long)L * 4096;
    __nv_bfloat16 h, l; split_bf16(src[e], h, l);
    g_w2H[off + e] = h;
    g_w2L[off + e] = l;
}

// ------------------------------------------------------------------
// Fused TCN block (bf16 hi/lo planes end-to-end, LDSM, cp.async staging):
//   conv1: CIN -> 128 (k=5, dil DIL) + bias + relu, two co-halves of 64
//   conv2: 128 -> 32 (1x1) + bias + relu
// CIN==1 (FOLD): taps folded into K=16, one mma round per half.
// 512 thr = 16 warps, 2 CTAs/SM.
// ------------------------------------------------------------------
template<int CIN, int DIL, int TIL>
__global__ void __launch_bounds__(512, 2)
block_mma_kernel(const void* __restrict__ xHv, const void* __restrict__ xLv, long xss,
                 const __nv_bfloat16* __restrict__ w1Hg, const __nv_bfloat16* __restrict__ w1Lg,
                 const __nv_bfloat16* __restrict__ w2Hg, const __nv_bfloat16* __restrict__ w2Lg,
                 const float* __restrict__ b1, const float* __restrict__ b2,
                 __nv_bfloat16* __restrict__ yH, __nv_bfloat16* __restrict__ yL, long yss,
                 const int* __restrict__ ids,
                 long w1_cs, long b1_cs, long w2_cs, long b2_cs)
{
    constexpr bool FOLD = (CIN == 1);
    constexpr int CINP = FOLD ? 16 : CIN;
    constexpr int XW   = FOLD ? TIL : (TIL + 4 * DIL);
    constexpr int NK   = CINP / 16;
    constexpr int SB   = CINP + 8;       // xt / wa row stride (bf16)
    constexpr int SH   = 72;             // hT row stride
    constexpr int S2   = 136;            // w2 row stride
    constexpr int NT   = TIL / 64;
    constexpr bool DBUF = (!FOLD && CIN <= 32);
    constexpr int NBUF = DBUF ? 2 : 1;
    constexpr int WBUF = 64 * SB;
    constexpr int WW   = 64 * CINP / 2;      // words per tap per half per plane
    constexpr int WRW  = CINP / 2;           // words per co row
    constexpr int CHK  = WRW / 4;            // 16B chunks per co row
    constexpr int NCP  = 64 * CHK;           // chunks per plane per tap

    extern __shared__ __nv_bfloat16 smb[];
    __nv_bfloat16* xtH = smb;
    __nv_bfloat16* xtL = xtH + XW * SB;
    __nv_bfloat16* waB = xtL + XW * SB;      // H bufs then L bufs
    __nv_bfloat16* hH  = waB + 2 * NBUF * WBUF;
    __nv_bfloat16* hL  = hH  + TIL * SH;
    __nv_bfloat16* w2H = hL  + TIL * SH;
    __nv_bfloat16* w2L = w2H + 32 * S2;
    float* b1s = (float*)(w2L + 32 * S2);
    float* b2s = b1s + 128;

    const int b    = blockIdx.y;
    const int l0   = blockIdx.x * TIL;
    const int tid  = threadIdx.x;
    const int warp = tid >> 5;
    const int ln   = tid & 31;
    const int lq   = ln & 3;
    const int lg   = ln >> 2;
    const int lr   = ln & 7;
    const int lt   = ln >> 3;

    const __nv_bfloat16* w1Hp = w1Hg;
    const __nv_bfloat16* w1Lp = w1Lg;
    const __nv_bfloat16* w2Hp = w2Hg;
    const __nv_bfloat16* w2Lp = w2Lg;
    const float* b1p = b1;
    const float* b2p = b2;
    if (ids) {
        int c = ids[b];
        w1Hp += (long)c * w1_cs;  w1Lp += (long)c * w1_cs;
        w2Hp += (long)c * w2_cs;  w2Lp += (long)c * w2_cs;
        b1p  += (long)c * b1_cs;  b2p  += (long)c * b2_cs;
    }

    // ---- stage x ----
    if constexpr (FOLD) {
        // xt[r][k] = x[l0 - 2*DIL + r + k*DIL], k<5 real
        const float* xf = (const float*)xHv + (long)b * xss;
        for (int i = tid; i < TIL * 16; i += 512) {
            int r = i >> 4, k = i & 15;
            int pos = l0 - 2 * DIL + r + k * DIL;
            float v = (k < 5 && pos >= 0 && pos < LLEN) ? xf[pos] : 0.f;
            __nv_bfloat16 hv, lv; split_bf16(v, hv, lv);
            xtH[r * SB + k] = hv;
            xtL[r * SB + k] = lv;
        }
    } else {
        constexpr int WR = CIN / 2;
        const unsigned* xbH = (const unsigned*)((const __nv_bfloat16*)xHv + (long)b * xss);
        const unsigned* xbL = (const unsigned*)((const __nv_bfloat16*)xLv + (long)b * xss);
        for (int i = tid; i < XW * WR; i += 512) {
            int r = i / WR, w = i - r * WR;
            int pos = l0 - 2 * DIL + r;
            unsigned vh = 0, vl = 0;
            if (pos >= 0 && pos < LLEN) { vh = xbH[pos * WR + w]; vl = xbL[pos * WR + w]; }
            ((unsigned*)(xtH + r * SB))[w] = vh;
            ((unsigned*)(xtL + r * SB))[w] = vl;
        }
    }
    // ---- stage W2 (pre-split copy) + biases ----
    {
        const unsigned* s2H = (const unsigned*)w2Hp;
        const unsigned* s2L = (const unsigned*)w2Lp;
        for (int i = tid; i < 2048; i += 512) {
            int co = i >> 6, kw = i & 63;
            ((unsigned*)(w2H + co * S2))[kw] = s2H[i];
            ((unsigned*)(w2L + co * S2))[kw] = s2L[i];
        }
    }
    if (tid < 128) b1s[tid] = b1p[tid];
    if (tid < 32)  b2s[tid] = b2p[tid];

    const int wm  = warp >> 3;
    const int wn  = warp & 7;
    const int wm2 = warp & 1;
    const int wn2 = warp >> 1;

    float a2[NT][4];
    #pragma unroll
    for (int nt = 0; nt < NT; nt++)
        #pragma unroll
        for (int q = 0; q < 4; q++) a2[nt][q] = 0.f;

    #pragma unroll
    for (int half = 0; half < 2; half++) {
        const int coB = half * 64;

        float acc[2][NT][4];
        #pragma unroll
        for (int mt = 0; mt < 2; mt++)
            #pragma unroll
            for (int nt = 0; nt < NT; nt++)
                #pragma unroll
                for (int q = 0; q < 4; q++) acc[mt][nt][q] = 0.f;

        if constexpr (FOLD) {
            // ---- stage folded weights for this half (cp.async) ----
            if (tid < 256) {
                int pl = tid >> 7, q = tid & 127;   // 128 chunks per plane
                int co = q >> 1, ck = q & 1;        // 2x16B per co row
                const __nv_bfloat16* srcp = pl ? w1Lp : w1Hp;
                __nv_bfloat16* dstp = pl ? (waB + WBUF) : waB;
                cpa16(su32(dstp + co * SB) + ck * 16,
                      (const char*)srcp + half * 2048 + co * 32 + ck * 16);
            }
            CP_COMMIT(); CP_WAIT0();
            __syncthreads();

            // ---- single-kc conv1 mma ----
            unsigned ah[2][4], al[2][4];
            #pragma unroll
            for (int mt = 0; mt < 2; mt++) {
                int arow = wm * 32 + mt * 16 + lr + (lt & 1) * 8;
                int acol = (lt >> 1) * 8;
                ldsm4(ah[mt], su32(waB + arow * SB + acol));
                ldsm4(al[mt], su32(waB + WBUF + arow * SB + acol));
            }
            unsigned bh[4], bl[4];
            if (NT == 2) {
                int brow = wn * 16 + lr + (lt & 1) * 8;
                int bcol = (lt >> 1) * 8;
                ldsm4(bh, su32(xtH + brow * SB + bcol));
                ldsm4(bl, su32(xtL + brow * SB + bcol));
            } else {
                int brow = wn * 8 + lr;
                int bcol = ((ln >> 3) & 1) * 8;
                ldsm2(bh, su32(xtH + brow * SB + bcol));
                ldsm2(bl, su32(xtL + brow * SB + bcol));
            }
            #pragma unroll
            for (int nt = 0; nt < NT; nt++) {
                unsigned bh0 = (NT == 2) ? bh[nt] : bh[0];
                unsigned bh1 = (NT == 2) ? bh[nt + 2] : bh[1];
                unsigned bl0 = (NT == 2) ? bl[nt] : bl[0];
                unsigned bl1 = (NT == 2) ? bl[nt + 2] : bl[1];
                #pragma unroll
                for (int mt = 0; mt < 2; mt++) {
                    mma_bf16(acc[mt][nt], ah[mt], bh0, bh1);
                    mma_bf16(acc[mt][nt], ah[mt], bl0, bl1);
                    mma_bf16(acc[mt][nt], al[mt], bh0, bh1);
                }
            }
        } else {
            const char* w1Hh = (const char*)w1Hp + (size_t)half * 5 * WW * 4;
            const char* w1Lh = (const char*)w1Lp + (size_t)half * 5 * WW * 4;

            // stage_w: issue cp.async for tap tt into buffer bufsel
            auto stage_w = [&](int tt, int bufsel) {
                __nv_bfloat16* dH = waB + bufsel * WBUF;
                __nv_bfloat16* dL = dH + NBUF * WBUF;
                const char* sH = w1Hh + (size_t)tt * WW * 4;
                const char* sL = w1Lh + (size_t)tt * WW * 4;
                #pragma unroll
                for (int j = 0; j < (2 * NCP) / 512; j++) {
                    int i = tid + j * 512;
                    int pl = i / NCP, q = i - pl * NCP;
                    int co = q / CHK, ck = q - co * CHK;
                    const char* s = (pl ? sL : sH) + co * (WRW * 4) + ck * 16;
                    unsigned d = su32((pl ? dL : dH) + co * SB) + ck * 16;
                    cpa16(d, s);
                }
            };

            // ---- preload t=0 ----
            stage_w(0, 0);
            CP_COMMIT(); CP_WAIT0();
            __syncthreads();

            #pragma unroll
            for (int t = 0; t < 5; t++) {
                if (DBUF && t < 4) {
                    stage_w(t + 1, (t + 1) & 1);   // overlaps this tap's mma
                    CP_COMMIT();
                }

                const __nv_bfloat16* wH = waB + (DBUF ? (t & 1) * WBUF : 0);
                const __nv_bfloat16* wL = wH + NBUF * WBUF;

                #pragma unroll
                for (int kc = 0; kc < NK; kc++) {
                    unsigned ah[2][4], al[2][4];
                    #pragma unroll
                    for (int mt = 0; mt < 2; mt++) {
                        int arow = wm * 32 + mt * 16 + lr + (lt & 1) * 8;
                        int acol = kc * 16 + (lt >> 1) * 8;
                        ldsm4(ah[mt], su32(wH + arow * SB + acol));
                        ldsm4(al[mt], su32(wL + arow * SB + acol));
                    }
                    unsigned bh[4], bl[4];
                    if (NT == 2) {
                        int brow = wn * 16 + lr + (lt & 1) * 8 + t * DIL;
                        int bcol = kc * 16 + (lt >> 1) * 8;
                        ldsm4(bh, su32(xtH + brow * SB + bcol));
                        ldsm4(bl, su32(xtL + brow * SB + bcol));
                    } else {
                        int brow = wn * 8 + lr + t * DIL;
                        int bcol = kc * 16 + ((ln >> 3) & 1) * 8;
                        ldsm2(bh, su32(xtH + brow * SB + bcol));
                        ldsm2(bl, su32(xtL + brow * SB + bcol));
                    }
                    #pragma unroll
                    for (int nt = 0; nt < NT; nt++) {
                        unsigned bh0 = (NT == 2) ? bh[nt] : bh[0];
                        unsigned bh1 = (NT == 2) ? bh[nt + 2] : bh[1];
                        unsigned bl0 = (NT == 2) ? bl[nt] : bl[0];
                        unsigned bl1 = (NT == 2) ? bl[nt + 2] : bl[1];
                        #pragma unroll
                        for (int mt = 0; mt < 2; mt++) {
                            mma_bf16(acc[mt][nt], ah[mt], bh0, bh1);
                            mma_bf16(acc[mt][nt], ah[mt], bl0, bl1);
                            mma_bf16(acc[mt][nt], al[mt], bh0, bh1);
                        }
                    }
                }

                if (t < 4) {
                    if (!DBUF) {
                        __syncthreads();          // all readers done w/ buf0
                        stage_w(t + 1, 0);
                        CP_COMMIT();
                    }
                    CP_WAIT0();
                    __syncthreads();
                }
            }
        }

        // ---- conv1 epilogue: bias + relu + split -> hT (l-major) ----
        __syncthreads();
        #pragma unroll
        for (int mt = 0; mt < 2; mt++) {
            int m = wm * 32 + mt * 16 + lg;
            float bb0 = b1s[coB + m], bb1 = b1s[coB + m + 8];
            #pragma unroll
            for (int nt = 0; nt < NT; nt++) {
                int n = ((NT == 2) ? wn * 16 + nt * 8 : wn * 8) + 2 * lq;
                float* a = acc[mt][nt];
                float v00 = a[0] + bb0, v01 = a[1] + bb0;
                float v10 = a[2] + bb1, v11 = a[3] + bb1;
                v00 = v00 > 0.f ? v00 : 0.f;  v01 = v01 > 0.f ? v01 : 0.f;
                v10 = v10 > 0.f ? v10 : 0.f;  v11 = v11 > 0.f ? v11 : 0.f;
                __nv_bfloat16 hv, lv;
                split_bf16(v00, hv, lv); hH[n * SH + m] = hv;           hL[n * SH + m] = lv;
                split_bf16(v01, hv, lv); hH[(n + 1) * SH + m] = hv;     hL[(n + 1) * SH + m] = lv;
                split_bf16(v10, hv, lv); hH[n * SH + m + 8] = hv;       hL[n * SH + m + 8] = lv;
                split_bf16(v11, hv, lv); hH[(n + 1) * SH + m + 8] = hv; hL[(n + 1) * SH + m + 8] = lv;
            }
        }
        __syncthreads();

        // ---- conv2 partial ----
        #pragma unroll
        for (int kc = 0; kc < 4; kc++) {
            unsigned ah[4], al[4];
            {
                int arow = wm2 * 16 + lr + (lt & 1) * 8;
                int acol = coB + kc * 16 + (lt >> 1) * 8;
                ldsm4(ah, su32(w2H + arow * S2 + acol));
                ldsm4(al, su32(w2L + arow * S2 + acol));
            }
            unsigned bh[4], bl[4];
            if (NT == 2) {
                int brow = wn2 * 16 + lr + (lt & 1) * 8;
                int bcol = kc * 16 + (lt >> 1) * 8;
                ldsm4(bh, su32(hH + brow * SH + bcol));
                ldsm4(bl, su32(hL + brow * SH + bcol));
            } else {
                int brow = wn2 * 8 + lr;
                int bcol = kc * 16 + ((ln >> 3) & 1) * 8;
                ldsm2(bh, su32(hH + brow * SH + bcol));
                ldsm2(bl, su32(hL + brow * SH + bcol));
            }
            #pragma unroll
            for (int nt = 0; nt < NT; nt++) {
                unsigned bh0 = (NT == 2) ? bh[nt] : bh[0];
                unsigned bh1 = (NT == 2) ? bh[nt + 2] : bh[1];
                unsigned bl0 = (NT == 2) ? bl[nt] : bl[0];
                unsigned bl1 = (NT == 2) ? bl[nt + 2] : bl[1];
                mma_bf16(a2[nt], ah, bh0, bh1);
                mma_bf16(a2[nt], ah, bl0, bl1);
                mma_bf16(a2[nt], al, bh0, bh1);
            }
        }
    }

    // ---- conv2 epilogue: bias + relu + split -> y planes [l][co] ----
    __nv_bfloat16* yHb = yH + (long)b * yss;
    __nv_bfloat16* yLb = yL + (long)b * yss;
    {
        int row = wm2 * 16 + lg;
        float bb0 = b2s[row], bb1 = b2s[row + 8];
        #pragma unroll
        for (int nt = 0; nt < NT; nt++) {
            int col = ((NT == 2) ? wn2 * 16 + nt * 8 : wn2 * 8) + 2 * lq;
            float v0 = a2[nt][0] + bb0, v1 = a2[nt][1] + bb0;
            float v2 = a2[nt][2] + bb1, v3 = a2[nt][3] + bb1;
            v0 = v0 > 0.f ? v0 : 0.f;  v1 = v1 > 0.f ? v1 : 0.f;
            v2 = v2 > 0.f ? v2 : 0.f;  v3 = v3 > 0.f ? v3 : 0.f;
            __nv_bfloat16 hv, lv;
            split_bf16(v0, hv, lv);
            yHb[(long)(l0 + col) * 32 + row] = hv;       yLb[(long)(l0 + col) * 32 + row] = lv;
            split_bf16(v1, hv, lv);
            yHb[(long)(l0 + col + 1) * 32 + row] = hv;   yLb[(long)(l0 + col + 1) * 32 + row] = lv;
            split_bf16(v2, hv, lv);
            yHb[(long)(l0 + col) * 32 + row + 8] = hv;   yLb[(long)(l0 + col) * 32 + row + 8] = lv;
            split_bf16(v3, hv, lv);
            yHb[(long)(l0 + col + 1) * 32 + row + 8] = hv; yLb[(long)(l0 + col + 1) * 32 + row + 8] = lv;
        }
    }
}

// ------------------------------------------------------------------
// compress conv (192 -> 64) + avgpool(2) + nearest-upsample(2), mma.
// ------------------------------------------------------------------
#define CTILE 64
__global__ void __launch_bounds__(512, 2)
comp_mma_kernel(const __nv_bfloat16* __restrict__ catH, const __nv_bfloat16* __restrict__ catL,
                const float* __restrict__ cb,
                __nv_bfloat16* __restrict__ uH, __nv_bfloat16* __restrict__ uL)
{
    constexpr int SA = 200;

    extern __shared__ __nv_bfloat16 smb[];
    __nv_bfloat16* xtH = smb;                  // [64 l][200]
    __nv_bfloat16* xtL = xtH + 64 * SA;
    __nv_bfloat16* waH = xtL + 64 * SA;        // [64 co][200]
    __nv_bfloat16* waL = waH + 64 * SA;
    float* cbs = (float*)(waL + 64 * SA);

    const int b    = blockIdx.y;
    const int l0   = blockIdx.x * CTILE;
    const int tid  = threadIdx.x;
    const int warp = tid >> 5;
    const int ln   = tid & 31;
    const int lq   = ln & 3;
    const int lg   = ln >> 2;
    const int lr   = ln & 7;
    const int lt   = ln >> 3;
    const int wm   = warp & 3;
    const int wn   = warp >> 2;

    const unsigned* cbH = (const unsigned*)(catH + (long)b * SS32);
    const unsigned* cbL = (const unsigned*)(catL + (long)b * SS32);
    for (int i = tid; i < 64 * 96; i += 512) {
        int r = i / 96, w = i - r * 96;
        int plane = w >> 4, wi = w & 15;
        long src = (long)plane * (PLN / 2) + (long)(l0 + r) * 16 + wi;
        ((unsigned*)(xtH + r * SA))[w] = cbH[src];
        ((unsigned*)(xtL + r * SA))[w] = cbL[src];
    }
    {
        const unsigned* sH = (const unsigned*)(g_w2H + 73728);
        const unsigned* sL = (const unsigned*)(g_w2L + 73728);
        for (int i = tid; i < 64 * 96; i += 512) {
            int co = i / 96, w = i - co * 96;
            ((unsigned*)(waH + co * SA))[w] = sH[i];
            ((unsigned*)(waL + co * SA))[w] = sL[i];
        }
    }
    if (tid < 64) cbs[tid] = cb[tid];
    __syncthreads();

    float acc[2][4];
    #pragma unroll
    for (int nt = 0; nt < 2; nt++)
        #pragma unroll
        for (int q = 0; q < 4; q++) acc[nt][q] = 0.f;

    #pragma unroll
    for (int kc = 0; kc < 12; kc++) {
        unsigned ah[4], al[4];
        {
            int arow = wm * 16 + lr + (lt & 1) * 8;
            int acol = kc * 16 + (lt >> 1) * 8;
            ldsm4(ah, su32(waH + arow * SA + acol));
            ldsm4(al, su32(waL + arow * SA + acol));
        }
        unsigned bh[4], bl[4];
        {
            int brow = wn * 16 + lr + (lt & 1) * 8;
            int bcol = kc * 16 + (lt >> 1) * 8;
            ldsm4(bh, su32(xtH + brow * SA + bcol));
            ldsm4(bl, su32(xtL + brow * SA + bcol));
        }
        #pragma unroll
        for (int nt = 0; nt < 2; nt++) {
            mma_bf16(acc[nt], ah, bh[nt], bh[nt + 2]);
            mma_bf16(acc[nt], ah, bl[nt], bl[nt + 2]);
            mma_bf16(acc[nt], al, bh[nt], bh[nt + 2]);
        }
    }

    __nv_bfloat16* uHb = uH + (long)b * SSU;
    __nv_bfloat16* uLb = uL + (long)b * SSU;
    {
        int m = wm * 16 + lg;
        float bb0 = cbs[m], bb1 = cbs[m + 8];
        #pragma unroll
        for (int nt = 0; nt < 2; nt++) {
            int n = wn * 16 + nt * 8 + 2 * lq;
            float* a = acc[nt];
            float p0 = 0.5f * ((a[0] + bb0) + (a[1] + bb0));
            float p1 = 0.5f * ((a[2] + bb1) + (a[3] + bb1));
            __nv_bfloat16 hv, lv;
            split_bf16(p0, hv, lv);
            uHb[(long)(l0 + n) * 64 + m] = hv;      uHb[(long)(l0 + n + 1) * 64 + m] = hv;
            uLb[(long)(l0 + n) * 64 + m] = lv;      uLb[(long)(l0 + n + 1) * 64 + m] = lv;
            split_bf16(p1, hv, lv);
            uHb[(long)(l0 + n) * 64 + m + 8] = hv;  uHb[(long)(l0 + n + 1) * 64 + m + 8] = hv;
            uLb[(long)(l0 + n) * 64 + m + 8] = lv;  uLb[(long)(l0 + n + 1) * 64 + m + 8] = lv;
        }
    }
}

// ------------------------------------------------------------------
// final per-sample 1x1 conv: 192 -> 1, from dec planes. Grid (4, NB).
// ------------------------------------------------------------------
__global__ void __launch_bounds__(256, 1)
final_kernel(const __nv_bfloat16* __restrict__ decH, const __nv_bfloat16* __restrict__ decL,
             const float* __restrict__ cw, const float* __restrict__ cbv,
             float* __restrict__ out)
{
    __shared__ float ws[192];
    const int b   = blockIdx.y;
    const int tid = threadIdx.x;
    const int l   = blockIdx.x * 256 + tid;
    const int c   = g_ids[b];
    if (tid < 192) ws[tid] = cw[(long)c * 192 + tid];
    __syncthreads();
    float s = cbv[c];
    #pragma unroll
    for (int plane = 0; plane < 6; plane++) {
        const unsigned* pH = (const unsigned*)(decH + (long)b * SS32 + (long)plane * PLN + (long)l * 32);
        const unsigned* pL = (const unsigned*)(decL + (long)b * SS32 + (long)plane * PLN + (long)l * 32);
        #pragma unroll
        for (int w = 0; w < 16; w++) {
            unsigned uh = pH[w], ul = pL[w];
            float2 fh = __bfloat1622float2(*(const __nv_bfloat162*)&uh);
            float2 fl = __bfloat1622float2(*(const __nv_bfloat162*)&ul);
            s = fmaf(ws[plane * 32 + 2 * w],     fh.x + fl.x, s);
            s = fmaf(ws[plane * 32 + 2 * w + 1], fh.y + fl.y, s);
        }
    }
    out[(long)b * LLEN + l] = s;
}

// ------------------------------------------------------------------
static constexpr int smem_mma(int cin, int dil, int til) {
    bool fold = (cin == 1);
    int cinp = fold ? 16 : cin;
    int sb   = cinp + 8;
    int nbuf = (!fold && cin <= 32) ? 2 : 1;
    int xw   = fold ? til : (til + 4 * dil);
    int elems = 2 * xw * sb + 2 * nbuf * 64 * sb + 2 * til * 72 + 2 * 32 * 136;
    return elems * 2 + 160 * 4;
}
static constexpr int SMEM_C = (4 * 64 * 200) * 2 + 256;

template<int CIN, int DIL, int TIL>
static void launch_block(const void* xH, const void* xL, long xss,
                         const __nv_bfloat16* w1H, const __nv_bfloat16* w1L,
                         const __nv_bfloat16* w2H, const __nv_bfloat16* w2L,
                         const float* b1, const float* b2,
                         __nv_bfloat16* yH, __nv_bfloat16* yL, long yss,
                         const int* ids, long w1cs, long b1cs, long w2cs, long b2cs)
{
    static bool attr_done = false;
    if (!attr_done) {
        cudaFuncSetAttribute(block_mma_kernel<CIN, DIL, TIL>,
                             cudaFuncAttributeMaxDynamicSharedMemorySize,
                             smem_mma(CIN, DIL, TIL));
        attr_done = true;
    }
    dim3 grid(LLEN / TIL, NB);
    block_mma_kernel<CIN, DIL, TIL><<<grid, 512, smem_mma(CIN, DIL, TIL)>>>(
        xH, xL, xss, w1H, w1L, w2H, w2L, b1, b2, yH, yL, yss,
        ids, w1cs, b1cs, w2cs, b2cs);
}

extern "C" void kernel_launch(void* const* d_in, const int* in_sizes, int n_in,
                              void* d_out, int out_size)
{
    const float* x        = (const float*)d_in[0];
    const float* enc0_b1  = (const float*)d_in[2];
    const float* enc0_b2  = (const float*)d_in[4];
    const float* enc_b1   = (const float*)d_in[6];
    const float* enc_b2   = (const float*)d_in[8];
    const float* comp_b   = (const float*)d_in[10];
    const float* decf0_b1 = (const float*)d_in[12];
    const float* decf0_b2 = (const float*)d_in[14];
    const float* decf_b1  = (const float*)d_in[16];
    const float* decf_b2  = (const float*)d_in[18];
    const float* decv_b1  = (const float*)d_in[20];
    const float* decv_b2  = (const float*)d_in[22];
    const float* decv_cw  = (const float*)d_in[23];
    const float* decv_cb  = (const float*)d_in[24];
    float* out = (float*)d_out;

    __nv_bfloat16 *catH, *catL, *decH, *decL, *uH, *uL, *w1H, *w1L, *w2H, *w2L;
    int* idsp;
    cudaGetSymbolAddress((void**)&catH, g_catH);
    cudaGetSymbolAddress((void**)&catL, g_catL);
    cudaGetSymbolAddress((void**)&decH, g_decH);
    cudaGetSymbolAddress((void**)&decL, g_decL);
    cudaGetSymbolAddress((void**)&uH,   g_encUH);
    cudaGetSymbolAddress((void**)&uL,   g_encUL);
    cudaGetSymbolAddress((void**)&w1H,  g_w1H);
    cudaGetSymbolAddress((void**)&w1L,  g_w1L);
    cudaGetSymbolAddress((void**)&w2H,  g_w2H);
    cudaGetSymbolAddress((void**)&w2L,  g_w2L);
    cudaGetSymbolAddress((void**)&idsp, g_ids);

    static bool comp_attr = false;
    if (!comp_attr) {
        cudaFuncSetAttribute(comp_mma_kernel,
                             cudaFuncAttributeMaxDynamicSharedMemorySize, SMEM_C);
        comp_attr = true;
    }

    ids_kernel<<<1, 64>>>(x);
    {
        dim3 g1(160, 18);
        prep_w1<<<g1, 256>>>((const float*)d_in[1], (const float*)d_in[5],
                             (const float*)d_in[11], (const float*)d_in[15],
                             (const float*)d_in[19]);
        dim3 g2(48, 19);
        prep_w2<<<g2, 256>>>((const float*)d_in[3], (const float*)d_in[7],
                             (const float*)d_in[13], (const float*)d_in[17],
                             (const float*)d_in[21], (const float*)d_in[9]);
    }

    static const int OFF1[18] = {
        0, 10240, 30720, 51200, 71680, 92160, 112640,
        153600, 174080, 194560,
        215040, 235520, 256000, 276480, 296960, 317440, 337920, 358400};

    // ---- encoder ----
    launch_block<1, 1, 128>(x, nullptr, (long)(LLEN + 1),
                            w1H + OFF1[0], w1L + OFF1[0], w2H + 0, w2L + 0,
                            enc0_b1, enc0_b2,
                            catH, catL, SS32, nullptr, 0, 0, 0, 0);
    launch_block<32, 2, 128>(catH + 0 * PLN, catL + 0 * PLN, SS32,
                             w1H + OFF1[1], w1L + OFF1[1], w2H + 1 * 4096, w2L + 1 * 4096,
                             enc_b1 + 0 * 128, enc_b2 + 0 * 32,
                             catH + 1 * PLN, catL + 1 * PLN, SS32, nullptr, 0, 0, 0, 0);
    launch_block<32, 4, 128>(catH + 1 * PLN, catL + 1 * PLN, SS32,
                             w1H + OFF1[2], w1L + OFF1[2], w2H + 2 * 4096, w2L + 2 * 4096,
                             enc_b1 + 1 * 128, enc_b2 + 1 * 32,
                             catH + 2 * PLN, catL + 2 * PLN, SS32, nullptr, 0, 0, 0, 0);
    launch_block<32, 8, 128>(catH + 2 * PLN, catL + 2 * PLN, SS32,
                             w1H + OFF1[3], w1L + OFF1[3], w2H + 3 * 4096, w2L + 3 * 4096,
                             enc_b1 + 2 * 128, enc_b2 + 2 * 32,
                             catH + 3 * PLN, catL + 3 * PLN, SS32, nullptr, 0, 0, 0, 0);
    launch_block<32, 16, 128>(catH + 3 * PLN, catL + 3 * PLN, SS32,
                              w1H + OFF1[4], w1L + OFF1[4], w2H + 4 * 4096, w2L + 4 * 4096,
                              enc_b1 + 3 * 128, enc_b2 + 3 * 32,
                              catH + 4 * PLN, catL + 4 * PLN, SS32, nullptr, 0, 0, 0, 0);
    launch_block<32, 32, 64>(catH + 4 * PLN, catL + 4 * PLN, SS32,
                             w1H + OFF1[5], w1L + OFF1[5], w2H + 5 * 4096, w2L + 5 * 4096,
                             enc_b1 + 4 * 128, enc_b2 + 4 * 32,
                             catH + 5 * PLN, catL + 5 * PLN, SS32, nullptr, 0, 0, 0, 0);

    // ---- compress + pool + upsample ----
    {
        dim3 grid(LLEN / CTILE, NB);
        comp_mma_kernel<<<grid, 512, SMEM_C>>>(catH, catL, comp_b, uH, uL);
    }

    // ---- fixed decoder ----
    launch_block<64, 32, 64>(uH, uL, (long)SSU,
                             w1H + OFF1[6], w1L + OFF1[6], w2H + 6 * 4096, w2L + 6 * 4096,
                             decf0_b1, decf0_b2,
                             decH, decL, SS32, nullptr, 0, 0, 0, 0);
    launch_block<32, 16, 128>(decH + 0 * PLN, decL + 0 * PLN, SS32,
                              w1H + OFF1[7], w1L + OFF1[7], w2H + 7 * 4096, w2L + 7 * 4096,
                              decf_b1 + 0 * 128, decf_b2 + 0 * 32,
                              decH + 1 * PLN, decL + 1 * PLN, SS32, nullptr, 0, 0, 0, 0);
    launch_block<32, 8, 128>(decH + 1 * PLN, decL + 1 * PLN, SS32,
                             w1H + OFF1[8], w1L + OFF1[8], w2H + 8 * 4096, w2L + 8 * 4096,
                             decf_b1 + 1 * 128, decf_b2 + 1 * 32,
                             decH + 2 * PLN, decL + 2 * PLN, SS32, nullptr, 0, 0, 0, 0);
    launch_block<32, 4, 128>(decH + 2 * PLN, decL + 2 * PLN, SS32,
                             w1H + OFF1[9], w1L + OFF1[9], w2H + 9 * 4096, w2L + 9 * 4096,
                             decf_b1 + 2 * 128, decf_b2 + 2 * 32,
                             decH + 3 * PLN, decL + 3 * PLN, SS32, nullptr, 0, 0, 0, 0);

    // ---- variable decoder: per-sample selected combination ----
    launch_block<32, 2, 128>(decH + 3 * PLN, decL + 3 * PLN, SS32,
                             w1H + OFF1[10], w1L + OFF1[10],
                             w2H + 10 * 4096, w2L + 10 * 4096,
                             decv_b1 + 0 * 128, decv_b2 + 0 * 32,
                             decH + 4 * PLN, decL + 4 * PLN, SS32,
                             idsp, 40960, 256, 8192, 64);
    launch_block<32, 1, 128>(decH + 4 * PLN, decL + 4 * PLN, SS32,
                             w1H + OFF1[10] + 20480, w1L + OFF1[10] + 20480,
                             w2H + 11 * 4096, w2L + 11 * 4096,
                             decv_b1 + 1 * 128, decv_b2 + 1 * 32,
                             decH + 5 * PLN, decL + 5 * PLN, SS32,
                             idsp, 40960, 256, 8192, 64);

    // ---- final 1x1 conv (per-sample weights) ----
    {
        dim3 grid(4, NB);
        final_kernel<<<grid, 256>>>(decH, decL, decv_cw, decv_cb, out);
    }
}

// round 12
// speedup vs baseline: 1.4977x; 1.1017x over previous
#include <cuda_runtime.h>
#include <cuda_bf16.h>

#define LLEN 1024
#define NB   64
#define PLN  (LLEN * 32)          // one 32-ch plane, elems
#define SS32 (6 * PLN)            // cat/dec sample stride (elems)
#define SSU  (LLEN * 64)          // encU sample stride

// ---- device scratch (no allocations allowed) ----
__device__ __nv_bfloat16 g_catH[NB * SS32], g_catL[NB * SS32];
__device__ __nv_bfloat16 g_decH[NB * SS32], g_decL[NB * SS32];
__device__ __nv_bfloat16 g_encUH[NB * SSU], g_encUL[NB * SSU];
__device__ __nv_bfloat16 g_w1H[378880], g_w1L[378880];
__device__ __nv_bfloat16 g_w2H[86016],  g_w2L[86016];
__device__ int g_ids[NB];

__constant__ int c_OFF1[18] = {
    0, 10240, 30720, 51200, 71680, 92160, 112640,
    153600, 174080, 194560,
    215040, 235520, 256000, 276480, 296960, 317440, 337920, 358400};

// ------------------------------------------------------------------
__global__ void ids_kernel(const float* __restrict__ x) {
    int b = threadIdx.x;
    if (b < NB) g_ids[b] = (int)x[(long)b * (LLEN + 1) + LLEN];
}

__device__ __forceinline__ void mma_bf16(float* c, const unsigned* a,
                                         unsigned b0, unsigned b1) {
    asm volatile(
        "mma.sync.aligned.m16n8k16.row.col.f32.bf16.bf16.f32 "
        "{%0,%1,%2,%3}, {%4,%5,%6,%7}, {%8,%9}, {%0,%1,%2,%3};\n"
        : "+f"(c[0]), "+f"(c[1]), "+f"(c[2]), "+f"(c[3])
        : "r"(a[0]), "r"(a[1]), "r"(a[2]), "r"(a[3]), "r"(b0), "r"(b1));
}
__device__ __forceinline__ void ldsm4(unsigned* r, unsigned addr) {
    asm volatile("ldmatrix.sync.aligned.m8n8.x4.shared.b16 {%0,%1,%2,%3}, [%4];\n"
                 : "=r"(r[0]), "=r"(r[1]), "=r"(r[2]), "=r"(r[3]) : "r"(addr));
}
__device__ __forceinline__ void ldsm2(unsigned* r, unsigned addr) {
    asm volatile("ldmatrix.sync.aligned.m8n8.x2.shared.b16 {%0,%1}, [%2];\n"
                 : "=r"(r[0]), "=r"(r[1]) : "r"(addr));
}
__device__ __forceinline__ unsigned su32(const void* p) {
    return (unsigned)__cvta_generic_to_shared(p);
}
__device__ __forceinline__ void cpa16(unsigned dst, const void* src) {
    asm volatile("cp.async.ca.shared.global [%0], [%1], 16;\n"
                 :: "r"(dst), "l"(src));
}
// zero-fill variant: sz==0 writes 16B of zeros (halo padding)
__device__ __forceinline__ void cpa16z(unsigned dst, const void* src, int sz) {
    asm volatile("cp.async.ca.shared.global [%0], [%1], 16, %2;\n"
                 :: "r"(dst), "l"(src), "r"(sz));
}
#define CP_COMMIT() asm volatile("cp.async.commit_group;\n" ::: "memory")
#define CP_WAIT0()  asm volatile("cp.async.wait_group 0;\n"  ::: "memory")

__device__ __forceinline__ void split_bf16(float v, __nv_bfloat16& hi, __nv_bfloat16& lo) {
    hi = __float2bfloat16(v);
    lo = __float2bfloat16(v - __bfloat162float(hi));
}

// ------------------------------------------------------------------
// prep kernels: split weights into bf16 hi/lo planes, staging layout
//  L==0 (FOLD): e = (half*64 + co)*16 + k, k=t (k>=5 zero)
//  else:        e = ((half*5 + t)*64 + co)*CINP + ci
// ------------------------------------------------------------------
__global__ void prep_w1(const float* __restrict__ enc0, const float* __restrict__ enc,
                        const float* __restrict__ decf0, const float* __restrict__ decf,
                        const float* __restrict__ decv)
{
    int L = blockIdx.y;
    int e = blockIdx.x * 256 + threadIdx.x;
    if (L == 0) {
        if (e >= 2048) return;
        int k = e & 15, tmp = e >> 4;
        int co = tmp & 63, half = tmp >> 6;
        float v = (k < 5) ? enc0[(long)(half * 64 + co) * 5 + k] : 0.f;
        __nv_bfloat16 h, l; split_bf16(v, h, l);
        g_w1H[e] = h;  g_w1L[e] = l;
        return;
    }
    int cinv = (L == 6) ? 64 : 32;
    int cinp = cinv;
    int total = 640 * cinp;
    if (e >= total) return;
    int ci  = e % cinp;
    int tmp = e / cinp;
    int co  = tmp & 63;  tmp >>= 6;
    int t   = tmp % 5, half = tmp / 5;
    const float* src;
    if (L <= 5) src = enc + (L - 1) * 20480;
    else if (L == 6) src = decf0;
    else if (L <= 9) src = decf + (L - 7) * 20480;
    else src = decv + (L - 10) * 20480;
    float v = src[(long)(half * 64 + co) * (cinv * 5) + ci * 5 + t];
    __nv_bfloat16 h, l; split_bf16(v, h, l);
    g_w1H[c_OFF1[L] + e] = h;
    g_w1L[c_OFF1[L] + e] = l;
}

__global__ void prep_w2(const float* __restrict__ enc0, const float* __restrict__ enc,
                        const float* __restrict__ decf0, const float* __restrict__ decf,
                        const float* __restrict__ decv, const float* __restrict__ comp)
{
    int L = blockIdx.y;
    int sz = (L == 18) ? 12288 : 4096;
    int e = blockIdx.x * 256 + threadIdx.x;
    if (e >= sz) return;
    const float* src;
    if (L == 0) src = enc0;
    else if (L <= 5) src = enc + (L - 1) * 4096;
    else if (L == 6) src = decf0;
    else if (L <= 9) src = decf + (L - 7) * 4096;
    else if (L <= 17) src = decv + (L - 10) * 4096;
    else src = comp;
    long off = (L == 18) ? 73728 : (long)L * 4096;
    __nv_bfloat16 h, l; split_bf16(src[e], h, l);
    g_w2H[off + e] = h;
    g_w2L[off + e] = l;
}

// ------------------------------------------------------------------
// Fused TCN block (bf16 hi/lo planes end-to-end, LDSM, cp.async staging):
//   conv1: CIN -> 128 (k=5, dil DIL) + bias + relu, two co-halves of 64
//   conv2: 128 -> 32 (1x1) + bias + relu
// CIN==1 (FOLD): taps folded into K=16, one mma round per half.
// All staging (x tile incl. zero-filled halo, W2, W1 taps) is cp.async.
// 512 thr = 16 warps, 2 CTAs/SM.
// ------------------------------------------------------------------
template<int CIN, int DIL, int TIL>
__global__ void __launch_bounds__(512, 2)
block_mma_kernel(const void* __restrict__ xHv, const void* __restrict__ xLv, long xss,
                 const __nv_bfloat16* __restrict__ w1Hg, const __nv_bfloat16* __restrict__ w1Lg,
                 const __nv_bfloat16* __restrict__ w2Hg, const __nv_bfloat16* __restrict__ w2Lg,
                 const float* __restrict__ b1, const float* __restrict__ b2,
                 __nv_bfloat16* __restrict__ yH, __nv_bfloat16* __restrict__ yL, long yss,
                 const int* __restrict__ ids,
                 long w1_cs, long b1_cs, long w2_cs, long b2_cs)
{
    constexpr bool FOLD = (CIN == 1);
    constexpr int CINP = FOLD ? 16 : CIN;
    constexpr int XW   = FOLD ? TIL : (TIL + 4 * DIL);
    constexpr int NK   = CINP / 16;
    constexpr int SB   = CINP + 8;       // xt / wa row stride (bf16)
    constexpr int SH   = 72;             // hT row stride
    constexpr int S2   = 136;            // w2 row stride
    constexpr int NT   = TIL / 64;
    constexpr bool DBUF = (!FOLD && CIN <= 32);
    constexpr int NBUF = DBUF ? 2 : 1;
    constexpr int WBUF = 64 * SB;
    constexpr int WW   = 64 * CINP / 2;      // words per tap per half per plane
    constexpr int WRW  = CINP / 2;           // words per co row
    constexpr int CHK  = WRW / 4;            // 16B chunks per co row
    constexpr int NCP  = 64 * CHK;           // chunks per plane per tap

    extern __shared__ __nv_bfloat16 smb[];
    __nv_bfloat16* xtH = smb;
    __nv_bfloat16* xtL = xtH + XW * SB;
    __nv_bfloat16* waB = xtL + XW * SB;      // H bufs then L bufs
    __nv_bfloat16* hH  = waB + 2 * NBUF * WBUF;
    __nv_bfloat16* hL  = hH  + TIL * SH;
    __nv_bfloat16* w2H = hL  + TIL * SH;
    __nv_bfloat16* w2L = w2H + 32 * S2;
    float* b1s = (float*)(w2L + 32 * S2);
    float* b2s = b1s + 128;

    const int b    = blockIdx.y;
    const int l0   = blockIdx.x * TIL;
    const int tid  = threadIdx.x;
    const int warp = tid >> 5;
    const int ln   = tid & 31;
    const int lq   = ln & 3;
    const int lg   = ln >> 2;
    const int lr   = ln & 7;
    const int lt   = ln >> 3;

    const __nv_bfloat16* w1Hp = w1Hg;
    const __nv_bfloat16* w1Lp = w1Lg;
    const __nv_bfloat16* w2Hp = w2Hg;
    const __nv_bfloat16* w2Lp = w2Lg;
    const float* b1p = b1;
    const float* b2p = b2;
    if (ids) {
        int c = ids[b];
        w1Hp += (long)c * w1_cs;  w1Lp += (long)c * w1_cs;
        w2Hp += (long)c * w2_cs;  w2Lp += (long)c * w2_cs;
        b1p  += (long)c * b1_cs;  b2p  += (long)c * b2_cs;
    }

    // ---- stage x (async; zero-fill halo) ----
    if constexpr (FOLD) {
        // xt[r][k] = x[l0 - 2*DIL + r + k*DIL], k<5 real (scattered; scalar)
        const float* xf = (const float*)xHv + (long)b * xss;
        for (int i = tid; i < TIL * 16; i += 512) {
            int r = i >> 4, k = i & 15;
            int pos = l0 - 2 * DIL + r + k * DIL;
            float v = (k < 5 && pos >= 0 && pos < LLEN) ? xf[pos] : 0.f;
            __nv_bfloat16 hv, lv; split_bf16(v, hv, lv);
            xtH[r * SB + k] = hv;
            xtL[r * SB + k] = lv;
        }
    } else {
        constexpr int WR  = CIN / 2;       // words per row
        constexpr int RCH = WR / 4;        // 16B chunks per row
        const char* xbH = (const char*)((const __nv_bfloat16*)xHv + (long)b * xss);
        const char* xbL = (const char*)((const __nv_bfloat16*)xLv + (long)b * xss);
        for (int i = tid; i < XW * RCH * 2; i += 512) {
            int pl = i / (XW * RCH);
            int q  = i - pl * (XW * RCH);
            int r  = q / RCH, ck = q - r * RCH;
            int pos = l0 - 2 * DIL + r;
            bool ok = (pos >= 0 && pos < LLEN);
            const char* src = (pl ? xbL : xbH) + ((long)(ok ? pos : 0) * WR + ck * 4) * 4;
            unsigned dst = su32((pl ? xtL : xtH) + r * SB) + ck * 16;
            cpa16z(dst, src, ok ? 16 : 0);
        }
    }
    // ---- stage W2 (async) + biases ----
    for (int i = tid; i < 1024; i += 512) {
        int pl = i >> 9, q = i & 511;
        int co = q >> 4, ck = q & 15;
        const char* src = (const char*)(pl ? w2Lp : w2Hp) + (co * 64 + ck * 4) * 4;
        unsigned dst = su32((pl ? w2L : w2H) + co * S2) + ck * 16;
        cpa16(dst, src);
    }
    if (tid < 128) b1s[tid] = b1p[tid];
    if (tid < 32)  b2s[tid] = b2p[tid];

    const int wm  = warp >> 3;
    const int wn  = warp & 7;
    const int wm2 = warp & 1;
    const int wn2 = warp >> 1;

    float a2[NT][4];
    #pragma unroll
    for (int nt = 0; nt < NT; nt++)
        #pragma unroll
        for (int q = 0; q < 4; q++) a2[nt][q] = 0.f;

    #pragma unroll
    for (int half = 0; half < 2; half++) {
        const int coB = half * 64;

        float acc[2][NT][4];
        #pragma unroll
        for (int mt = 0; mt < 2; mt++)
            #pragma unroll
            for (int nt = 0; nt < NT; nt++)
                #pragma unroll
                for (int q = 0; q < 4; q++) acc[mt][nt][q] = 0.f;

        if constexpr (FOLD) {
            // ---- stage folded weights for this half (cp.async) ----
            if (tid < 256) {
                int pl = tid >> 7, q = tid & 127;   // 128 chunks per plane
                int co = q >> 1, ck = q & 1;        // 2x16B per co row
                const __nv_bfloat16* srcp = pl ? w1Lp : w1Hp;
                __nv_bfloat16* dstp = pl ? (waB + WBUF) : waB;
                cpa16(su32(dstp + co * SB) + ck * 16,
                      (const char*)srcp + half * 2048 + co * 32 + ck * 16);
            }
            CP_COMMIT(); CP_WAIT0();
            __syncthreads();

            // ---- single-kc conv1 mma ----
            unsigned ah[2][4], al[2][4];
            #pragma unroll
            for (int mt = 0; mt < 2; mt++) {
                int arow = wm * 32 + mt * 16 + lr + (lt & 1) * 8;
                int acol = (lt >> 1) * 8;
                ldsm4(ah[mt], su32(waB + arow * SB + acol));
                ldsm4(al[mt], su32(waB + WBUF + arow * SB + acol));
            }
            unsigned bh[4], bl[4];
            if (NT == 2) {
                int brow = wn * 16 + lr + (lt & 1) * 8;
                int bcol = (lt >> 1) * 8;
                ldsm4(bh, su32(xtH + brow * SB + bcol));
                ldsm4(bl, su32(xtL + brow * SB + bcol));
            } else {
                int brow = wn * 8 + lr;
                int bcol = ((ln >> 3) & 1) * 8;
                ldsm2(bh, su32(xtH + brow * SB + bcol));
                ldsm2(bl, su32(xtL + brow * SB + bcol));
            }
            #pragma unroll
            for (int nt = 0; nt < NT; nt++) {
                unsigned bh0 = (NT == 2) ? bh[nt] : bh[0];
                unsigned bh1 = (NT == 2) ? bh[nt + 2] : bh[1];
                unsigned bl0 = (NT == 2) ? bl[nt] : bl[0];
                unsigned bl1 = (NT == 2) ? bl[nt + 2] : bl[1];
                #pragma unroll
                for (int mt = 0; mt < 2; mt++) {
                    mma_bf16(acc[mt][nt], ah[mt], bh0, bh1);
                    mma_bf16(acc[mt][nt], ah[mt], bl0, bl1);
                    mma_bf16(acc[mt][nt], al[mt], bh0, bh1);
                }
            }
        } else {
            const char* w1Hh = (const char*)w1Hp + (size_t)half * 5 * WW * 4;
            const char* w1Lh = (const char*)w1Lp + (size_t)half * 5 * WW * 4;

            // stage_w: issue cp.async for tap tt into buffer bufsel
            auto stage_w = [&](int tt, int bufsel) {
                __nv_bfloat16* dH = waB + bufsel * WBUF;
                __nv_bfloat16* dL = dH + NBUF * WBUF;
                const char* sH = w1Hh + (size_t)tt * WW * 4;
                const char* sL = w1Lh + (size_t)tt * WW * 4;
                #pragma unroll
                for (int j = 0; j < (2 * NCP) / 512; j++) {
                    int i = tid + j * 512;
                    int pl = i / NCP, q = i - pl * NCP;
                    int co = q / CHK, ck = q - co * CHK;
                    const char* s = (pl ? sL : sH) + co * (WRW * 4) + ck * 16;
                    unsigned d = su32((pl ? dL : dH) + co * SB) + ck * 16;
                    cpa16(d, s);
                }
            };

            // ---- preload t=0 (joins the x / w2 async batch) ----
            stage_w(0, 0);
            CP_COMMIT(); CP_WAIT0();
            __syncthreads();

            #pragma unroll
            for (int t = 0; t < 5; t++) {
                if (DBUF && t < 4) {
                    stage_w(t + 1, (t + 1) & 1);   // overlaps this tap's mma
                    CP_COMMIT();
                }

                const __nv_bfloat16* wH = waB + (DBUF ? (t & 1) * WBUF : 0);
                const __nv_bfloat16* wL = wH + NBUF * WBUF;

                #pragma unroll
                for (int kc = 0; kc < NK; kc++) {
                    unsigned ah[2][4], al[2][4];
                    #pragma unroll
                    for (int mt = 0; mt < 2; mt++) {
                        int arow = wm * 32 + mt * 16 + lr + (lt & 1) * 8;
                        int acol = kc * 16 + (lt >> 1) * 8;
                        ldsm4(ah[mt], su32(wH + arow * SB + acol));
                        ldsm4(al[mt], su32(wL + arow * SB + acol));
                    }
                    unsigned bh[4], bl[4];
                    if (NT == 2) {
                        int brow = wn * 16 + lr + (lt & 1) * 8 + t * DIL;
                        int bcol = kc * 16 + (lt >> 1) * 8;
                        ldsm4(bh, su32(xtH + brow * SB + bcol));
                        ldsm4(bl, su32(xtL + brow * SB + bcol));
                    } else {
                        int brow = wn * 8 + lr + t * DIL;
                        int bcol = kc * 16 + ((ln >> 3) & 1) * 8;
                        ldsm2(bh, su32(xtH + brow * SB + bcol));
                        ldsm2(bl, su32(xtL + brow * SB + bcol));
                    }
                    #pragma unroll
                    for (int nt = 0; nt < NT; nt++) {
                        unsigned bh0 = (NT == 2) ? bh[nt] : bh[0];
                        unsigned bh1 = (NT == 2) ? bh[nt + 2] : bh[1];
                        unsigned bl0 = (NT == 2) ? bl[nt] : bl[0];
                        unsigned bl1 = (NT == 2) ? bl[nt + 2] : bl[1];
                        #pragma unroll
                        for (int mt = 0; mt < 2; mt++) {
                            mma_bf16(acc[mt][nt], ah[mt], bh0, bh1);
                            mma_bf16(acc[mt][nt], ah[mt], bl0, bl1);
                            mma_bf16(acc[mt][nt], al[mt], bh0, bh1);
                        }
                    }
                }

                if (t < 4) {
                    if (!DBUF) {
                        __syncthreads();          // all readers done w/ buf0
                        stage_w(t + 1, 0);
                        CP_COMMIT();
                    }
                    CP_WAIT0();
                    __syncthreads();
                }
            }
        }

        // ---- conv1 epilogue: bias + relu + split -> hT (l-major) ----
        __syncthreads();
        #pragma unroll
        for (int mt = 0; mt < 2; mt++) {
            int m = wm * 32 + mt * 16 + lg;
            float bb0 = b1s[coB + m], bb1 = b1s[coB + m + 8];
            #pragma unroll
            for (int nt = 0; nt < NT; nt++) {
                int n = ((NT == 2) ? wn * 16 + nt * 8 : wn * 8) + 2 * lq;
                float* a = acc[mt][nt];
                float v00 = a[0] + bb0, v01 = a[1] + bb0;
                float v10 = a[2] + bb1, v11 = a[3] + bb1;
                v00 = v00 > 0.f ? v00 : 0.f;  v01 = v01 > 0.f ? v01 : 0.f;
                v10 = v10 > 0.f ? v10 : 0.f;  v11 = v11 > 0.f ? v11 : 0.f;
                __nv_bfloat16 hv, lv;
                split_bf16(v00, hv, lv); hH[n * SH + m] = hv;           hL[n * SH + m] = lv;
                split_bf16(v01, hv, lv); hH[(n + 1) * SH + m] = hv;     hL[(n + 1) * SH + m] = lv;
                split_bf16(v10, hv, lv); hH[n * SH + m + 8] = hv;       hL[n * SH + m + 8] = lv;
                split_bf16(v11, hv, lv); hH[(n + 1) * SH + m + 8] = hv; hL[(n + 1) * SH + m + 8] = lv;
            }
        }
        __syncthreads();

        // ---- conv2 partial ----
        #pragma unroll
        for (int kc = 0; kc < 4; kc++) {
            unsigned ah[4], al[4];
            {
                int arow = wm2 * 16 + lr + (lt & 1) * 8;
                int acol = coB + kc * 16 + (lt >> 1) * 8;
                ldsm4(ah, su32(w2H + arow * S2 + acol));
                ldsm4(al, su32(w2L + arow * S2 + acol));
            }
            unsigned bh[4], bl[4];
            if (NT == 2) {
                int brow = wn2 * 16 + lr + (lt & 1) * 8;
                int bcol = kc * 16 + (lt >> 1) * 8;
                ldsm4(bh, su32(hH + brow * SH + bcol));
                ldsm4(bl, su32(hL + brow * SH + bcol));
            } else {
                int brow = wn2 * 8 + lr;
                int bcol = kc * 16 + ((ln >> 3) & 1) * 8;
                ldsm2(bh, su32(hH + brow * SH + bcol));
                ldsm2(bl, su32(hL + brow * SH + bcol));
            }
            #pragma unroll
            for (int nt = 0; nt < NT; nt++) {
                unsigned bh0 = (NT == 2) ? bh[nt] : bh[0];
                unsigned bh1 = (NT == 2) ? bh[nt + 2] : bh[1];
                unsigned bl0 = (NT == 2) ? bl[nt] : bl[0];
                unsigned bl1 = (NT == 2) ? bl[nt + 2] : bl[1];
                mma_bf16(a2[nt], ah, bh0, bh1);
                mma_bf16(a2[nt], ah, bl0, bl1);
                mma_bf16(a2[nt], al, bh0, bh1);
            }
        }
    }

    // ---- conv2 epilogue: bias + relu + split -> y planes [l][co] ----
    __nv_bfloat16* yHb = yH + (long)b * yss;
    __nv_bfloat16* yLb = yL + (long)b * yss;
    {
        int row = wm2 * 16 + lg;
        float bb0 = b2s[row], bb1 = b2s[row + 8];
        #pragma unroll
        for (int nt = 0; nt < NT; nt++) {
            int col = ((NT == 2) ? wn2 * 16 + nt * 8 : wn2 * 8) + 2 * lq;
            float v0 = a2[nt][0] + bb0, v1 = a2[nt][1] + bb0;
            float v2 = a2[nt][2] + bb1, v3 = a2[nt][3] + bb1;
            v0 = v0 > 0.f ? v0 : 0.f;  v1 = v1 > 0.f ? v1 : 0.f;
            v2 = v2 > 0.f ? v2 : 0.f;  v3 = v3 > 0.f ? v3 : 0.f;
            __nv_bfloat16 hv, lv;
            split_bf16(v0, hv, lv);
            yHb[(long)(l0 + col) * 32 + row] = hv;       yLb[(long)(l0 + col) * 32 + row] = lv;
            split_bf16(v1, hv, lv);
            yHb[(long)(l0 + col + 1) * 32 + row] = hv;   yLb[(long)(l0 + col + 1) * 32 + row] = lv;
            split_bf16(v2, hv, lv);
            yHb[(long)(l0 + col) * 32 + row + 8] = hv;   yLb[(long)(l0 + col) * 32 + row + 8] = lv;
            split_bf16(v3, hv, lv);
            yHb[(long)(l0 + col + 1) * 32 + row + 8] = hv; yLb[(long)(l0 + col + 1) * 32 + row + 8] = lv;
        }
    }
}

// ------------------------------------------------------------------
// compress conv (192 -> 64) + avgpool(2) + nearest-upsample(2), mma.
// ------------------------------------------------------------------
#define CTILE 64
__global__ void __launch_bounds__(512, 2)
comp_mma_kernel(const __nv_bfloat16* __restrict__ catH, const __nv_bfloat16* __restrict__ catL,
                const float* __restrict__ cb,
                __nv_bfloat16* __restrict__ uH, __nv_bfloat16* __restrict__ uL)
{
    constexpr int SA = 200;

    extern __shared__ __nv_bfloat16 smb[];
    __nv_bfloat16* xtH = smb;                  // [64 l][200]
    __nv_bfloat16* xtL = xtH + 64 * SA;
    __nv_bfloat16* waH = xtL + 64 * SA;        // [64 co][200]
    __nv_bfloat16* waL = waH + 64 * SA;
    float* cbs = (float*)(waL + 64 * SA);

    const int b    = blockIdx.y;
    const int l0   = blockIdx.x * CTILE;
    const int tid  = threadIdx.x;
    const int warp = tid >> 5;
    const int ln   = tid & 31;
    const int lq   = ln & 3;
    const int lg   = ln >> 2;
    const int lr   = ln & 7;
    const int lt   = ln >> 3;
    const int wm   = warp & 3;
    const int wn   = warp >> 2;

    // stage x tiles (async): per row, 6 planes x 16 words = 24 chunks
    const char* cbH = (const char*)(catH + (long)b * SS32);
    const char* cbL = (const char*)(catL + (long)b * SS32);
    for (int i = tid; i < 64 * 24 * 2; i += 512) {
        int pl = i / (64 * 24);
        int q  = i - pl * (64 * 24);
        int r  = q / 24, ck = q - r * 24;
        int plane = ck / 4, wi = ck - plane * 4;
        long srcoff = ((long)plane * (PLN / 2) + (long)(l0 + r) * 16 + wi * 4) * 4;
        unsigned dst = su32((pl ? xtL : xtH) + r * SA) + (plane * 16 + wi * 4) * 4;
        cpa16(dst, (pl ? cbL : cbH) + srcoff);
    }
    {
        const char* sH = (const char*)(g_w2H + 73728);
        const char* sL = (const char*)(g_w2L + 73728);
        for (int i = tid; i < 64 * 24 * 2; i += 512) {
            int pl = i / (64 * 24);
            int q  = i - pl * (64 * 24);
            int co = q / 24, ck = q - co * 24;
            unsigned dst = su32((pl ? waL : waH) + co * SA) + ck * 16;
            cpa16(dst, (pl ? sL : sH) + (co * 96 + ck * 4) * 4);
        }
    }
    if (tid < 64) cbs[tid] = cb[tid];
    CP_COMMIT(); CP_WAIT0();
    __syncthreads();

    float acc[2][4];
    #pragma unroll
    for (int nt = 0; nt < 2; nt++)
        #pragma unroll
        for (int q = 0; q < 4; q++) acc[nt][q] = 0.f;

    #pragma unroll
    for (int kc = 0; kc < 12; kc++) {
        unsigned ah[4], al[4];
        {
            int arow = wm * 16 + lr + (lt & 1) * 8;
            int acol = kc * 16 + (lt >> 1) * 8;
            ldsm4(ah, su32(waH + arow * SA + acol));
            ldsm4(al, su32(waL + arow * SA + acol));
        }
        unsigned bh[4], bl[4];
        {
            int brow = wn * 16 + lr + (lt & 1) * 8;
            int bcol = kc * 16 + (lt >> 1) * 8;
            ldsm4(bh, su32(xtH + brow * SA + bcol));
            ldsm4(bl, su32(xtL + brow * SA + bcol));
        }
        #pragma unroll
        for (int nt = 0; nt < 2; nt++) {
            mma_bf16(acc[nt], ah, bh[nt], bh[nt + 2]);
            mma_bf16(acc[nt], ah, bl[nt], bl[nt + 2]);
            mma_bf16(acc[nt], al, bh[nt], bh[nt + 2]);
        }
    }

    __nv_bfloat16* uHb = uH + (long)b * SSU;
    __nv_bfloat16* uLb = uL + (long)b * SSU;
    {
        int m = wm * 16 + lg;
        float bb0 = cbs[m], bb1 = cbs[m + 8];
        #pragma unroll
        for (int nt = 0; nt < 2; nt++) {
            int n = wn * 16 + nt * 8 + 2 * lq;
            float* a = acc[nt];
            float p0 = 0.5f * ((a[0] + bb0) + (a[1] + bb0));
            float p1 = 0.5f * ((a[2] + bb1) + (a[3] + bb1));
            __nv_bfloat16 hv, lv;
            split_bf16(p0, hv, lv);
            uHb[(long)(l0 + n) * 64 + m] = hv;      uHb[(long)(l0 + n + 1) * 64 + m] = hv;
            uLb[(long)(l0 + n) * 64 + m] = lv;      uLb[(long)(l0 + n + 1) * 64 + m] = lv;
            split_bf16(p1, hv, lv);
            uHb[(long)(l0 + n) * 64 + m + 8] = hv;  uHb[(long)(l0 + n + 1) * 64 + m + 8] = hv;
            uLb[(long)(l0 + n) * 64 + m + 8] = lv;  uLb[(long)(l0 + n + 1) * 64 + m + 8] = lv;
        }
    }
}

// ------------------------------------------------------------------
// final per-sample 1x1 conv: 192 -> 1, from dec planes. Grid (4, NB).
// ------------------------------------------------------------------
__global__ void __launch_bounds__(256, 1)
final_kernel(const __nv_bfloat16* __restrict__ decH, const __nv_bfloat16* __restrict__ decL,
             const float* __restrict__ cw, const float* __restrict__ cbv,
             float* __restrict__ out)
{
    __shared__ float ws[192];
    const int b   = blockIdx.y;
    const int tid = threadIdx.x;
    const int l   = blockIdx.x * 256 + tid;
    const int c   = g_ids[b];
    if (tid < 192) ws[tid] = cw[(long)c * 192 + tid];
    __syncthreads();
    float s = cbv[c];
    #pragma unroll
    for (int plane = 0; plane < 6; plane++) {
        const unsigned* pH = (const unsigned*)(decH + (long)b * SS32 + (long)plane * PLN + (long)l * 32);
        const unsigned* pL = (const unsigned*)(decL + (long)b * SS32 + (long)plane * PLN + (long)l * 32);
        #pragma unroll
        for (int w = 0; w < 16; w++) {
            unsigned uh = pH[w], ul = pL[w];
            float2 fh = __bfloat1622float2(*(const __nv_bfloat162*)&uh);
            float2 fl = __bfloat1622float2(*(const __nv_bfloat162*)&ul);
            s = fmaf(ws[plane * 32 + 2 * w],     fh.x + fl.x, s);
            s = fmaf(ws[plane * 32 + 2 * w + 1], fh.y + fl.y, s);
        }
    }
    out[(long)b * LLEN + l] = s;
}

// ------------------------------------------------------------------
static constexpr int smem_mma(int cin, int dil, int til) {
    bool fold = (cin == 1);
    int cinp = fold ? 16 : cin;
    int sb   = cinp + 8;
    int nbuf = (!fold && cin <= 32) ? 2 : 1;
    int xw   = fold ? til : (til + 4 * dil);
    int elems = 2 * xw * sb + 2 * nbuf * 64 * sb + 2 * til * 72 + 2 * 32 * 136;
    return elems * 2 + 160 * 4;
}
static constexpr int SMEM_C = (4 * 64 * 200) * 2 + 256;

template<int CIN, int DIL, int TIL>
static void launch_block(const void* xH, const void* xL, long xss,
                         const __nv_bfloat16* w1H, const __nv_bfloat16* w1L,
                         const __nv_bfloat16* w2H, const __nv_bfloat16* w2L,
                         const float* b1, const float* b2,
                         __nv_bfloat16* yH, __nv_bfloat16* yL, long yss,
                         const int* ids, long w1cs, long b1cs, long w2cs, long b2cs)
{
    static bool attr_done = false;
    if (!attr_done) {
        cudaFuncSetAttribute(block_mma_kernel<CIN, DIL, TIL>,
                             cudaFuncAttributeMaxDynamicSharedMemorySize,
                             smem_mma(CIN, DIL, TIL));
        attr_done = true;
    }
    dim3 grid(LLEN / TIL, NB);
    block_mma_kernel<CIN, DIL, TIL><<<grid, 512, smem_mma(CIN, DIL, TIL)>>>(
        xH, xL, xss, w1H, w1L, w2H, w2L, b1, b2, yH, yL, yss,
        ids, w1cs, b1cs, w2cs, b2cs);
}

extern "C" void kernel_launch(void* const* d_in, const int* in_sizes, int n_in,
                              void* d_out, int out_size)
{
    const float* x        = (const float*)d_in[0];
    const float* enc0_b1  = (const float*)d_in[2];
    const float* enc0_b2  = (const float*)d_in[4];
    const float* enc_b1   = (const float*)d_in[6];
    const float* enc_b2   = (const float*)d_in[8];
    const float* comp_b   = (const float*)d_in[10];
    const float* decf0_b1 = (const float*)d_in[12];
    const float* decf0_b2 = (const float*)d_in[14];
    const float* decf_b1  = (const float*)d_in[16];
    const float* decf_b2  = (const float*)d_in[18];
    const float* decv_b1  = (const float*)d_in[20];
    const float* decv_b2  = (const float*)d_in[22];
    const float* decv_cw  = (const float*)d_in[23];
    const float* decv_cb  = (const float*)d_in[24];
    float* out = (float*)d_out;

    __nv_bfloat16 *catH, *catL, *decH, *decL, *uH, *uL, *w1H, *w1L, *w2H, *w2L;
    int* idsp;
    cudaGetSymbolAddress((void**)&catH, g_catH);
    cudaGetSymbolAddress((void**)&catL, g_catL);
    cudaGetSymbolAddress((void**)&decH, g_decH);
    cudaGetSymbolAddress((void**)&decL, g_decL);
    cudaGetSymbolAddress((void**)&uH,   g_encUH);
    cudaGetSymbolAddress((void**)&uL,   g_encUL);
    cudaGetSymbolAddress((void**)&w1H,  g_w1H);
    cudaGetSymbolAddress((void**)&w1L,  g_w1L);
    cudaGetSymbolAddress((void**)&w2H,  g_w2H);
    cudaGetSymbolAddress((void**)&w2L,  g_w2L);
    cudaGetSymbolAddress((void**)&idsp, g_ids);

    static bool comp_attr = false;
    if (!comp_attr) {
        cudaFuncSetAttribute(comp_mma_kernel,
                             cudaFuncAttributeMaxDynamicSharedMemorySize, SMEM_C);
        comp_attr = true;
    }

    ids_kernel<<<1, 64>>>(x);
    {
        dim3 g1(160, 18);
        prep_w1<<<g1, 256>>>((const float*)d_in[1], (const float*)d_in[5],
                             (const float*)d_in[11], (const float*)d_in[15],
                             (const float*)d_in[19]);
        dim3 g2(48, 19);
        prep_w2<<<g2, 256>>>((const float*)d_in[3], (const float*)d_in[7],
                             (const float*)d_in[13], (const float*)d_in[17],
                             (const float*)d_in[21], (const float*)d_in[9]);
    }

    static const int OFF1[18] = {
        0, 10240, 30720, 51200, 71680, 92160, 112640,
        153600, 174080, 194560,
        215040, 235520, 256000, 276480, 296960, 317440, 337920, 358400};

    // ---- encoder ----
    launch_block<1, 1, 128>(x, nullptr, (long)(LLEN + 1),
                            w1H + OFF1[0], w1L + OFF1[0], w2H + 0, w2L + 0,
                            enc0_b1, enc0_b2,
                            catH, catL, SS32, nullptr, 0, 0, 0, 0);
    launch_block<32, 2, 128>(catH + 0 * PLN, catL + 0 * PLN, SS32,
                             w1H + OFF1[1], w1L + OFF1[1], w2H + 1 * 4096, w2L + 1 * 4096,
                             enc_b1 + 0 * 128, enc_b2 + 0 * 32,
                             catH + 1 * PLN, catL + 1 * PLN, SS32, nullptr, 0, 0, 0, 0);
    launch_block<32, 4, 128>(catH + 1 * PLN, catL + 1 * PLN, SS32,
                             w1H + OFF1[2], w1L + OFF1[2], w2H + 2 * 4096, w2L + 2 * 4096,
                             enc_b1 + 1 * 128, enc_b2 + 1 * 32,
                             catH + 2 * PLN, catL + 2 * PLN, SS32, nullptr, 0, 0, 0, 0);
    launch_block<32, 8, 128>(catH + 2 * PLN, catL + 2 * PLN, SS32,
                             w1H + OFF1[3], w1L + OFF1[3], w2H + 3 * 4096, w2L + 3 * 4096,
                             enc_b1 + 2 * 128, enc_b2 + 2 * 32,
                             catH + 3 * PLN, catL + 3 * PLN, SS32, nullptr, 0, 0, 0, 0);
    launch_block<32, 16, 128>(catH + 3 * PLN, catL + 3 * PLN, SS32,
                              w1H + OFF1[4], w1L + OFF1[4], w2H + 4 * 4096, w2L + 4 * 4096,
                              enc_b1 + 3 * 128, enc_b2 + 3 * 32,
                              catH + 4 * PLN, catL + 4 * PLN, SS32, nullptr, 0, 0, 0, 0);
    launch_block<32, 32, 64>(catH + 4 * PLN, catL + 4 * PLN, SS32,
                             w1H + OFF1[5], w1L + OFF1[5], w2H + 5 * 4096, w2L + 5 * 4096,
                             enc_b1 + 4 * 128, enc_b2 + 4 * 32,
                             catH + 5 * PLN, catL + 5 * PLN, SS32, nullptr, 0, 0, 0, 0);

    // ---- compress + pool + upsample ----
    {
        dim3 grid(LLEN / CTILE, NB);
        comp_mma_kernel<<<grid, 512, SMEM_C>>>(catH, catL, comp_b, uH, uL);
    }

    // ---- fixed decoder ----
    launch_block<64, 32, 64>(uH, uL, (long)SSU,
                             w1H + OFF1[6], w1L + OFF1[6], w2H + 6 * 4096, w2L + 6 * 4096,
                             decf0_b1, decf0_b2,
                             decH, decL, SS32, nullptr, 0, 0, 0, 0);
    launch_block<32, 16, 128>(decH + 0 * PLN, decL + 0 * PLN, SS32,
                              w1H + OFF1[7], w1L + OFF1[7], w2H + 7 * 4096, w2L + 7 * 4096,
                              decf_b1 + 0 * 128, decf_b2 + 0 * 32,
                              decH + 1 * PLN, decL + 1 * PLN, SS32, nullptr, 0, 0, 0, 0);
    launch_block<32, 8, 128>(decH + 1 * PLN, decL + 1 * PLN, SS32,
                             w1H + OFF1[8], w1L + OFF1[8], w2H + 8 * 4096, w2L + 8 * 4096,
                             decf_b1 + 1 * 128, decf_b2 + 1 * 32,
                             decH + 2 * PLN, decL + 2 * PLN, SS32, nullptr, 0, 0, 0, 0);
    launch_block<32, 4, 128>(decH + 2 * PLN, decL + 2 * PLN, SS32,
                             w1H + OFF1[9], w1L + OFF1[9], w2H + 9 * 4096, w2L + 9 * 4096,
                             decf_b1 + 2 * 128, decf_b2 + 2 * 32,
                             decH + 3 * PLN, decL + 3 * PLN, SS32, nullptr, 0, 0, 0, 0);

    // ---- variable decoder: per-sample selected combination ----
    launch_block<32, 2, 128>(decH + 3 * PLN, decL + 3 * PLN, SS32,
                             w1H + OFF1[10], w1L + OFF1[10],
                             w2H + 10 * 4096, w2L + 10 * 4096,
                             decv_b1 + 0 * 128, decv_b2 + 0 * 32,
                             decH + 4 * PLN, decL + 4 * PLN, SS32,
                             idsp, 40960, 256, 8192, 64);
    launch_block<32, 1, 128>(decH + 4 * PLN, decL + 4 * PLN, SS32,
                             w1H + OFF1[10] + 20480, w1L + OFF1[10] + 20480,
                             w2H + 11 * 4096, w2L + 11 * 4096,
                             decv_b1 + 1 * 128, decv_b2 + 1 * 32,
                             decH + 5 * PLN, decL + 5 * PLN, SS32,
                             idsp, 40960, 256, 8192, 64);

    // ---- final 1x1 conv (per-sample weights) ----
    {
        dim3 grid(4, NB);
        final_kernel<<<grid, 256>>>(decH, decL, decv_cw, decv_cb, out);
    }
}

// round 13
// speedup vs baseline: 1.5391x; 1.0276x over previous
#include <cuda_runtime.h>
#include <cuda_bf16.h>

#define LLEN 1024
#define NB   64
#define PLN  (LLEN * 32)          // one 32-ch plane, elems
#define SS32 (6 * PLN)            // cat/dec sample stride (elems)
#define SSU  (LLEN * 64)          // encU sample stride

// ---- device scratch (no allocations allowed) ----
__device__ __nv_bfloat16 g_catH[NB * SS32], g_catL[NB * SS32];
__device__ __nv_bfloat16 g_decH[NB * SS32], g_decL[NB * SS32];
__device__ __nv_bfloat16 g_encUH[NB * SSU], g_encUL[NB * SSU];
__device__ __nv_bfloat16 g_w1H[378880], g_w1L[378880];
__device__ __nv_bfloat16 g_w2H[86016],  g_w2L[86016];
__device__ int g_ids[NB];

__constant__ int c_OFF1[18] = {
    0, 10240, 30720, 51200, 71680, 92160, 112640,
    153600, 174080, 194560,
    215040, 235520, 256000, 276480, 296960, 317440, 337920, 358400};

// ------------------------------------------------------------------
__global__ void ids_kernel(const float* __restrict__ x) {
    int b = threadIdx.x;
    if (b < NB) g_ids[b] = (int)x[(long)b * (LLEN + 1) + LLEN];
}

__device__ __forceinline__ void mma_bf16(float* c, const unsigned* a,
                                         unsigned b0, unsigned b1) {
    asm volatile(
        "mma.sync.aligned.m16n8k16.row.col.f32.bf16.bf16.f32 "
        "{%0,%1,%2,%3}, {%4,%5,%6,%7}, {%8,%9}, {%0,%1,%2,%3};\n"
        : "+f"(c[0]), "+f"(c[1]), "+f"(c[2]), "+f"(c[3])
        : "r"(a[0]), "r"(a[1]), "r"(a[2]), "r"(a[3]), "r"(b0), "r"(b1));
}
__device__ __forceinline__ void ldsm4(unsigned* r, unsigned addr) {
    asm volatile("ldmatrix.sync.aligned.m8n8.x4.shared.b16 {%0,%1,%2,%3}, [%4];\n"
                 : "=r"(r[0]), "=r"(r[1]), "=r"(r[2]), "=r"(r[3]) : "r"(addr));
}
__device__ __forceinline__ void ldsm2(unsigned* r, unsigned addr) {
    asm volatile("ldmatrix.sync.aligned.m8n8.x2.shared.b16 {%0,%1}, [%2];\n"
                 : "=r"(r[0]), "=r"(r[1]) : "r"(addr));
}
__device__ __forceinline__ void ldsm4t(unsigned* r, unsigned addr) {
    asm volatile("ldmatrix.sync.aligned.m8n8.x4.trans.shared.b16 {%0,%1,%2,%3}, [%4];\n"
                 : "=r"(r[0]), "=r"(r[1]), "=r"(r[2]), "=r"(r[3]) : "r"(addr));
}
__device__ __forceinline__ void ldsm2t(unsigned* r, unsigned addr) {
    asm volatile("ldmatrix.sync.aligned.m8n8.x2.trans.shared.b16 {%0,%1}, [%2];\n"
                 : "=r"(r[0]), "=r"(r[1]) : "r"(addr));
}
__device__ __forceinline__ unsigned su32(const void* p) {
    return (unsigned)__cvta_generic_to_shared(p);
}
__device__ __forceinline__ void cpa16(unsigned dst, const void* src) {
    asm volatile("cp.async.ca.shared.global [%0], [%1], 16;\n"
                 :: "r"(dst), "l"(src));
}
__device__ __forceinline__ void cpa16z(unsigned dst, const void* src, int sz) {
    asm volatile("cp.async.ca.shared.global [%0], [%1], 16, %2;\n"
                 :: "r"(dst), "l"(src), "r"(sz));
}
#define CP_COMMIT() asm volatile("cp.async.commit_group;\n" ::: "memory")
#define CP_WAIT0()  asm volatile("cp.async.wait_group 0;\n"  ::: "memory")

__device__ __forceinline__ void split_bf16(float v, __nv_bfloat16& hi, __nv_bfloat16& lo) {
    hi = __float2bfloat16(v);
    lo = __float2bfloat16(v - __bfloat162float(hi));
}

// ------------------------------------------------------------------
// prep kernels: split weights into bf16 hi/lo planes, staging layout
// ------------------------------------------------------------------
__global__ void prep_w1(const float* __restrict__ enc0, const float* __restrict__ enc,
                        const float* __restrict__ decf0, const float* __restrict__ decf,
                        const float* __restrict__ decv)
{
    int L = blockIdx.y;
    int e = blockIdx.x * 256 + threadIdx.x;
    if (L == 0) {
        if (e >= 2048) return;
        int k = e & 15, tmp = e >> 4;
        int co = tmp & 63, half = tmp >> 6;
        float v = (k < 5) ? enc0[(long)(half * 64 + co) * 5 + k] : 0.f;
        __nv_bfloat16 h, l; split_bf16(v, h, l);
        g_w1H[e] = h;  g_w1L[e] = l;
        return;
    }
    int cinv = (L == 6) ? 64 : 32;
    int cinp = cinv;
    int total = 640 * cinp;
    if (e >= total) return;
    int ci  = e % cinp;
    int tmp = e / cinp;
    int co  = tmp & 63;  tmp >>= 6;
    int t   = tmp % 5, half = tmp / 5;
    const float* src;
    if (L <= 5) src = enc + (L - 1) * 20480;
    else if (L == 6) src = decf0;
    else if (L <= 9) src = decf + (L - 7) * 20480;
    else src = decv + (L - 10) * 20480;
    float v = src[(long)(half * 64 + co) * (cinv * 5) + ci * 5 + t];
    __nv_bfloat16 h, l; split_bf16(v, h, l);
    g_w1H[c_OFF1[L] + e] = h;
    g_w1L[c_OFF1[L] + e] = l;
}

__global__ void prep_w2(const float* __restrict__ enc0, const float* __restrict__ enc,
                        const float* __restrict__ decf0, const float* __restrict__ decf,
                        const float* __restrict__ decv, const float* __restrict__ comp)
{
    int L = blockIdx.y;
    int sz = (L == 18) ? 12288 : 4096;
    int e = blockIdx.x * 256 + threadIdx.x;
    if (e >= sz) return;
    const float* src;
    if (L == 0) src = enc0;
    else if (L <= 5) src = enc + (L - 1) * 4096;
    else if (L == 6) src = decf0;
    else if (L <= 9) src = decf + (L - 7) * 4096;
    else if (L <= 17) src = decv + (L - 10) * 4096;
    else src = comp;
    long off = (L == 18) ? 73728 : (long)L * 4096;
    __nv_bfloat16 h, l; split_bf16(src[e], h, l);
    g_w2H[off + e] = h;
    g_w2L[off + e] = l;
}

// ------------------------------------------------------------------
// Fused TCN block (bf16 hi/lo planes end-to-end, LDSM, cp.async staging):
//   conv1: CIN -> 128 (k=5, dil DIL) + bias + relu, two co-halves of 64
//   conv2: 128 -> 32 (1x1) + bias + relu
// hs kept in natural [co][l] orientation (packed bf16x2 stores); conv2 B
// loaded via ldmatrix.trans. CIN==1 (FOLD): taps folded into K=16.
// 512 thr = 16 warps, 2 CTAs/SM.
// ------------------------------------------------------------------
template<int CIN, int DIL, int TIL>
__global__ void __launch_bounds__(512, 2)
block_mma_kernel(const void* __restrict__ xHv, const void* __restrict__ xLv, long xss,
                 const __nv_bfloat16* __restrict__ w1Hg, const __nv_bfloat16* __restrict__ w1Lg,
                 const __nv_bfloat16* __restrict__ w2Hg, const __nv_bfloat16* __restrict__ w2Lg,
                 const float* __restrict__ b1, const float* __restrict__ b2,
                 __nv_bfloat16* __restrict__ yH, __nv_bfloat16* __restrict__ yL, long yss,
                 const int* __restrict__ ids,
                 long w1_cs, long b1_cs, long w2_cs, long b2_cs)
{
    constexpr bool FOLD = (CIN == 1);
    constexpr int CINP = FOLD ? 16 : CIN;
    constexpr int XW   = FOLD ? TIL : (TIL + 4 * DIL);
    constexpr int NK   = CINP / 16;
    constexpr int SB   = CINP + 8;       // xt / wa row stride (bf16)
    constexpr int SHS  = TIL + 8;        // hs row stride (co-major)
    constexpr int S2   = 136;            // w2 row stride
    constexpr int NT   = TIL / 64;
    constexpr bool DBUF = (!FOLD && CIN <= 32);
    constexpr int NBUF = DBUF ? 2 : 1;
    constexpr int WBUF = 64 * SB;
    constexpr int WW   = 64 * CINP / 2;      // words per tap per half per plane
    constexpr int WRW  = CINP / 2;           // words per co row
    constexpr int CHK  = WRW / 4;            // 16B chunks per co row
    constexpr int NCP  = 64 * CHK;           // chunks per plane per tap

    extern __shared__ __nv_bfloat16 smb[];
    __nv_bfloat16* xtH = smb;
    __nv_bfloat16* xtL = xtH + XW * SB;
    __nv_bfloat16* waB = xtL + XW * SB;      // H bufs then L bufs
    __nv_bfloat16* hH  = waB + 2 * NBUF * WBUF;    // [64 co][SHS]
    __nv_bfloat16* hL  = hH  + 64 * SHS;
    __nv_bfloat16* w2H = hL  + 64 * SHS;
    __nv_bfloat16* w2L = w2H + 32 * S2;
    float* b1s = (float*)(w2L + 32 * S2);
    float* b2s = b1s + 128;

    const int b    = blockIdx.y;
    const int l0   = blockIdx.x * TIL;
    const int tid  = threadIdx.x;
    const int warp = tid >> 5;
    const int ln   = tid & 31;
    const int lq   = ln & 3;
    const int lg   = ln >> 2;
    const int lr   = ln & 7;
    const int lt   = ln >> 3;

    const __nv_bfloat16* w1Hp = w1Hg;
    const __nv_bfloat16* w1Lp = w1Lg;
    const __nv_bfloat16* w2Hp = w2Hg;
    const __nv_bfloat16* w2Lp = w2Lg;
    const float* b1p = b1;
    const float* b2p = b2;
    if (ids) {
        int c = ids[b];
        w1Hp += (long)c * w1_cs;  w1Lp += (long)c * w1_cs;
        w2Hp += (long)c * w2_cs;  w2Lp += (long)c * w2_cs;
        b1p  += (long)c * b1_cs;  b2p  += (long)c * b2_cs;
    }

    // ---- stage x (async; zero-fill halo) ----
    if constexpr (FOLD) {
        const float* xf = (const float*)xHv + (long)b * xss;
        for (int i = tid; i < TIL * 16; i += 512) {
            int r = i >> 4, k = i & 15;
            int pos = l0 - 2 * DIL + r + k * DIL;
            float v = (k < 5 && pos >= 0 && pos < LLEN) ? xf[pos] : 0.f;
            __nv_bfloat16 hv, lv; split_bf16(v, hv, lv);
            xtH[r * SB + k] = hv;
            xtL[r * SB + k] = lv;
        }
    } else {
        constexpr int WR  = CIN / 2;       // words per row
        constexpr int RCH = WR / 4;        // 16B chunks per row
        const char* xbH = (const char*)((const __nv_bfloat16*)xHv + (long)b * xss);
        const char* xbL = (const char*)((const __nv_bfloat16*)xLv + (long)b * xss);
        for (int i = tid; i < XW * RCH * 2; i += 512) {
            int pl = i / (XW * RCH);
            int q  = i - pl * (XW * RCH);
            int r  = q / RCH, ck = q - r * RCH;
            int pos = l0 - 2 * DIL + r;
            bool ok = (pos >= 0 && pos < LLEN);
            const char* src = (pl ? xbL : xbH) + ((long)(ok ? pos : 0) * WR + ck * 4) * 4;
            unsigned dst = su32((pl ? xtL : xtH) + r * SB) + ck * 16;
            cpa16z(dst, src, ok ? 16 : 0);
        }
    }
    // ---- stage W2 (async) + biases ----
    for (int i = tid; i < 1024; i += 512) {
        int pl = i >> 9, q = i & 511;
        int co = q >> 4, ck = q & 15;
        const char* src = (const char*)(pl ? w2Lp : w2Hp) + (co * 64 + ck * 4) * 4;
        unsigned dst = su32((pl ? w2L : w2H) + co * S2) + ck * 16;
        cpa16(dst, src);
    }
    if (tid < 128) b1s[tid] = b1p[tid];
    if (tid < 32)  b2s[tid] = b2p[tid];

    const int wm  = warp >> 3;
    const int wn  = warp & 7;
    const int wm2 = warp & 1;
    const int wn2 = warp >> 1;

    float a2[NT][4];
    #pragma unroll
    for (int nt = 0; nt < NT; nt++)
        #pragma unroll
        for (int q = 0; q < 4; q++) a2[nt][q] = 0.f;

    #pragma unroll
    for (int half = 0; half < 2; half++) {
        const int coB = half * 64;

        float acc[2][NT][4];
        #pragma unroll
        for (int mt = 0; mt < 2; mt++)
            #pragma unroll
            for (int nt = 0; nt < NT; nt++)
                #pragma unroll
                for (int q = 0; q < 4; q++) acc[mt][nt][q] = 0.f;

        if constexpr (FOLD) {
            if (tid < 256) {
                int pl = tid >> 7, q = tid & 127;
                int co = q >> 1, ck = q & 1;
                const __nv_bfloat16* srcp = pl ? w1Lp : w1Hp;
                __nv_bfloat16* dstp = pl ? (waB + WBUF) : waB;
                cpa16(su32(dstp + co * SB) + ck * 16,
                      (const char*)srcp + half * 2048 + co * 32 + ck * 16);
            }
            CP_COMMIT(); CP_WAIT0();
            __syncthreads();

            unsigned ah[2][4], al[2][4];
            #pragma unroll
            for (int mt = 0; mt < 2; mt++) {
                int arow = wm * 32 + mt * 16 + lr + (lt & 1) * 8;
                int acol = (lt >> 1) * 8;
                ldsm4(ah[mt], su32(waB + arow * SB + acol));
                ldsm4(al[mt], su32(waB + WBUF + arow * SB + acol));
            }
            unsigned bh[4], bl[4];
            if (NT == 2) {
                int brow = wn * 16 + lr + (lt & 1) * 8;
                int bcol = (lt >> 1) * 8;
                ldsm4(bh, su32(xtH + brow * SB + bcol));
                ldsm4(bl, su32(xtL + brow * SB + bcol));
            } else {
                int brow = wn * 8 + lr;
                int bcol = ((ln >> 3) & 1) * 8;
                ldsm2(bh, su32(xtH + brow * SB + bcol));
                ldsm2(bl, su32(xtL + brow * SB + bcol));
            }
            #pragma unroll
            for (int nt = 0; nt < NT; nt++) {
                unsigned bh0 = (NT == 2) ? bh[nt] : bh[0];
                unsigned bh1 = (NT == 2) ? bh[nt + 2] : bh[1];
                unsigned bl0 = (NT == 2) ? bl[nt] : bl[0];
                unsigned bl1 = (NT == 2) ? bl[nt + 2] : bl[1];
                #pragma unroll
                for (int mt = 0; mt < 2; mt++) {
                    mma_bf16(acc[mt][nt], ah[mt], bh0, bh1);
                    mma_bf16(acc[mt][nt], ah[mt], bl0, bl1);
                    mma_bf16(acc[mt][nt], al[mt], bh0, bh1);
                }
            }
        } else {
            const char* w1Hh = (const char*)w1Hp + (size_t)half * 5 * WW * 4;
            const char* w1Lh = (const char*)w1Lp + (size_t)half * 5 * WW * 4;

            auto stage_w = [&](int tt, int bufsel) {
                __nv_bfloat16* dH = waB + bufsel * WBUF;
                __nv_bfloat16* dL = dH + NBUF * WBUF;
                const char* sH = w1Hh + (size_t)tt * WW * 4;
                const char* sL = w1Lh + (size_t)tt * WW * 4;
                #pragma unroll
                for (int j = 0; j < (2 * NCP) / 512; j++) {
                    int i = tid + j * 512;
                    int pl = i / NCP, q = i - pl * NCP;
                    int co = q / CHK, ck = q - co * CHK;
                    const char* s = (pl ? sL : sH) + co * (WRW * 4) + ck * 16;
                    unsigned d = su32((pl ? dL : dH) + co * SB) + ck * 16;
                    cpa16(d, s);
                }
            };

            stage_w(0, 0);
            CP_COMMIT(); CP_WAIT0();
            __syncthreads();

            #pragma unroll
            for (int t = 0; t < 5; t++) {
                if (DBUF && t < 4) {
                    stage_w(t + 1, (t + 1) & 1);
                    CP_COMMIT();
                }

                const __nv_bfloat16* wH = waB + (DBUF ? (t & 1) * WBUF : 0);
                const __nv_bfloat16* wL = wH + NBUF * WBUF;

                #pragma unroll
                for (int kc = 0; kc < NK; kc++) {
                    unsigned ah[2][4], al[2][4];
                    #pragma unroll
                    for (int mt = 0; mt < 2; mt++) {
                        int arow = wm * 32 + mt * 16 + lr + (lt & 1) * 8;
                        int acol = kc * 16 + (lt >> 1) * 8;
                        ldsm4(ah[mt], su32(wH + arow * SB + acol));
                        ldsm4(al[mt], su32(wL + arow * SB + acol));
                    }
                    unsigned bh[4], bl[4];
                    if (NT == 2) {
                        int brow = wn * 16 + lr + (lt & 1) * 8 + t * DIL;
                        int bcol = kc * 16 + (lt >> 1) * 8;
                        ldsm4(bh, su32(xtH + brow * SB + bcol));
                        ldsm4(bl, su32(xtL + brow * SB + bcol));
                    } else {
                        int brow = wn * 8 + lr + t * DIL;
                        int bcol = kc * 16 + ((ln >> 3) & 1) * 8;
                        ldsm2(bh, su32(xtH + brow * SB + bcol));
                        ldsm2(bl, su32(xtL + brow * SB + bcol));
                    }
                    #pragma unroll
                    for (int nt = 0; nt < NT; nt++) {
                        unsigned bh0 = (NT == 2) ? bh[nt] : bh[0];
                        unsigned bh1 = (NT == 2) ? bh[nt + 2] : bh[1];
                        unsigned bl0 = (NT == 2) ? bl[nt] : bl[0];
                        unsigned bl1 = (NT == 2) ? bl[nt + 2] : bl[1];
                        #pragma unroll
                        for (int mt = 0; mt < 2; mt++) {
                            mma_bf16(acc[mt][nt], ah[mt], bh0, bh1);
                            mma_bf16(acc[mt][nt], ah[mt], bl0, bl1);
                            mma_bf16(acc[mt][nt], al[mt], bh0, bh1);
                        }
                    }
                }

                if (t < 4) {
                    if (!DBUF) {
                        __syncthreads();
                        stage_w(t + 1, 0);
                        CP_COMMIT();
                    }
                    CP_WAIT0();
                    __syncthreads();
                }
            }
        }

        // ---- conv1 epilogue: bias + relu + split -> hs [co][l], packed ----
        // (ordering vs prev-half conv2 reads is provided by this half's
        //  staging barrier; per-thread mma->epilogue dependency is automatic)
        #pragma unroll
        for (int mt = 0; mt < 2; mt++) {
            int m = wm * 32 + mt * 16 + lg;      // local co (0..63)
            float bb0 = b1s[coB + m], bb1 = b1s[coB + m + 8];
            #pragma unroll
            for (int nt = 0; nt < NT; nt++) {
                int n = ((NT == 2) ? wn * 16 + nt * 8 : wn * 8) + 2 * lq;
                float* a = acc[mt][nt];
                float v00 = a[0] + bb0, v01 = a[1] + bb0;
                float v10 = a[2] + bb1, v11 = a[3] + bb1;
                v00 = v00 > 0.f ? v00 : 0.f;  v01 = v01 > 0.f ? v01 : 0.f;
                v10 = v10 > 0.f ? v10 : 0.f;  v11 = v11 > 0.f ? v11 : 0.f;
                __nv_bfloat16 h0, l0, h1, l1;
                split_bf16(v00, h0, l0); split_bf16(v01, h1, l1);
                *(__nv_bfloat162*)(hH + m * SHS + n) = __halves2bfloat162(h0, h1);
                *(__nv_bfloat162*)(hL + m * SHS + n) = __halves2bfloat162(l0, l1);
                split_bf16(v10, h0, l0); split_bf16(v11, h1, l1);
                *(__nv_bfloat162*)(hH + (m + 8) * SHS + n) = __halves2bfloat162(h0, h1);
                *(__nv_bfloat162*)(hL + (m + 8) * SHS + n) = __halves2bfloat162(l0, l1);
            }
        }
        __syncthreads();

        // ---- conv2 partial: B via ldmatrix.trans from [co][l] hs ----
        #pragma unroll
        for (int kc = 0; kc < 4; kc++) {
            unsigned ah[4], al[4];
            {
                int arow = wm2 * 16 + lr + (lt & 1) * 8;
                int acol = coB + kc * 16 + (lt >> 1) * 8;
                ldsm4(ah, su32(w2H + arow * S2 + acol));
                ldsm4(al, su32(w2L + arow * S2 + acol));
            }
            unsigned bh[4], bl[4];
            if (NT == 2) {
                int brow = kc * 16 + (lt & 1) * 8 + lr;     // k (local co)
                int bcol = wn2 * 16 + (lt >> 1) * 8;        // n (l)
                ldsm4t(bh, su32(hH + brow * SHS + bcol));
                ldsm4t(bl, su32(hL + brow * SHS + bcol));
            } else {
                int brow = kc * 16 + ((ln >> 3) & 1) * 8 + lr;
                int bcol = wn2 * 8;
                ldsm2t(bh, su32(hH + brow * SHS + bcol));
                ldsm2t(bl, su32(hL + brow * SHS + bcol));
            }
            #pragma unroll
            for (int nt = 0; nt < NT; nt++) {
                // trans x4 order: {nt0: b0,b1, nt1: b0,b1}
                unsigned bh0 = (NT == 2) ? bh[2 * nt]     : bh[0];
                unsigned bh1 = (NT == 2) ? bh[2 * nt + 1] : bh[1];
                unsigned bl0 = (NT == 2) ? bl[2 * nt]     : bl[0];
                unsigned bl1 = (NT == 2) ? bl[2 * nt + 1] : bl[1];
                mma_bf16(a2[nt], ah, bh0, bh1);
                mma_bf16(a2[nt], ah, bl0, bl1);
                mma_bf16(a2[nt], al, bh0, bh1);
            }
        }
    }

    // ---- conv2 epilogue: bias + relu + split -> y planes [l][co] ----
    __nv_bfloat16* yHb = yH + (long)b * yss;
    __nv_bfloat16* yLb = yL + (long)b * yss;
    {
        int row = wm2 * 16 + lg;
        float bb0 = b2s[row], bb1 = b2s[row + 8];
        #pragma unroll
        for (int nt = 0; nt < NT; nt++) {
            int col = ((NT == 2) ? wn2 * 16 + nt * 8 : wn2 * 8) + 2 * lq;
            float v0 = a2[nt][0] + bb0, v1 = a2[nt][1] + bb0;
            float v2 = a2[nt][2] + bb1, v3 = a2[nt][3] + bb1;
            v0 = v0 > 0.f ? v0 : 0.f;  v1 = v1 > 0.f ? v1 : 0.f;
            v2 = v2 > 0.f ? v2 : 0.f;  v3 = v3 > 0.f ? v3 : 0.f;
            __nv_bfloat16 hv, lv;
            split_bf16(v0, hv, lv);
            yHb[(long)(l0 + col) * 32 + row] = hv;       yLb[(long)(l0 + col) * 32 + row] = lv;
            split_bf16(v1, hv, lv);
            yHb[(long)(l0 + col + 1) * 32 + row] = hv;   yLb[(long)(l0 + col + 1) * 32 + row] = lv;
            split_bf16(v2, hv, lv);
            yHb[(long)(l0 + col) * 32 + row + 8] = hv;   yLb[(long)(l0 + col) * 32 + row + 8] = lv;
            split_bf16(v3, hv, lv);
            yHb[(long)(l0 + col + 1) * 32 + row + 8] = hv; yLb[(long)(l0 + col + 1) * 32 + row + 8] = lv;
        }
    }
}

// ------------------------------------------------------------------
// compress conv (192 -> 64) + avgpool(2) + nearest-upsample(2), mma.
// ------------------------------------------------------------------
#define CTILE 64
__global__ void __launch_bounds__(512, 2)
comp_mma_kernel(const __nv_bfloat16* __restrict__ catH, const __nv_bfloat16* __restrict__ catL,
                const float* __restrict__ cb,
                __nv_bfloat16* __restrict__ uH, __nv_bfloat16* __restrict__ uL)
{
    constexpr int SA = 200;

    extern __shared__ __nv_bfloat16 smb[];
    __nv_bfloat16* xtH = smb;                  // [64 l][200]
    __nv_bfloat16* xtL = xtH + 64 * SA;
    __nv_bfloat16* waH = xtL + 64 * SA;        // [64 co][200]
    __nv_bfloat16* waL = waH + 64 * SA;
    float* cbs = (float*)(waL + 64 * SA);

    const int b    = blockIdx.y;
    const int l0   = blockIdx.x * CTILE;
    const int tid  = threadIdx.x;
    const int warp = tid >> 5;
    const int ln   = tid & 31;
    const int lq   = ln & 3;
    const int lg   = ln >> 2;
    const int lr   = ln & 7;
    const int lt   = ln >> 3;
    const int wm   = warp & 3;
    const int wn   = warp >> 2;

    const char* cbH = (const char*)(catH + (long)b * SS32);
    const char* cbL = (const char*)(catL + (long)b * SS32);
    for (int i = tid; i < 64 * 24 * 2; i += 512) {
        int pl = i / (64 * 24);
        int q  = i - pl * (64 * 24);
        int r  = q / 24, ck = q - r * 24;
        int plane = ck / 4, wi = ck - plane * 4;
        long srcoff = ((long)plane * (PLN / 2) + (long)(l0 + r) * 16 + wi * 4) * 4;
        unsigned dst = su32((pl ? xtL : xtH) + r * SA) + (plane * 16 + wi * 4) * 4;
        cpa16(dst, (pl ? cbL : cbH) + srcoff);
    }
    {
        const char* sH = (const char*)(g_w2H + 73728);
        const char* sL = (const char*)(g_w2L + 73728);
        for (int i = tid; i < 64 * 24 * 2; i += 512) {
            int pl = i / (64 * 24);
            int q  = i - pl * (64 * 24);
            int co = q / 24, ck = q - co * 24;
            unsigned dst = su32((pl ? waL : waH) + co * SA) + ck * 16;
            cpa16(dst, (pl ? sL : sH) + (co * 96 + ck * 4) * 4);
        }
    }
    if (tid < 64) cbs[tid] = cb[tid];
    CP_COMMIT(); CP_WAIT0();
    __syncthreads();

    float acc[2][4];
    #pragma unroll
    for (int nt = 0; nt < 2; nt++)
        #pragma unroll
        for (int q = 0; q < 4; q++) acc[nt][q] = 0.f;

    #pragma unroll
    for (int kc = 0; kc < 12; kc++) {
        unsigned ah[4], al[4];
        {
            int arow = wm * 16 + lr + (lt & 1) * 8;
            int acol = kc * 16 + (lt >> 1) * 8;
            ldsm4(ah, su32(waH + arow * SA + acol));
            ldsm4(al, su32(waL + arow * SA + acol));
        }
        unsigned bh[4], bl[4];
        {
            int brow = wn * 16 + lr + (lt & 1) * 8;
            int bcol = kc * 16 + (lt >> 1) * 8;
            ldsm4(bh, su32(xtH + brow * SA + bcol));
            ldsm4(bl, su32(xtL + brow * SA + bcol));
        }
        #pragma unroll
        for (int nt = 0; nt < 2; nt++) {
            mma_bf16(acc[nt], ah, bh[nt], bh[nt + 2]);
            mma_bf16(acc[nt], ah, bl[nt], bl[nt + 2]);
            mma_bf16(acc[nt], al, bh[nt], bh[nt + 2]);
        }
    }

    __nv_bfloat16* uHb = uH + (long)b * SSU;
    __nv_bfloat16* uLb = uL + (long)b * SSU;
    {
        int m = wm * 16 + lg;
        float bb0 = cbs[m], bb1 = cbs[m + 8];
        #pragma unroll
        for (int nt = 0; nt < 2; nt++) {
            int n = wn * 16 + nt * 8 + 2 * lq;
            float* a = acc[nt];
            float p0 = 0.5f * ((a[0] + bb0) + (a[1] + bb0));
            float p1 = 0.5f * ((a[2] + bb1) + (a[3] + bb1));
            __nv_bfloat16 hv, lv;
            split_bf16(p0, hv, lv);
            uHb[(long)(l0 + n) * 64 + m] = hv;      uHb[(long)(l0 + n + 1) * 64 + m] = hv;
            uLb[(long)(l0 + n) * 64 + m] = lv;      uLb[(long)(l0 + n + 1) * 64 + m] = lv;
            split_bf16(p1, hv, lv);
            uHb[(long)(l0 + n) * 64 + m + 8] = hv;  uHb[(long)(l0 + n + 1) * 64 + m + 8] = hv;
            uLb[(long)(l0 + n) * 64 + m + 8] = lv;  uLb[(long)(l0 + n + 1) * 64 + m + 8] = lv;
        }
    }
}

// ------------------------------------------------------------------
// final per-sample 1x1 conv: 192 -> 1, from dec planes. Grid (4, NB).
// ------------------------------------------------------------------
__global__ void __launch_bounds__(256, 1)
final_kernel(const __nv_bfloat16* __restrict__ decH, const __nv_bfloat16* __restrict__ decL,
             const float* __restrict__ cw, const float* __restrict__ cbv,
             float* __restrict__ out)
{
    __shared__ float ws[192];
    const int b   = blockIdx.y;
    const int tid = threadIdx.x;
    const int l   = blockIdx.x * 256 + tid;
    const int c   = g_ids[b];
    if (tid < 192) ws[tid] = cw[(long)c * 192 + tid];
    __syncthreads();
    float s = cbv[c];
    #pragma unroll
    for (int plane = 0; plane < 6; plane++) {
        const unsigned* pH = (const unsigned*)(decH + (long)b * SS32 + (long)plane * PLN + (long)l * 32);
        const unsigned* pL = (const unsigned*)(decL + (long)b * SS32 + (long)plane * PLN + (long)l * 32);
        #pragma unroll
        for (int w = 0; w < 16; w++) {
            unsigned uh = pH[w], ul = pL[w];
            float2 fh = __bfloat1622float2(*(const __nv_bfloat162*)&uh);
            float2 fl = __bfloat1622float2(*(const __nv_bfloat162*)&ul);
            s = fmaf(ws[plane * 32 + 2 * w],     fh.x + fl.x, s);
            s = fmaf(ws[plane * 32 + 2 * w + 1], fh.y + fl.y, s);
        }
    }
    out[(long)b * LLEN + l] = s;
}

// ------------------------------------------------------------------
static constexpr int smem_mma(int cin, int dil, int til) {
    bool fold = (cin == 1);
    int cinp = fold ? 16 : cin;
    int sb   = cinp + 8;
    int nbuf = (!fold && cin <= 32) ? 2 : 1;
    int xw   = fold ? til : (til + 4 * dil);
    int elems = 2 * xw * sb + 2 * nbuf * 64 * sb + 2 * 64 * (til + 8) + 2 * 32 * 136;
    return elems * 2 + 160 * 4;
}
static constexpr int SMEM_C = (4 * 64 * 200) * 2 + 256;

template<int CIN, int DIL, int TIL>
static void launch_block(const void* xH, const void* xL, long xss,
                         const __nv_bfloat16* w1H, const __nv_bfloat16* w1L,
                         const __nv_bfloat16* w2H, const __nv_bfloat16* w2L,
                         const float* b1, const float* b2,
                         __nv_bfloat16* yH, __nv_bfloat16* yL, long yss,
                         const int* ids, long w1cs, long b1cs, long w2cs, long b2cs)
{
    static bool attr_done = false;
    if (!attr_done) {
        cudaFuncSetAttribute(block_mma_kernel<CIN, DIL, TIL>,
                             cudaFuncAttributeMaxDynamicSharedMemorySize,
                             smem_mma(CIN, DIL, TIL));
        attr_done = true;
    }
    dim3 grid(LLEN / TIL, NB);
    block_mma_kernel<CIN, DIL, TIL><<<grid, 512, smem_mma(CIN, DIL, TIL)>>>(
        xH, xL, xss, w1H, w1L, w2H, w2L, b1, b2, yH, yL, yss,
        ids, w1cs, b1cs, w2cs, b2cs);
}

extern "C" void kernel_launch(void* const* d_in, const int* in_sizes, int n_in,
                              void* d_out, int out_size)
{
    const float* x        = (const float*)d_in[0];
    const float* enc0_b1  = (const float*)d_in[2];
    const float* enc0_b2  = (const float*)d_in[4];
    const float* enc_b1   = (const float*)d_in[6];
    const float* enc_b2   = (const float*)d_in[8];
    const float* comp_b   = (const float*)d_in[10];
    const float* decf0_b1 = (const float*)d_in[12];
    const float* decf0_b2 = (const float*)d_in[14];
    const float* decf_b1  = (const float*)d_in[16];
    const float* decf_b2  = (const float*)d_in[18];
    const float* decv_b1  = (const float*)d_in[20];
    const float* decv_b2  = (const float*)d_in[22];
    const float* decv_cw  = (const float*)d_in[23];
    const float* decv_cb  = (const float*)d_in[24];
    float* out = (float*)d_out;

    __nv_bfloat16 *catH, *catL, *decH, *decL, *uH, *uL, *w1H, *w1L, *w2H, *w2L;
    int* idsp;
    cudaGetSymbolAddress((void**)&catH, g_catH);
    cudaGetSymbolAddress((void**)&catL, g_catL);
    cudaGetSymbolAddress((void**)&decH, g_decH);
    cudaGetSymbolAddress((void**)&decL, g_decL);
    cudaGetSymbolAddress((void**)&uH,   g_encUH);
    cudaGetSymbolAddress((void**)&uL,   g_encUL);
    cudaGetSymbolAddress((void**)&w1H,  g_w1H);
    cudaGetSymbolAddress((void**)&w1L,  g_w1L);
    cudaGetSymbolAddress((void**)&w2H,  g_w2H);
    cudaGetSymbolAddress((void**)&w2L,  g_w2L);
    cudaGetSymbolAddress((void**)&idsp, g_ids);

    static bool comp_attr = false;
    if (!comp_attr) {
        cudaFuncSetAttribute(comp_mma_kernel,
                             cudaFuncAttributeMaxDynamicSharedMemorySize, SMEM_C);
        comp_attr = true;
    }

    ids_kernel<<<1, 64>>>(x);
    {
        dim3 g1(160, 18);
        prep_w1<<<g1, 256>>>((const float*)d_in[1], (const float*)d_in[5],
                             (const float*)d_in[11], (const float*)d_in[15],
                             (const float*)d_in[19]);
        dim3 g2(48, 19);
        prep_w2<<<g2, 256>>>((const float*)d_in[3], (const float*)d_in[7],
                             (const float*)d_in[13], (const float*)d_in[17],
                             (const float*)d_in[21], (const float*)d_in[9]);
    }

    static const int OFF1[18] = {
        0, 10240, 30720, 51200, 71680, 92160, 112640,
        153600, 174080, 194560,
        215040, 235520, 256000, 276480, 296960, 317440, 337920, 358400};

    // ---- encoder ----
    launch_block<1, 1, 128>(x, nullptr, (long)(LLEN + 1),
                            w1H + OFF1[0], w1L + OFF1[0], w2H + 0, w2L + 0,
                            enc0_b1, enc0_b2,
                            catH, catL, SS32, nullptr, 0, 0, 0, 0);
    launch_block<32, 2, 128>(catH + 0 * PLN, catL + 0 * PLN, SS32,
                             w1H + OFF1[1], w1L + OFF1[1], w2H + 1 * 4096, w2L + 1 * 4096,
                             enc_b1 + 0 * 128, enc_b2 + 0 * 32,
                             catH + 1 * PLN, catL + 1 * PLN, SS32, nullptr, 0, 0, 0, 0);
    launch_block<32, 4, 128>(catH + 1 * PLN, catL + 1 * PLN, SS32,
                             w1H + OFF1[2], w1L + OFF1[2], w2H + 2 * 4096, w2L + 2 * 4096,
                             enc_b1 + 1 * 128, enc_b2 + 1 * 32,
                             catH + 2 * PLN, catL + 2 * PLN, SS32, nullptr, 0, 0, 0, 0);
    launch_block<32, 8, 128>(catH + 2 * PLN, catL + 2 * PLN, SS32,
                             w1H + OFF1[3], w1L + OFF1[3], w2H + 3 * 4096, w2L + 3 * 4096,
                             enc_b1 + 2 * 128, enc_b2 + 2 * 32,
                             catH + 3 * PLN, catL + 3 * PLN, SS32, nullptr, 0, 0, 0, 0);
    launch_block<32, 16, 128>(catH + 3 * PLN, catL + 3 * PLN, SS32,
                              w1H + OFF1[4], w1L + OFF1[4], w2H + 4 * 4096, w2L + 4 * 4096,
                              enc_b1 + 3 * 128, enc_b2 + 3 * 32,
                              catH + 4 * PLN, catL + 4 * PLN, SS32, nullptr, 0, 0, 0, 0);
    launch_block<32, 32, 64>(catH + 4 * PLN, catL + 4 * PLN, SS32,
                             w1H + OFF1[5], w1L + OFF1[5], w2H + 5 * 4096, w2L + 5 * 4096,
                             enc_b1 + 4 * 128, enc_b2 + 4 * 32,
                             catH + 5 * PLN, catL + 5 * PLN, SS32, nullptr, 0, 0, 0, 0);

    // ---- compress + pool + upsample ----
    {
        dim3 grid(LLEN / CTILE, NB);
        comp_mma_kernel<<<grid, 512, SMEM_C>>>(catH, catL, comp_b, uH, uL);
    }

    // ---- fixed decoder ----
    launch_block<64, 32, 64>(uH, uL, (long)SSU,
                             w1H + OFF1[6], w1L + OFF1[6], w2H + 6 * 4096, w2L + 6 * 4096,
                             decf0_b1, decf0_b2,
                             decH, decL, SS32, nullptr, 0, 0, 0, 0);
    launch_block<32, 16, 128>(decH + 0 * PLN, decL + 0 * PLN, SS32,
                              w1H + OFF1[7], w1L + OFF1[7], w2H + 7 * 4096, w2L + 7 * 4096,
                              decf_b1 + 0 * 128, decf_b2 + 0 * 32,
                              decH + 1 * PLN, decL + 1 * PLN, SS32, nullptr, 0, 0, 0, 0);
    launch_block<32, 8, 128>(decH + 1 * PLN, decL + 1 * PLN, SS32,
                             w1H + OFF1[8], w1L + OFF1[8], w2H + 8 * 4096, w2L + 8 * 4096,
                             decf_b1 + 1 * 128, decf_b2 + 1 * 32,
                             decH + 2 * PLN, decL + 2 * PLN, SS32, nullptr, 0, 0, 0, 0);
    launch_block<32, 4, 128>(decH + 2 * PLN, decL + 2 * PLN, SS32,
                             w1H + OFF1[9], w1L + OFF1[9], w2H + 9 * 4096, w2L + 9 * 4096,
                             decf_b1 + 2 * 128, decf_b2 + 2 * 32,
                             decH + 3 * PLN, decL + 3 * PLN, SS32, nullptr, 0, 0, 0, 0);

    // ---- variable decoder: per-sample selected combination ----
    launch_block<32, 2, 128>(decH + 3 * PLN, decL + 3 * PLN, SS32,
                             w1H + OFF1[10], w1L + OFF1[10],
                             w2H + 10 * 4096, w2L + 10 * 4096,
                             decv_b1 + 0 * 128, decv_b2 + 0 * 32,
                             decH + 4 * PLN, decL + 4 * PLN, SS32,
                             idsp, 40960, 256, 8192, 64);
    launch_block<32, 1, 128>(decH + 4 * PLN, decL + 4 * PLN, SS32,
                             w1H + OFF1[10] + 20480, w1L + OFF1[10] + 20480,
                             w2H + 11 * 4096, w2L + 11 * 4096,
                             decv_b1 + 1 * 128, decv_b2 + 1 * 32,
                             decH + 5 * PLN, decL + 5 * PLN, SS32,
                             idsp, 40960, 256, 8192, 64);

    // ---- final 1x1 conv (per-sample weights) ----
    {
        dim3 grid(4, NB);
        final_kernel<<<grid, 256>>>(decH, decL, decv_cw, decv_cb, out);
    }
}

// round 14
// speedup vs baseline: 1.5573x; 1.0118x over previous
#include <cuda_runtime.h>
#include <cuda_bf16.h>

#define LLEN 1024
#define NB   64
#define PLN  (LLEN * 32)          // one 32-ch plane, elems
#define SS32 (6 * PLN)            // cat/dec sample stride (elems)
#define SSU  (LLEN * 64)          // encU sample stride

// ---- device scratch (no allocations allowed) ----
__device__ __nv_bfloat16 g_catH[NB * SS32], g_catL[NB * SS32];
__device__ __nv_bfloat16 g_decH[NB * SS32], g_decL[NB * SS32];
__device__ __nv_bfloat16 g_encUH[NB * SSU], g_encUL[NB * SSU];
__device__ __nv_bfloat16 g_w1H[378880], g_w1L[378880];
__device__ __nv_bfloat16 g_w2H[86016],  g_w2L[86016];
__device__ int g_ids[NB];

__constant__ int c_OFF1[18] = {
    0, 10240, 30720, 51200, 71680, 92160, 112640,
    153600, 174080, 194560,
    215040, 235520, 256000, 276480, 296960, 317440, 337920, 358400};

__device__ __forceinline__ void mma_bf16(float* c, const unsigned* a,
                                         unsigned b0, unsigned b1) {
    asm volatile(
        "mma.sync.aligned.m16n8k16.row.col.f32.bf16.bf16.f32 "
        "{%0,%1,%2,%3}, {%4,%5,%6,%7}, {%8,%9}, {%0,%1,%2,%3};\n"
        : "+f"(c[0]), "+f"(c[1]), "+f"(c[2]), "+f"(c[3])
        : "r"(a[0]), "r"(a[1]), "r"(a[2]), "r"(a[3]), "r"(b0), "r"(b1));
}
__device__ __forceinline__ void ldsm4(unsigned* r, unsigned addr) {
    asm volatile("ldmatrix.sync.aligned.m8n8.x4.shared.b16 {%0,%1,%2,%3}, [%4];\n"
                 : "=r"(r[0]), "=r"(r[1]), "=r"(r[2]), "=r"(r[3]) : "r"(addr));
}
__device__ __forceinline__ void ldsm2(unsigned* r, unsigned addr) {
    asm volatile("ldmatrix.sync.aligned.m8n8.x2.shared.b16 {%0,%1}, [%2];\n"
                 : "=r"(r[0]), "=r"(r[1]) : "r"(addr));
}
__device__ __forceinline__ void ldsm4t(unsigned* r, unsigned addr) {
    asm volatile("ldmatrix.sync.aligned.m8n8.x4.trans.shared.b16 {%0,%1,%2,%3}, [%4];\n"
                 : "=r"(r[0]), "=r"(r[1]), "=r"(r[2]), "=r"(r[3]) : "r"(addr));
}
__device__ __forceinline__ void ldsm2t(unsigned* r, unsigned addr) {
    asm volatile("ldmatrix.sync.aligned.m8n8.x2.trans.shared.b16 {%0,%1}, [%2];\n"
                 : "=r"(r[0]), "=r"(r[1]) : "r"(addr));
}
__device__ __forceinline__ unsigned su32(const void* p) {
    return (unsigned)__cvta_generic_to_shared(p);
}
__device__ __forceinline__ void cpa16(unsigned dst, const void* src) {
    asm volatile("cp.async.ca.shared.global [%0], [%1], 16;\n"
                 :: "r"(dst), "l"(src));
}
__device__ __forceinline__ void cpa16z(unsigned dst, const void* src, int sz) {
    asm volatile("cp.async.ca.shared.global [%0], [%1], 16, %2;\n"
                 :: "r"(dst), "l"(src), "r"(sz));
}
#define CP_COMMIT() asm volatile("cp.async.commit_group;\n" ::: "memory")
#define CP_WAIT0()  asm volatile("cp.async.wait_group 0;\n"  ::: "memory")

__device__ __forceinline__ void split_bf16(float v, __nv_bfloat16& hi, __nv_bfloat16& lo) {
    hi = __float2bfloat16(v);
    lo = __float2bfloat16(v - __bfloat162float(hi));
}

// ------------------------------------------------------------------
// prep kernels: split weights into bf16 hi/lo planes, staging layout
// ------------------------------------------------------------------
__global__ void prep_w1(const float* __restrict__ enc0, const float* __restrict__ enc,
                        const float* __restrict__ decf0, const float* __restrict__ decf,
                        const float* __restrict__ decv)
{
    int L = blockIdx.y;
    int e = blockIdx.x * 256 + threadIdx.x;
    if (L == 0) {
        if (e >= 2048) return;
        int k = e & 15, tmp = e >> 4;
        int co = tmp & 63, half = tmp >> 6;
        float v = (k < 5) ? enc0[(long)(half * 64 + co) * 5 + k] : 0.f;
        __nv_bfloat16 h, l; split_bf16(v, h, l);
        g_w1H[e] = h;  g_w1L[e] = l;
        return;
    }
    int cinv = (L == 6) ? 64 : 32;
    int cinp = cinv;
    int total = 640 * cinp;
    if (e >= total) return;
    int ci  = e % cinp;
    int tmp = e / cinp;
    int co  = tmp & 63;  tmp >>= 6;
    int t   = tmp % 5, half = tmp / 5;
    const float* src;
    if (L <= 5) src = enc + (L - 1) * 20480;
    else if (L == 6) src = decf0;
    else if (L <= 9) src = decf + (L - 7) * 20480;
    else src = decv + (L - 10) * 20480;
    float v = src[(long)(half * 64 + co) * (cinv * 5) + ci * 5 + t];
    __nv_bfloat16 h, l; split_bf16(v, h, l);
    g_w1H[c_OFF1[L] + e] = h;
    g_w1L[c_OFF1[L] + e] = l;
}

// L==19 row additionally extracts the per-sample combination ids.
__global__ void prep_w2(const float* __restrict__ enc0, const float* __restrict__ enc,
                        const float* __restrict__ decf0, const float* __restrict__ decf,
                        const float* __restrict__ decv, const float* __restrict__ comp,
                        const float* __restrict__ x)
{
    int L = blockIdx.y;
    int e = blockIdx.x * 256 + threadIdx.x;
    if (L == 19) {
        if (blockIdx.x == 0 && e < NB)
            g_ids[e] = (int)x[(long)e * (LLEN + 1) + LLEN];
        return;
    }
    int sz = (L == 18) ? 12288 : 4096;
    if (e >= sz) return;
    const float* src;
    if (L == 0) src = enc0;
    else if (L <= 5) src = enc + (L - 1) * 4096;
    else if (L == 6) src = decf0;
    else if (L <= 9) src = decf + (L - 7) * 4096;
    else if (L <= 17) src = decv + (L - 10) * 4096;
    else src = comp;
    long off = (L == 18) ? 73728 : (long)L * 4096;
    __nv_bfloat16 h, l; split_bf16(src[e], h, l);
    g_w2H[off + e] = h;
    g_w2L[off + e] = l;
}

// ------------------------------------------------------------------
// Fused TCN block (bf16 hi/lo planes end-to-end, LDSM, cp.async staging):
//   conv1: CIN -> 128 (k=5, dil DIL) + bias + relu, two co-halves of 64
//   conv2: 128 -> 32 (1x1) + bias + relu
// hs kept in natural [co][l] orientation; conv2 B via ldmatrix.trans.
// CIN==1 (FOLD): taps folded into K=16.
// FINAL: this is the last decv layer; keep conv2 output (plane 5) in smem
//   and finish with the 192->1 per-sample output conv (planes 0-4 global).
// 512 thr = 16 warps, 2 CTAs/SM.
// ------------------------------------------------------------------
template<int CIN, int DIL, int TIL, bool FINAL = false>
__global__ void __launch_bounds__(512, 2)
block_mma_kernel(const void* __restrict__ xHv, const void* __restrict__ xLv, long xss,
                 const __nv_bfloat16* __restrict__ w1Hg, const __nv_bfloat16* __restrict__ w1Lg,
                 const __nv_bfloat16* __restrict__ w2Hg, const __nv_bfloat16* __restrict__ w2Lg,
                 const float* __restrict__ b1, const float* __restrict__ b2,
                 __nv_bfloat16* __restrict__ yH, __nv_bfloat16* __restrict__ yL, long yss,
                 const int* __restrict__ ids,
                 long w1_cs, long b1_cs, long w2_cs, long b2_cs,
                 const float* __restrict__ fcw, const float* __restrict__ fcb,
                 float* __restrict__ fout)
{
    constexpr bool FOLD = (CIN == 1);
    constexpr int CINP = FOLD ? 16 : CIN;
    constexpr int XW   = FOLD ? TIL : (TIL + 4 * DIL);
    constexpr int NK   = CINP / 16;
    constexpr int SB   = CINP + 8;       // xt / wa row stride (bf16)
    constexpr int SHS  = TIL + 8;        // hs row stride (co-major)
    constexpr int S2   = 136;            // w2 row stride
    constexpr int NT   = TIL / 64;
    constexpr bool DBUF = (!FOLD && CIN <= 32);
    constexpr int NBUF = DBUF ? 2 : 1;
    constexpr int WBUF = 64 * SB;
    constexpr int WW   = 64 * CINP / 2;      // words per tap per half per plane
    constexpr int WRW  = CINP / 2;           // words per co row
    constexpr int CHK  = WRW / 4;            // 16B chunks per co row
    constexpr int NCP  = 64 * CHK;           // chunks per plane per tap
    constexpr int SF   = TIL + 4;            // final fp32 plane5 row stride

    extern __shared__ __nv_bfloat16 smb[];
    __nv_bfloat16* xtH = smb;
    __nv_bfloat16* xtL = xtH + XW * SB;
    __nv_bfloat16* waB = xtL + XW * SB;      // H bufs then L bufs
    __nv_bfloat16* hH  = waB + 2 * NBUF * WBUF;    // [64 co][SHS]
    __nv_bfloat16* hL  = hH  + 64 * SHS;
    __nv_bfloat16* w2H = hL  + 64 * SHS;
    __nv_bfloat16* w2L = w2H + 32 * S2;
    float* b1s = (float*)(w2L + 32 * S2);
    float* b2s = b1s + 128;

    const int b    = blockIdx.y;
    const int l0   = blockIdx.x * TIL;
    const int tid  = threadIdx.x;
    const int warp = tid >> 5;
    const int ln   = tid & 31;
    const int lq   = ln & 3;
    const int lg   = ln >> 2;
    const int lr   = ln & 7;
    const int lt   = ln >> 3;

    const __nv_bfloat16* w1Hp = w1Hg;
    const __nv_bfloat16* w1Lp = w1Lg;
    const __nv_bfloat16* w2Hp = w2Hg;
    const __nv_bfloat16* w2Lp = w2Lg;
    const float* b1p = b1;
    const float* b2p = b2;
    int cid = 0;
    if (ids) {
        cid = ids[b];
        w1Hp += (long)cid * w1_cs;  w1Lp += (long)cid * w1_cs;
        w2Hp += (long)cid * w2_cs;  w2Lp += (long)cid * w2_cs;
        b1p  += (long)cid * b1_cs;  b2p  += (long)cid * b2_cs;
    }

    // ---- stage x (async; zero-fill halo) ----
    if constexpr (FOLD) {
        const float* xf = (const float*)xHv + (long)b * xss;
        for (int i = tid; i < TIL * 16; i += 512) {
            int r = i >> 4, k = i & 15;
            int pos = l0 - 2 * DIL + r + k * DIL;
            float v = (k < 5 && pos >= 0 && pos < LLEN) ? xf[pos] : 0.f;
            __nv_bfloat16 hv, lv; split_bf16(v, hv, lv);
            xtH[r * SB + k] = hv;
            xtL[r * SB + k] = lv;
        }
    } else {
        constexpr int WR  = CIN / 2;       // words per row
        constexpr int RCH = WR / 4;        // 16B chunks per row
        const char* xbH = (const char*)((const __nv_bfloat16*)xHv + (long)b * xss);
        const char* xbL = (const char*)((const __nv_bfloat16*)xLv + (long)b * xss);
        for (int i = tid; i < XW * RCH * 2; i += 512) {
            int pl = i / (XW * RCH);
            int q  = i - pl * (XW * RCH);
            int r  = q / RCH, ck = q - r * RCH;
            int pos = l0 - 2 * DIL + r;
            bool ok = (pos >= 0 && pos < LLEN);
            const char* src = (pl ? xbL : xbH) + ((long)(ok ? pos : 0) * WR + ck * 4) * 4;
            unsigned dst = su32((pl ? xtL : xtH) + r * SB) + ck * 16;
            cpa16z(dst, src, ok ? 16 : 0);
        }
    }
    // ---- stage W2 (async) + biases ----
    for (int i = tid; i < 1024; i += 512) {
        int pl = i >> 9, q = i & 511;
        int co = q >> 4, ck = q & 15;
        const char* src = (const char*)(pl ? w2Lp : w2Hp) + (co * 64 + ck * 4) * 4;
        unsigned dst = su32((pl ? w2L : w2H) + co * S2) + ck * 16;
        cpa16(dst, src);
    }
    if (tid < 128) b1s[tid] = b1p[tid];
    if (tid < 32)  b2s[tid] = b2p[tid];

    const int wm  = warp >> 3;
    const int wn  = warp & 7;
    const int wm2 = warp & 1;
    const int wn2 = warp >> 1;

    float a2[NT][4];
    #pragma unroll
    for (int nt = 0; nt < NT; nt++)
        #pragma unroll
        for (int q = 0; q < 4; q++) a2[nt][q] = 0.f;

    #pragma unroll
    for (int half = 0; half < 2; half++) {
        const int coB = half * 64;

        float acc[2][NT][4];
        #pragma unroll
        for (int mt = 0; mt < 2; mt++)
            #pragma unroll
            for (int nt = 0; nt < NT; nt++)
                #pragma unroll
                for (int q = 0; q < 4; q++) acc[mt][nt][q] = 0.f;

        if constexpr (FOLD) {
            if (tid < 256) {
                int pl = tid >> 7, q = tid & 127;
                int co = q >> 1, ck = q & 1;
                const __nv_bfloat16* srcp = pl ? w1Lp : w1Hp;
                __nv_bfloat16* dstp = pl ? (waB + WBUF) : waB;
                cpa16(su32(dstp + co * SB) + ck * 16,
                      (const char*)srcp + half * 2048 + co * 32 + ck * 16);
            }
            CP_COMMIT(); CP_WAIT0();
            __syncthreads();

            unsigned ah[2][4], al[2][4];
            #pragma unroll
            for (int mt = 0; mt < 2; mt++) {
                int arow = wm * 32 + mt * 16 + lr + (lt & 1) * 8;
                int acol = (lt >> 1) * 8;
                ldsm4(ah[mt], su32(waB + arow * SB + acol));
                ldsm4(al[mt], su32(waB + WBUF + arow * SB + acol));
            }
            unsigned bh[4], bl[4];
            if (NT == 2) {
                int brow = wn * 16 + lr + (lt & 1) * 8;
                int bcol = (lt >> 1) * 8;
                ldsm4(bh, su32(xtH + brow * SB + bcol));
                ldsm4(bl, su32(xtL + brow * SB + bcol));
            } else {
                int brow = wn * 8 + lr;
                int bcol = ((ln >> 3) & 1) * 8;
                ldsm2(bh, su32(xtH + brow * SB + bcol));
                ldsm2(bl, su32(xtL + brow * SB + bcol));
            }
            #pragma unroll
            for (int nt = 0; nt < NT; nt++) {
                unsigned bh0 = (NT == 2) ? bh[nt] : bh[0];
                unsigned bh1 = (NT == 2) ? bh[nt + 2] : bh[1];
                unsigned bl0 = (NT == 2) ? bl[nt] : bl[0];
                unsigned bl1 = (NT == 2) ? bl[nt + 2] : bl[1];
                #pragma unroll
                for (int mt = 0; mt < 2; mt++) {
                    mma_bf16(acc[mt][nt], ah[mt], bh0, bh1);
                    mma_bf16(acc[mt][nt], ah[mt], bl0, bl1);
                    mma_bf16(acc[mt][nt], al[mt], bh0, bh1);
                }
            }
        } else {
            const char* w1Hh = (const char*)w1Hp + (size_t)half * 5 * WW * 4;
            const char* w1Lh = (const char*)w1Lp + (size_t)half * 5 * WW * 4;

            auto stage_w = [&](int tt, int bufsel) {
                __nv_bfloat16* dH = waB + bufsel * WBUF;
                __nv_bfloat16* dL = dH + NBUF * WBUF;
                const char* sH = w1Hh + (size_t)tt * WW * 4;
                const char* sL = w1Lh + (size_t)tt * WW * 4;
                #pragma unroll
                for (int j = 0; j < (2 * NCP) / 512; j++) {
                    int i = tid + j * 512;
                    int pl = i / NCP, q = i - pl * NCP;
                    int co = q / CHK, ck = q - co * CHK;
                    const char* s = (pl ? sL : sH) + co * (WRW * 4) + ck * 16;
                    unsigned d = su32((pl ? dL : dH) + co * SB) + ck * 16;
                    cpa16(d, s);
                }
            };

            stage_w(0, 0);
            CP_COMMIT(); CP_WAIT0();
            __syncthreads();

            #pragma unroll
            for (int t = 0; t < 5; t++) {
                if (DBUF && t < 4) {
                    stage_w(t + 1, (t + 1) & 1);
                    CP_COMMIT();
                }

                const __nv_bfloat16* wH = waB + (DBUF ? (t & 1) * WBUF : 0);
                const __nv_bfloat16* wL = wH + NBUF * WBUF;

                #pragma unroll
                for (int kc = 0; kc < NK; kc++) {
                    unsigned ah[2][4], al[2][4];
                    #pragma unroll
                    for (int mt = 0; mt < 2; mt++) {
                        int arow = wm * 32 + mt * 16 + lr + (lt & 1) * 8;
                        int acol = kc * 16 + (lt >> 1) * 8;
                        ldsm4(ah[mt], su32(wH + arow * SB + acol));
                        ldsm4(al[mt], su32(wL + arow * SB + acol));
                    }
                    unsigned bh[4], bl[4];
                    if (NT == 2) {
                        int brow = wn * 16 + lr + (lt & 1) * 8 + t * DIL;
                        int bcol = kc * 16 + (lt >> 1) * 8;
                        ldsm4(bh, su32(xtH + brow * SB + bcol));
                        ldsm4(bl, su32(xtL + brow * SB + bcol));
                    } else {
                        int brow = wn * 8 + lr + t * DIL;
                        int bcol = kc * 16 + ((ln >> 3) & 1) * 8;
                        ldsm2(bh, su32(xtH + brow * SB + bcol));
                        ldsm2(bl, su32(xtL + brow * SB + bcol));
                    }
                    #pragma unroll
                    for (int nt = 0; nt < NT; nt++) {
                        unsigned bh0 = (NT == 2) ? bh[nt] : bh[0];
                        unsigned bh1 = (NT == 2) ? bh[nt + 2] : bh[1];
                        unsigned bl0 = (NT == 2) ? bl[nt] : bl[0];
                        unsigned bl1 = (NT == 2) ? bl[nt + 2] : bl[1];
                        #pragma unroll
                        for (int mt = 0; mt < 2; mt++) {
                            mma_bf16(acc[mt][nt], ah[mt], bh0, bh1);
                            mma_bf16(acc[mt][nt], ah[mt], bl0, bl1);
                            mma_bf16(acc[mt][nt], al[mt], bh0, bh1);
                        }
                    }
                }

                if (t < 4) {
                    if (!DBUF) {
                        __syncthreads();
                        stage_w(t + 1, 0);
                        CP_COMMIT();
                    }
                    CP_WAIT0();
                    __syncthreads();
                }
            }
        }

        // ---- conv1 epilogue: bias + relu + split -> hs [co][l], packed ----
        #pragma unroll
        for (int mt = 0; mt < 2; mt++) {
            int m = wm * 32 + mt * 16 + lg;      // local co (0..63)
            float bb0 = b1s[coB + m], bb1 = b1s[coB + m + 8];
            #pragma unroll
            for (int nt = 0; nt < NT; nt++) {
                int n = ((NT == 2) ? wn * 16 + nt * 8 : wn * 8) + 2 * lq;
                float* a = acc[mt][nt];
                float v00 = a[0] + bb0, v01 = a[1] + bb0;
                float v10 = a[2] + bb1, v11 = a[3] + bb1;
                v00 = v00 > 0.f ? v00 : 0.f;  v01 = v01 > 0.f ? v01 : 0.f;
                v10 = v10 > 0.f ? v10 : 0.f;  v11 = v11 > 0.f ? v11 : 0.f;
                __nv_bfloat16 h0, l0h, h1, l1h;
                split_bf16(v00, h0, l0h); split_bf16(v01, h1, l1h);
                *(__nv_bfloat162*)(hH + m * SHS + n) = __halves2bfloat162(h0, h1);
                *(__nv_bfloat162*)(hL + m * SHS + n) = __halves2bfloat162(l0h, l1h);
                split_bf16(v10, h0, l0h); split_bf16(v11, h1, l1h);
                *(__nv_bfloat162*)(hH + (m + 8) * SHS + n) = __halves2bfloat162(h0, h1);
                *(__nv_bfloat162*)(hL + (m + 8) * SHS + n) = __halves2bfloat162(l0h, l1h);
            }
        }
        __syncthreads();

        // ---- conv2 partial: B via ldmatrix.trans from [co][l] hs ----
        #pragma unroll
        for (int kc = 0; kc < 4; kc++) {
            unsigned ah[4], al[4];
            {
                int arow = wm2 * 16 + lr + (lt & 1) * 8;
                int acol = coB + kc * 16 + (lt >> 1) * 8;
                ldsm4(ah, su32(w2H + arow * S2 + acol));
                ldsm4(al, su32(w2L + arow * S2 + acol));
            }
            unsigned bh[4], bl[4];
            if (NT == 2) {
                int brow = kc * 16 + (lt & 1) * 8 + lr;     // k (local co)
                int bcol = wn2 * 16 + (lt >> 1) * 8;        // n (l)
                ldsm4t(bh, su32(hH + brow * SHS + bcol));
                ldsm4t(bl, su32(hL + brow * SHS + bcol));
            } else {
                int brow = kc * 16 + ((ln >> 3) & 1) * 8 + lr;
                int bcol = wn2 * 8;
                ldsm2t(bh, su32(hH + brow * SHS + bcol));
                ldsm2t(bl, su32(hL + brow * SHS + bcol));
            }
            #pragma unroll
            for (int nt = 0; nt < NT; nt++) {
                unsigned bh0 = (NT == 2) ? bh[2 * nt]     : bh[0];
                unsigned bh1 = (NT == 2) ? bh[2 * nt + 1] : bh[1];
                unsigned bl0 = (NT == 2) ? bl[2 * nt]     : bl[0];
                unsigned bl1 = (NT == 2) ? bl[2 * nt + 1] : bl[1];
                mma_bf16(a2[nt], ah, bh0, bh1);
                mma_bf16(a2[nt], ah, bl0, bl1);
                mma_bf16(a2[nt], al, bh0, bh1);
            }
        }
    }

    if constexpr (!FINAL) {
        // ---- conv2 epilogue: bias + relu + split -> y planes [l][co] ----
        __nv_bfloat16* yHb = yH + (long)b * yss;
        __nv_bfloat16* yLb = yL + (long)b * yss;
        int row = wm2 * 16 + lg;
        float bb0 = b2s[row], bb1 = b2s[row + 8];
        #pragma unroll
        for (int nt = 0; nt < NT; nt++) {
            int col = ((NT == 2) ? wn2 * 16 + nt * 8 : wn2 * 8) + 2 * lq;
            float v0 = a2[nt][0] + bb0, v1 = a2[nt][1] + bb0;
            float v2 = a2[nt][2] + bb1, v3 = a2[nt][3] + bb1;
            v0 = v0 > 0.f ? v0 : 0.f;  v1 = v1 > 0.f ? v1 : 0.f;
            v2 = v2 > 0.f ? v2 : 0.f;  v3 = v3 > 0.f ? v3 : 0.f;
            __nv_bfloat16 hv, lv;
            split_bf16(v0, hv, lv);
            yHb[(long)(l0 + col) * 32 + row] = hv;       yLb[(long)(l0 + col) * 32 + row] = lv;
            split_bf16(v1, hv, lv);
            yHb[(long)(l0 + col + 1) * 32 + row] = hv;   yLb[(long)(l0 + col + 1) * 32 + row] = lv;
            split_bf16(v2, hv, lv);
            yHb[(long)(l0 + col) * 32 + row + 8] = hv;   yLb[(long)(l0 + col) * 32 + row + 8] = lv;
            split_bf16(v3, hv, lv);
            yHb[(long)(l0 + col + 1) * 32 + row + 8] = hv; yLb[(long)(l0 + col + 1) * 32 + row + 8] = lv;
        }
    } else {
        // ---- FINAL: plane5 -> smem fp32, then 192->1 output conv ----
        __syncthreads();                // all conv2 hs reads done before reuse
        float* ps = (float*)hH;         // [32 co][SF] fp32 plane5 tile
        float* ws = (float*)waB;        // 192 final weights
        {
            int row = wm2 * 16 + lg;
            float bb0 = b2s[row], bb1 = b2s[row + 8];
            #pragma unroll
            for (int nt = 0; nt < NT; nt++) {
                int col = ((NT == 2) ? wn2 * 16 + nt * 8 : wn2 * 8) + 2 * lq;
                float v0 = a2[nt][0] + bb0, v1 = a2[nt][1] + bb0;
                float v2 = a2[nt][2] + bb1, v3 = a2[nt][3] + bb1;
                ps[row * SF + col]           = v0 > 0.f ? v0 : 0.f;
                ps[row * SF + col + 1]       = v1 > 0.f ? v1 : 0.f;
                ps[(row + 8) * SF + col]     = v2 > 0.f ? v2 : 0.f;
                ps[(row + 8) * SF + col + 1] = v3 > 0.f ? v3 : 0.f;
            }
        }
        if (tid < 192) ws[tid] = fcw[(long)cid * 192 + tid];
        __syncthreads();

        if (tid < TIL) {
            int l = tid;
            float s = fcb[cid];
            // planes 0..4 from global (dec planes relative to this layer's x)
            const __nv_bfloat16* dH = (const __nv_bfloat16*)xHv + (long)b * xss - 4 * PLN;
            const __nv_bfloat16* dL = (const __nv_bfloat16*)xLv + (long)b * xss - 4 * PLN;
            #pragma unroll
            for (int plane = 0; plane < 5; plane++) {
                const unsigned* pH = (const unsigned*)(dH + (long)plane * PLN + (long)(l0 + l) * 32);
                const unsigned* pL = (const unsigned*)(dL + (long)plane * PLN + (long)(l0 + l) * 32);
                #pragma unroll
                for (int w = 0; w < 16; w++) {
                    unsigned uh = pH[w], ul = pL[w];
                    float2 fh = __bfloat1622float2(*(const __nv_bfloat162*)&uh);
                    float2 fl = __bfloat1622float2(*(const __nv_bfloat162*)&ul);
                    s = fmaf(ws[plane * 32 + 2 * w],     fh.x + fl.x, s);
                    s = fmaf(ws[plane * 32 + 2 * w + 1], fh.y + fl.y, s);
                }
            }
            // plane 5 from smem fp32
            #pragma unroll
            for (int ch = 0; ch < 32; ch++)
                s = fmaf(ws[160 + ch], ps[ch * SF + l], s);
            fout[(long)b * LLEN + l0 + l] = s;
        }
    }
}

// ------------------------------------------------------------------
// compress conv (192 -> 64) + avgpool(2) + nearest-upsample(2), mma.
// ------------------------------------------------------------------
#define CTILE 64
__global__ void __launch_bounds__(512, 2)
comp_mma_kernel(const __nv_bfloat16* __restrict__ catH, const __nv_bfloat16* __restrict__ catL,
                const float* __restrict__ cb,
                __nv_bfloat16* __restrict__ uH, __nv_bfloat16* __restrict__ uL)
{
    constexpr int SA = 200;

    extern __shared__ __nv_bfloat16 smb[];
    __nv_bfloat16* xtH = smb;                  // [64 l][200]
    __nv_bfloat16* xtL = xtH + 64 * SA;
    __nv_bfloat16* waH = xtL + 64 * SA;        // [64 co][200]
    __nv_bfloat16* waL = waH + 64 * SA;
    float* cbs = (float*)(waL + 64 * SA);

    const int b    = blockIdx.y;
    const int l0   = blockIdx.x * CTILE;
    const int tid  = threadIdx.x;
    const int warp = tid >> 5;
    const int ln   = tid & 31;
    const int lq   = ln & 3;
    const int lg   = ln >> 2;
    const int lr   = ln & 7;
    const int lt   = ln >> 3;
    const int wm   = warp & 3;
    const int wn   = warp >> 2;

    const char* cbH = (const char*)(catH + (long)b * SS32);
    const char* cbL = (const char*)(catL + (long)b * SS32);
    for (int i = tid; i < 64 * 24 * 2; i += 512) {
        int pl = i / (64 * 24);
        int q  = i - pl * (64 * 24);
        int r  = q / 24, ck = q - r * 24;
        int plane = ck / 4, wi = ck - plane * 4;
        long srcoff = ((long)plane * (PLN / 2) + (long)(l0 + r) * 16 + wi * 4) * 4;
        unsigned dst = su32((pl ? xtL : xtH) + r * SA) + (plane * 16 + wi * 4) * 4;
        cpa16(dst, (pl ? cbL : cbH) + srcoff);
    }
    {
        const char* sH = (const char*)(g_w2H + 73728);
        const char* sL = (const char*)(g_w2L + 73728);
        for (int i = tid; i < 64 * 24 * 2; i += 512) {
            int pl = i / (64 * 24);
            int q  = i - pl * (64 * 24);
            int co = q / 24, ck = q - co * 24;
            unsigned dst = su32((pl ? waL : waH) + co * SA) + ck * 16;
            cpa16(dst, (pl ? sL : sH) + (co * 96 + ck * 4) * 4);
        }
    }
    if (tid < 64) cbs[tid] = cb[tid];
    CP_COMMIT(); CP_WAIT0();
    __syncthreads();

    float acc[2][4];
    #pragma unroll
    for (int nt = 0; nt < 2; nt++)
        #pragma unroll
        for (int q = 0; q < 4; q++) acc[nt][q] = 0.f;

    #pragma unroll
    for (int kc = 0; kc < 12; kc++) {
        unsigned ah[4], al[4];
        {
            int arow = wm * 16 + lr + (lt & 1) * 8;
            int acol = kc * 16 + (lt >> 1) * 8;
            ldsm4(ah, su32(waH + arow * SA + acol));
            ldsm4(al, su32(waL + arow * SA + acol));
        }
        unsigned bh[4], bl[4];
        {
            int brow = wn * 16 + lr + (lt & 1) * 8;
            int bcol = kc * 16 + (lt >> 1) * 8;
            ldsm4(bh, su32(xtH + brow * SA + bcol));
            ldsm4(bl, su32(xtL + brow * SA + bcol));
        }
        #pragma unroll
        for (int nt = 0; nt < 2; nt++) {
            mma_bf16(acc[nt], ah, bh[nt], bh[nt + 2]);
            mma_bf16(acc[nt], ah, bl[nt], bl[nt + 2]);
            mma_bf16(acc[nt], al, bh[nt], bh[nt + 2]);
        }
    }

    __nv_bfloat16* uHb = uH + (long)b * SSU;
    __nv_bfloat16* uLb = uL + (long)b * SSU;
    {
        int m = wm * 16 + lg;
        float bb0 = cbs[m], bb1 = cbs[m + 8];
        #pragma unroll
        for (int nt = 0; nt < 2; nt++) {
            int n = wn * 16 + nt * 8 + 2 * lq;
            float* a = acc[nt];
            float p0 = 0.5f * ((a[0] + bb0) + (a[1] + bb0));
            float p1 = 0.5f * ((a[2] + bb1) + (a[3] + bb1));
            __nv_bfloat16 hv, lv;
            split_bf16(p0, hv, lv);
            uHb[(long)(l0 + n) * 64 + m] = hv;      uHb[(long)(l0 + n + 1) * 64 + m] = hv;
            uLb[(long)(l0 + n) * 64 + m] = lv;      uLb[(long)(l0 + n + 1) * 64 + m] = lv;
            split_bf16(p1, hv, lv);
            uHb[(long)(l0 + n) * 64 + m + 8] = hv;  uHb[(long)(l0 + n + 1) * 64 + m + 8] = hv;
            uLb[(long)(l0 + n) * 64 + m + 8] = lv;  uLb[(long)(l0 + n + 1) * 64 + m + 8] = lv;
        }
    }
}

// ------------------------------------------------------------------
static constexpr int smem_mma(int cin, int dil, int til) {
    bool fold = (cin == 1);
    int cinp = fold ? 16 : cin;
    int sb   = cinp + 8;
    int nbuf = (!fold && cin <= 32) ? 2 : 1;
    int xw   = fold ? til : (til + 4 * dil);
    int elems = 2 * xw * sb + 2 * nbuf * 64 * sb + 2 * 64 * (til + 8) + 2 * 32 * 136;
    return elems * 2 + 160 * 4;
}
static constexpr int SMEM_C = (4 * 64 * 200) * 2 + 256;

template<int CIN, int DIL, int TIL, bool FINAL = false>
static void launch_block(const void* xH, const void* xL, long xss,
                         const __nv_bfloat16* w1H, const __nv_bfloat16* w1L,
                         const __nv_bfloat16* w2H, const __nv_bfloat16* w2L,
                         const float* b1, const float* b2,
                         __nv_bfloat16* yH, __nv_bfloat16* yL, long yss,
                         const int* ids, long w1cs, long b1cs, long w2cs, long b2cs,
                         const float* fcw = nullptr, const float* fcb = nullptr,
                         float* fout = nullptr)
{
    static bool attr_done = false;
    if (!attr_done) {
        cudaFuncSetAttribute(block_mma_kernel<CIN, DIL, TIL, FINAL>,
                             cudaFuncAttributeMaxDynamicSharedMemorySize,
                             smem_mma(CIN, DIL, TIL));
        attr_done = true;
    }
    dim3 grid(LLEN / TIL, NB);
    block_mma_kernel<CIN, DIL, TIL, FINAL><<<grid, 512, smem_mma(CIN, DIL, TIL)>>>(
        xH, xL, xss, w1H, w1L, w2H, w2L, b1, b2, yH, yL, yss,
        ids, w1cs, b1cs, w2cs, b2cs, fcw, fcb, fout);
}

extern "C" void kernel_launch(void* const* d_in, const int* in_sizes, int n_in,
                              void* d_out, int out_size)
{
    const float* x        = (const float*)d_in[0];
    const float* enc0_b1  = (const float*)d_in[2];
    const float* enc0_b2  = (const float*)d_in[4];
    const float* enc_b1   = (const float*)d_in[6];
    const float* enc_b2   = (const float*)d_in[8];
    const float* comp_b   = (const float*)d_in[10];
    const float* decf0_b1 = (const float*)d_in[12];
    const float* decf0_b2 = (const float*)d_in[14];
    const float* decf_b1  = (const float*)d_in[16];
    const float* decf_b2  = (const float*)d_in[18];
    const float* decv_b1  = (const float*)d_in[20];
    const float* decv_b2  = (const float*)d_in[22];
    const float* decv_cw  = (const float*)d_in[23];
    const float* decv_cb  = (const float*)d_in[24];
    float* out = (float*)d_out;

    __nv_bfloat16 *catH, *catL, *decH, *decL, *uH, *uL, *w1H, *w1L, *w2H, *w2L;
    int* idsp;
    cudaGetSymbolAddress((void**)&catH, g_catH);
    cudaGetSymbolAddress((void**)&catL, g_catL);
    cudaGetSymbolAddress((void**)&decH, g_decH);
    cudaGetSymbolAddress((void**)&decL, g_decL);
    cudaGetSymbolAddress((void**)&uH,   g_encUH);
    cudaGetSymbolAddress((void**)&uL,   g_encUL);
    cudaGetSymbolAddress((void**)&w1H,  g_w1H);
    cudaGetSymbolAddress((void**)&w1L,  g_w1L);
    cudaGetSymbolAddress((void**)&w2H,  g_w2H);
    cudaGetSymbolAddress((void**)&w2L,  g_w2L);
    cudaGetSymbolAddress((void**)&idsp, g_ids);

    static bool comp_attr = false;
    if (!comp_attr) {
        cudaFuncSetAttribute(comp_mma_kernel,
                             cudaFuncAttributeMaxDynamicSharedMemorySize, SMEM_C);
        comp_attr = true;
    }

    {
        dim3 g1(160, 18);
        prep_w1<<<g1, 256>>>((const float*)d_in[1], (const float*)d_in[5],
                             (const float*)d_in[11], (const float*)d_in[15],
                             (const float*)d_in[19]);
        dim3 g2(48, 20);
        prep_w2<<<g2, 256>>>((const float*)d_in[3], (const float*)d_in[7],
                             (const float*)d_in[13], (const float*)d_in[17],
                             (const float*)d_in[21], (const float*)d_in[9], x);
    }

    static const int OFF1[18] = {
        0, 10240, 30720, 51200, 71680, 92160, 112640,
        153600, 174080, 194560,
        215040, 235520, 256000, 276480, 296960, 317440, 337920, 358400};

    // ---- encoder ----
    launch_block<1, 1, 128>(x, nullptr, (long)(LLEN + 1),
                            w1H + OFF1[0], w1L + OFF1[0], w2H + 0, w2L + 0,
                            enc0_b1, enc0_b2,
                            catH, catL, SS32, nullptr, 0, 0, 0, 0);
    launch_block<32, 2, 128>(catH + 0 * PLN, catL + 0 * PLN, SS32,
                             w1H + OFF1[1], w1L + OFF1[1], w2H + 1 * 4096, w2L + 1 * 4096,
                             enc_b1 + 0 * 128, enc_b2 + 0 * 32,
                             catH + 1 * PLN, catL + 1 * PLN, SS32, nullptr, 0, 0, 0, 0);
    launch_block<32, 4, 128>(catH + 1 * PLN, catL + 1 * PLN, SS32,
                             w1H + OFF1[2], w1L + OFF1[2], w2H + 2 * 4096, w2L + 2 * 4096,
                             enc_b1 + 1 * 128, enc_b2 + 1 * 32,
                             catH + 2 * PLN, catL + 2 * PLN, SS32, nullptr, 0, 0, 0, 0);
    launch_block<32, 8, 128>(catH + 2 * PLN, catL + 2 * PLN, SS32,
                             w1H + OFF1[3], w1L + OFF1[3], w2H + 3 * 4096, w2L + 3 * 4096,
                             enc_b1 + 2 * 128, enc_b2 + 2 * 32,
                             catH + 3 * PLN, catL + 3 * PLN, SS32, nullptr, 0, 0, 0, 0);
    launch_block<32, 16, 128>(catH + 3 * PLN, catL + 3 * PLN, SS32,
                              w1H + OFF1[4], w1L + OFF1[4], w2H + 4 * 4096, w2L + 4 * 4096,
                              enc_b1 + 3 * 128, enc_b2 + 3 * 32,
                              catH + 4 * PLN, catL + 4 * PLN, SS32, nullptr, 0, 0, 0, 0);
    launch_block<32, 32, 64>(catH + 4 * PLN, catL + 4 * PLN, SS32,
                             w1H + OFF1[5], w1L + OFF1[5], w2H + 5 * 4096, w2L + 5 * 4096,
                             enc_b1 + 4 * 128, enc_b2 + 4 * 32,
                             catH + 5 * PLN, catL + 5 * PLN, SS32, nullptr, 0, 0, 0, 0);

    // ---- compress + pool + upsample ----
    {
        dim3 grid(LLEN / CTILE, NB);
        comp_mma_kernel<<<grid, 512, SMEM_C>>>(catH, catL, comp_b, uH, uL);
    }

    // ---- fixed decoder ----
    launch_block<64, 32, 64>(uH, uL, (long)SSU,
                             w1H + OFF1[6], w1L + OFF1[6], w2H + 6 * 4096, w2L + 6 * 4096,
                             decf0_b1, decf0_b2,
                             decH, decL, SS32, nullptr, 0, 0, 0, 0);
    launch_block<32, 16, 128>(decH + 0 * PLN, decL + 0 * PLN, SS32,
                              w1H + OFF1[7], w1L + OFF1[7], w2H + 7 * 4096, w2L + 7 * 4096,
                              decf_b1 + 0 * 128, decf_b2 + 0 * 32,
                              decH + 1 * PLN, decL + 1 * PLN, SS32, nullptr, 0, 0, 0, 0);
    launch_block<32, 8, 128>(decH + 1 * PLN, decL + 1 * PLN, SS32,
                             w1H + OFF1[8], w1L + OFF1[8], w2H + 8 * 4096, w2L + 8 * 4096,
                             decf_b1 + 1 * 128, decf_b2 + 1 * 32,
                             decH + 2 * PLN, decL + 2 * PLN, SS32, nullptr, 0, 0, 0, 0);
    launch_block<32, 4, 128>(decH + 2 * PLN, decL + 2 * PLN, SS32,
                             w1H + OFF1[9], w1L + OFF1[9], w2H + 9 * 4096, w2L + 9 * 4096,
                             decf_b1 + 2 * 128, decf_b2 + 2 * 32,
                             decH + 3 * PLN, decL + 3 * PLN, SS32, nullptr, 0, 0, 0, 0);

    // ---- variable decoder (per-sample weights) ----
    launch_block<32, 2, 128>(decH + 3 * PLN, decL + 3 * PLN, SS32,
                             w1H + OFF1[10], w1L + OFF1[10],
                             w2H + 10 * 4096, w2L + 10 * 4096,
                             decv_b1 + 0 * 128, decv_b2 + 0 * 32,
                             decH + 4 * PLN, decL + 4 * PLN, SS32,
                             idsp, 40960, 256, 8192, 64);
    // last decv layer + fused 192->1 output conv
    launch_block<32, 1, 128, true>(decH + 4 * PLN, decL + 4 * PLN, SS32,
                                   w1H + OFF1[10] + 20480, w1L + OFF1[10] + 20480,
                                   w2H + 11 * 4096, w2L + 11 * 4096,
                                   decv_b1 + 1 * 128, decv_b2 + 1 * 32,
                                   nullptr, nullptr, 0,
                                   idsp, 40960, 256, 8192, 64,
                                   decv_cw, decv_cb, out);
}

// round 15
// speedup vs baseline: 1.6015x; 1.0284x over previous
#include <cuda_runtime.h>
#include <cuda_bf16.h>

#define LLEN 1024
#define NB   64
#define PLN  (LLEN * 32)          // one 32-ch plane, elems
#define SS32 (6 * PLN)            // cat/dec sample stride (elems)
#define SSU  (LLEN * 64)          // encU sample stride

// ---- device scratch (no allocations allowed) ----
__device__ __nv_bfloat16 g_catH[NB * SS32], g_catL[NB * SS32];
__device__ __nv_bfloat16 g_decH[NB * SS32], g_decL[NB * SS32];
__device__ __nv_bfloat16 g_encUH[NB * SSU], g_encUL[NB * SSU];
__device__ __nv_bfloat16 g_w1H[378880], g_w1L[378880];
__device__ __nv_bfloat16 g_w2H[86016],  g_w2L[86016];
__device__ int g_ids[NB];

__constant__ int c_OFF1[18] = {
    0, 10240, 30720, 51200, 71680, 92160, 112640,
    153600, 174080, 194560,
    215040, 235520, 256000, 276480, 296960, 317440, 337920, 358400};

__device__ __forceinline__ void mma_bf16(float* c, const unsigned* a,
                                         unsigned b0, unsigned b1) {
    asm volatile(
        "mma.sync.aligned.m16n8k16.row.col.f32.bf16.bf16.f32 "
        "{%0,%1,%2,%3}, {%4,%5,%6,%7}, {%8,%9}, {%0,%1,%2,%3};\n"
        : "+f"(c[0]), "+f"(c[1]), "+f"(c[2]), "+f"(c[3])
        : "r"(a[0]), "r"(a[1]), "r"(a[2]), "r"(a[3]), "r"(b0), "r"(b1));
}
__device__ __forceinline__ void ldsm4(unsigned* r, unsigned addr) {
    asm volatile("ldmatrix.sync.aligned.m8n8.x4.shared.b16 {%0,%1,%2,%3}, [%4];\n"
                 : "=r"(r[0]), "=r"(r[1]), "=r"(r[2]), "=r"(r[3]) : "r"(addr));
}
__device__ __forceinline__ void ldsm2(unsigned* r, unsigned addr) {
    asm volatile("ldmatrix.sync.aligned.m8n8.x2.shared.b16 {%0,%1}, [%2];\n"
                 : "=r"(r[0]), "=r"(r[1]) : "r"(addr));
}
__device__ __forceinline__ void ldsm4t(unsigned* r, unsigned addr) {
    asm volatile("ldmatrix.sync.aligned.m8n8.x4.trans.shared.b16 {%0,%1,%2,%3}, [%4];\n"
                 : "=r"(r[0]), "=r"(r[1]), "=r"(r[2]), "=r"(r[3]) : "r"(addr));
}
__device__ __forceinline__ void ldsm2t(unsigned* r, unsigned addr) {
    asm volatile("ldmatrix.sync.aligned.m8n8.x2.trans.shared.b16 {%0,%1}, [%2];\n"
                 : "=r"(r[0]), "=r"(r[1]) : "r"(addr));
}
__device__ __forceinline__ unsigned su32(const void* p) {
    return (unsigned)__cvta_generic_to_shared(p);
}
__device__ __forceinline__ void cpa16(unsigned dst, const void* src) {
    asm volatile("cp.async.ca.shared.global [%0], [%1], 16;\n"
                 :: "r"(dst), "l"(src));
}
__device__ __forceinline__ void cpa16z(unsigned dst, const void* src, int sz) {
    asm volatile("cp.async.ca.shared.global [%0], [%1], 16, %2;\n"
                 :: "r"(dst), "l"(src), "r"(sz));
}
#define CP_COMMIT() asm volatile("cp.async.commit_group;\n" ::: "memory")
#define CP_WAIT0()  asm volatile("cp.async.wait_group 0;\n"  ::: "memory")

// PDL primitives (griddepcontrol)
__device__ __forceinline__ void pdl_trigger() {
    asm volatile("griddepcontrol.launch_dependents;");
}
__device__ __forceinline__ void pdl_wait() {
    asm volatile("griddepcontrol.wait;" ::: "memory");
}

__device__ __forceinline__ void split_bf16(float v, __nv_bfloat16& hi, __nv_bfloat16& lo) {
    hi = __float2bfloat16(v);
    lo = __float2bfloat16(v - __bfloat162float(hi));
}

// ------------------------------------------------------------------
// prep kernels: split weights into bf16 hi/lo planes, staging layout
// ------------------------------------------------------------------
__global__ void prep_w1(const float* __restrict__ enc0, const float* __restrict__ enc,
                        const float* __restrict__ decf0, const float* __restrict__ decf,
                        const float* __restrict__ decv)
{
    int L = blockIdx.y;
    int e = blockIdx.x * 256 + threadIdx.x;
    if (L == 0) {
        if (e >= 2048) return;
        int k = e & 15, tmp = e >> 4;
        int co = tmp & 63, half = tmp >> 6;
        float v = (k < 5) ? enc0[(long)(half * 64 + co) * 5 + k] : 0.f;
        __nv_bfloat16 h, l; split_bf16(v, h, l);
        g_w1H[e] = h;  g_w1L[e] = l;
        return;
    }
    int cinv = (L == 6) ? 64 : 32;
    int cinp = cinv;
    int total = 640 * cinp;
    if (e >= total) return;
    int ci  = e % cinp;
    int tmp = e / cinp;
    int co  = tmp & 63;  tmp >>= 6;
    int t   = tmp % 5, half = tmp / 5;
    const float* src;
    if (L <= 5) src = enc + (L - 1) * 20480;
    else if (L == 6) src = decf0;
    else if (L <= 9) src = decf + (L - 7) * 20480;
    else src = decv + (L - 10) * 20480;
    float v = src[(long)(half * 64 + co) * (cinv * 5) + ci * 5 + t];
    __nv_bfloat16 h, l; split_bf16(v, h, l);
    g_w1H[c_OFF1[L] + e] = h;
    g_w1L[c_OFF1[L] + e] = l;
}

// L==19 row additionally extracts the per-sample combination ids.
__global__ void prep_w2(const float* __restrict__ enc0, const float* __restrict__ enc,
                        const float* __restrict__ decf0, const float* __restrict__ decf,
                        const float* __restrict__ decv, const float* __restrict__ comp,
                        const float* __restrict__ x)
{
    int L = blockIdx.y;
    int e = blockIdx.x * 256 + threadIdx.x;
    if (L == 19) {
        if (blockIdx.x == 0 && e < NB)
            g_ids[e] = (int)x[(long)e * (LLEN + 1) + LLEN];
        return;
    }
    int sz = (L == 18) ? 12288 : 4096;
    if (e >= sz) return;
    const float* src;
    if (L == 0) src = enc0;
    else if (L <= 5) src = enc + (L - 1) * 4096;
    else if (L == 6) src = decf0;
    else if (L <= 9) src = decf + (L - 7) * 4096;
    else if (L <= 17) src = decv + (L - 10) * 4096;
    else src = comp;
    long off = (L == 18) ? 73728 : (long)L * 4096;
    __nv_bfloat16 h, l; split_bf16(src[e], h, l);
    g_w2H[off + e] = h;
    g_w2L[off + e] = l;
}

// ------------------------------------------------------------------
// Fused TCN block (bf16 hi/lo planes end-to-end, LDSM, cp.async staging,
// PDL: weights staged pre-wait, activations post-wait):
//   conv1: CIN -> 128 (k=5, dil DIL) + bias + relu, two co-halves of 64
//   conv2: 128 -> 32 (1x1) + bias + relu
// hs kept in natural [co][l] orientation; conv2 B via ldmatrix.trans.
// CIN==1 (FOLD): taps folded into K=16.
// FINAL: last decv layer; plane-5 kept in smem; fused 192->1 output conv.
// 512 thr = 16 warps, 2 CTAs/SM.
// ------------------------------------------------------------------
template<int CIN, int DIL, int TIL, bool FINAL = false>
__global__ void __launch_bounds__(512, 2)
block_mma_kernel(const void* __restrict__ xHv, const void* __restrict__ xLv, long xss,
                 const __nv_bfloat16* __restrict__ w1Hg, const __nv_bfloat16* __restrict__ w1Lg,
                 const __nv_bfloat16* __restrict__ w2Hg, const __nv_bfloat16* __restrict__ w2Lg,
                 const float* __restrict__ b1, const float* __restrict__ b2,
                 __nv_bfloat16* __restrict__ yH, __nv_bfloat16* __restrict__ yL, long yss,
                 const int* __restrict__ ids,
                 long w1_cs, long b1_cs, long w2_cs, long b2_cs,
                 const float* __restrict__ fcw, const float* __restrict__ fcb,
                 float* __restrict__ fout)
{
    constexpr bool FOLD = (CIN == 1);
    constexpr int CINP = FOLD ? 16 : CIN;
    constexpr int XW   = FOLD ? TIL : (TIL + 4 * DIL);
    constexpr int NK   = CINP / 16;
    constexpr int SB   = CINP + 8;       // xt / wa row stride (bf16)
    constexpr int SHS  = TIL + 8;        // hs row stride (co-major)
    constexpr int S2   = 136;            // w2 row stride
    constexpr int NT   = TIL / 64;
    constexpr bool DBUF = (!FOLD && CIN <= 32);
    constexpr int NBUF = DBUF ? 2 : 1;
    constexpr int WBUF = 64 * SB;
    constexpr int WW   = 64 * CINP / 2;      // words per tap per half per plane
    constexpr int WRW  = CINP / 2;           // words per co row
    constexpr int CHK  = WRW / 4;            // 16B chunks per co row
    constexpr int NCP  = 64 * CHK;           // chunks per plane per tap
    constexpr int SF   = TIL + 4;            // final fp32 plane5 row stride

    extern __shared__ __nv_bfloat16 smb[];
    __nv_bfloat16* xtH = smb;
    __nv_bfloat16* xtL = xtH + XW * SB;
    __nv_bfloat16* waB = xtL + XW * SB;      // H bufs then L bufs
    __nv_bfloat16* hH  = waB + 2 * NBUF * WBUF;    // [64 co][SHS]
    __nv_bfloat16* hL  = hH  + 64 * SHS;
    __nv_bfloat16* w2H = hL  + 64 * SHS;
    __nv_bfloat16* w2L = w2H + 32 * S2;
    float* b1s = (float*)(w2L + 32 * S2);
    float* b2s = b1s + 128;

    const int b    = blockIdx.y;
    const int l0   = blockIdx.x * TIL;
    const int tid  = threadIdx.x;
    const int warp = tid >> 5;
    const int ln   = tid & 31;
    const int lq   = ln & 3;
    const int lg   = ln >> 2;
    const int lr   = ln & 7;
    const int lt   = ln >> 3;

    const __nv_bfloat16* w1Hp = w1Hg;
    const __nv_bfloat16* w1Lp = w1Lg;
    const __nv_bfloat16* w2Hp = w2Hg;
    const __nv_bfloat16* w2Lp = w2Lg;
    const float* b1p = b1;
    const float* b2p = b2;
    int cid = 0;
    if (ids) {   // g_ids written by prep (complete before any PDL kernel starts)
        cid = ids[b];
        w1Hp += (long)cid * w1_cs;  w1Lp += (long)cid * w1_cs;
        w2Hp += (long)cid * w2_cs;  w2Lp += (long)cid * w2_cs;
        b1p  += (long)cid * b1_cs;  b2p  += (long)cid * b2_cs;
    }

    pdl_trigger();   // let the next layer start its weight prologue

    // ---- weight staging lambdas ----
    auto stage_w1 = [&](int hf, int tt, int bufsel) {
        if constexpr (!FOLD) {
            __nv_bfloat16* dH = waB + bufsel * WBUF;
            __nv_bfloat16* dL = dH + NBUF * WBUF;
            const char* sH = (const char*)w1Hp + ((size_t)hf * 5 + tt) * WW * 4;
            const char* sL = (const char*)w1Lp + ((size_t)hf * 5 + tt) * WW * 4;
            #pragma unroll
            for (int j = 0; j < (2 * NCP) / 512; j++) {
                int i = tid + j * 512;
                int pl = i / NCP, q = i - pl * NCP;
                int co = q / CHK, ck = q - co * CHK;
                const char* s = (pl ? sL : sH) + co * (WRW * 4) + ck * 16;
                unsigned d = su32((pl ? dL : dH) + co * SB) + ck * 16;
                cpa16(d, s);
            }
        }
    };
    auto stage_fold = [&](int hf) {
        if constexpr (FOLD) {
            if (tid < 256) {
                int pl = tid >> 7, q = tid & 127;
                int co = q >> 1, ck = q & 1;
                const __nv_bfloat16* srcp = pl ? w1Lp : w1Hp;
                __nv_bfloat16* dstp = pl ? (waB + WBUF) : waB;
                cpa16(su32(dstp + co * SB) + ck * 16,
                      (const char*)srcp + hf * 2048 + co * 32 + ck * 16);
            }
        }
    };

    // ---- pre-wait prologue: weights + biases (prep outputs / inputs) ----
    for (int i = tid; i < 1024; i += 512) {
        int pl = i >> 9, q = i & 511;
        int co = q >> 4, ck = q & 15;
        const char* src = (const char*)(pl ? w2Lp : w2Hp) + (co * 64 + ck * 4) * 4;
        unsigned dst = su32((pl ? w2L : w2H) + co * S2) + ck * 16;
        cpa16(dst, src);
    }
    if constexpr (FOLD) stage_fold(0);
    else stage_w1(0, 0, 0);
    if (tid < 128) b1s[tid] = b1p[tid];
    if (tid < 32)  b2s[tid] = b2p[tid];

    pdl_wait();      // previous layer's activations now complete

    // ---- stage x (async; zero-fill halo) ----
    if constexpr (FOLD) {
        const float* xf = (const float*)xHv + (long)b * xss;
        for (int i = tid; i < TIL * 16; i += 512) {
            int r = i >> 4, k = i & 15;
            int pos = l0 - 2 * DIL + r + k * DIL;
            float v = (k < 5 && pos >= 0 && pos < LLEN) ? xf[pos] : 0.f;
            __nv_bfloat16 hv, lv; split_bf16(v, hv, lv);
            xtH[r * SB + k] = hv;
            xtL[r * SB + k] = lv;
        }
    } else {
        constexpr int WR  = CIN / 2;       // words per row
        constexpr int RCH = WR / 4;        // 16B chunks per row
        const char* xbH = (const char*)((const __nv_bfloat16*)xHv + (long)b * xss);
        const char* xbL = (const char*)((const __nv_bfloat16*)xLv + (long)b * xss);
        for (int i = tid; i < XW * RCH * 2; i += 512) {
            int pl = i / (XW * RCH);
            int q  = i - pl * (XW * RCH);
            int r  = q / RCH, ck = q - r * RCH;
            int pos = l0 - 2 * DIL + r;
            bool ok = (pos >= 0 && pos < LLEN);
            const char* src = (pl ? xbL : xbH) + ((long)(ok ? pos : 0) * WR + ck * 4) * 4;
            unsigned dst = su32((pl ? xtL : xtH) + r * SB) + ck * 16;
            cpa16z(dst, src, ok ? 16 : 0);
        }
    }
    CP_COMMIT();

    const int wm  = warp >> 3;
    const int wn  = warp & 7;
    const int wm2 = warp & 1;
    const int wn2 = warp >> 1;

    float a2[NT][4];
    #pragma unroll
    for (int nt = 0; nt < NT; nt++)
        #pragma unroll
        for (int q = 0; q < 4; q++) a2[nt][q] = 0.f;

    #pragma unroll
    for (int half = 0; half < 2; half++) {
        const int coB = half * 64;

        float acc[2][NT][4];
        #pragma unroll
        for (int mt = 0; mt < 2; mt++)
            #pragma unroll
            for (int nt = 0; nt < NT; nt++)
                #pragma unroll
                for (int q = 0; q < 4; q++) acc[mt][nt][q] = 0.f;

        if constexpr (FOLD) {
            if (half == 1) { stage_fold(1); CP_COMMIT(); }
            CP_WAIT0();
            __syncthreads();

            unsigned ah[2][4], al[2][4];
            #pragma unroll
            for (int mt = 0; mt < 2; mt++) {
                int arow = wm * 32 + mt * 16 + lr + (lt & 1) * 8;
                int acol = (lt >> 1) * 8;
                ldsm4(ah[mt], su32(waB + arow * SB + acol));
                ldsm4(al[mt], su32(waB + WBUF + arow * SB + acol));
            }
            unsigned bh[4], bl[4];
            if (NT == 2) {
                int brow = wn * 16 + lr + (lt & 1) * 8;
                int bcol = (lt >> 1) * 8;
                ldsm4(bh, su32(xtH + brow * SB + bcol));
                ldsm4(bl, su32(xtL + brow * SB + bcol));
            } else {
                int brow = wn * 8 + lr;
                int bcol = ((ln >> 3) & 1) * 8;
                ldsm2(bh, su32(xtH + brow * SB + bcol));
                ldsm2(bl, su32(xtL + brow * SB + bcol));
            }
            #pragma unroll
            for (int nt = 0; nt < NT; nt++) {
                unsigned bh0 = (NT == 2) ? bh[nt] : bh[0];
                unsigned bh1 = (NT == 2) ? bh[nt + 2] : bh[1];
                unsigned bl0 = (NT == 2) ? bl[nt] : bl[0];
                unsigned bl1 = (NT == 2) ? bl[nt + 2] : bl[1];
                #pragma unroll
                for (int mt = 0; mt < 2; mt++) {
                    mma_bf16(acc[mt][nt], ah[mt], bh0, bh1);
                    mma_bf16(acc[mt][nt], ah[mt], bl0, bl1);
                    mma_bf16(acc[mt][nt], al[mt], bh0, bh1);
                }
            }
        } else {
            if (half == 1) { stage_w1(1, 0, 0); CP_COMMIT(); }
            CP_WAIT0();
            __syncthreads();

            #pragma unroll
            for (int t = 0; t < 5; t++) {
                if (DBUF && t < 4) {
                    stage_w1(half, t + 1, (t + 1) & 1);
                    CP_COMMIT();
                }

                const __nv_bfloat16* wH = waB + (DBUF ? (t & 1) * WBUF : 0);
                const __nv_bfloat16* wL = wH + NBUF * WBUF;

                #pragma unroll
                for (int kc = 0; kc < NK; kc++) {
                    unsigned ah[2][4], al[2][4];
                    #pragma unroll
                    for (int mt = 0; mt < 2; mt++) {
                        int arow = wm * 32 + mt * 16 + lr + (lt & 1) * 8;
                        int acol = kc * 16 + (lt >> 1) * 8;
                        ldsm4(ah[mt], su32(wH + arow * SB + acol));
                        ldsm4(al[mt], su32(wL + arow * SB + acol));
                    }
                    unsigned bh[4], bl[4];
                    if (NT == 2) {
                        int brow = wn * 16 + lr + (lt & 1) * 8 + t * DIL;
                        int bcol = kc * 16 + (lt >> 1) * 8;
                        ldsm4(bh, su32(xtH + brow * SB + bcol));
                        ldsm4(bl, su32(xtL + brow * SB + bcol));
                    } else {
                        int brow = wn * 8 + lr + t * DIL;
                        int bcol = kc * 16 + ((ln >> 3) & 1) * 8;
                        ldsm2(bh, su32(xtH + brow * SB + bcol));
                        ldsm2(bl, su32(xtL + brow * SB + bcol));
                    }
                    #pragma unroll
                    for (int nt = 0; nt < NT; nt++) {
                        unsigned bh0 = (NT == 2) ? bh[nt] : bh[0];
                        unsigned bh1 = (NT == 2) ? bh[nt + 2] : bh[1];
                        unsigned bl0 = (NT == 2) ? bl[nt] : bl[0];
                        unsigned bl1 = (NT == 2) ? bl[nt + 2] : bl[1];
                        #pragma unroll
                        for (int mt = 0; mt < 2; mt++) {
                            mma_bf16(acc[mt][nt], ah[mt], bh0, bh1);
                            mma_bf16(acc[mt][nt], ah[mt], bl0, bl1);
                            mma_bf16(acc[mt][nt], al[mt], bh0, bh1);
                        }
                    }
                }

                if (t < 4) {
                    if (!DBUF) {
                        __syncthreads();
                        stage_w1(half, t + 1, 0);
                        CP_COMMIT();
                    }
                    CP_WAIT0();
                    __syncthreads();
                }
            }
        }

        // ---- conv1 epilogue: bias + relu + split -> hs [co][l], packed ----
        #pragma unroll
        for (int mt = 0; mt < 2; mt++) {
            int m = wm * 32 + mt * 16 + lg;      // local co (0..63)
            float bb0 = b1s[coB + m], bb1 = b1s[coB + m + 8];
            #pragma unroll
            for (int nt = 0; nt < NT; nt++) {
                int n = ((NT == 2) ? wn * 16 + nt * 8 : wn * 8) + 2 * lq;
                float* a = acc[mt][nt];
                float v00 = a[0] + bb0, v01 = a[1] + bb0;
                float v10 = a[2] + bb1, v11 = a[3] + bb1;
                v00 = v00 > 0.f ? v00 : 0.f;  v01 = v01 > 0.f ? v01 : 0.f;
                v10 = v10 > 0.f ? v10 : 0.f;  v11 = v11 > 0.f ? v11 : 0.f;
                __nv_bfloat16 h0, l0h, h1, l1h;
                split_bf16(v00, h0, l0h); split_bf16(v01, h1, l1h);
                *(__nv_bfloat162*)(hH + m * SHS + n) = __halves2bfloat162(h0, h1);
                *(__nv_bfloat162*)(hL + m * SHS + n) = __halves2bfloat162(l0h, l1h);
                split_bf16(v10, h0, l0h); split_bf16(v11, h1, l1h);
                *(__nv_bfloat162*)(hH + (m + 8) * SHS + n) = __halves2bfloat162(h0, h1);
                *(__nv_bfloat162*)(hL + (m + 8) * SHS + n) = __halves2bfloat162(l0h, l1h);
            }
        }
        __syncthreads();

        // ---- conv2 partial: B via ldmatrix.trans from [co][l] hs ----
        #pragma unroll
        for (int kc = 0; kc < 4; kc++) {
            unsigned ah[4], al[4];
            {
                int arow = wm2 * 16 + lr + (lt & 1) * 8;
                int acol = coB + kc * 16 + (lt >> 1) * 8;
                ldsm4(ah, su32(w2H + arow * S2 + acol));
                ldsm4(al, su32(w2L + arow * S2 + acol));
            }
            unsigned bh[4], bl[4];
            if (NT == 2) {
                int brow = kc * 16 + (lt & 1) * 8 + lr;     // k (local co)
                int bcol = wn2 * 16 + (lt >> 1) * 8;        // n (l)
                ldsm4t(bh, su32(hH + brow * SHS + bcol));
                ldsm4t(bl, su32(hL + brow * SHS + bcol));
            } else {
                int brow = kc * 16 + ((ln >> 3) & 1) * 8 + lr;
                int bcol = wn2 * 8;
                ldsm2t(bh, su32(hH + brow * SHS + bcol));
                ldsm2t(bl, su32(hL + brow * SHS + bcol));
            }
            #pragma unroll
            for (int nt = 0; nt < NT; nt++) {
                unsigned bh0 = (NT == 2) ? bh[2 * nt]     : bh[0];
                unsigned bh1 = (NT == 2) ? bh[2 * nt + 1] : bh[1];
                unsigned bl0 = (NT == 2) ? bl[2 * nt]     : bl[0];
                unsigned bl1 = (NT == 2) ? bl[2 * nt + 1] : bl[1];
                mma_bf16(a2[nt], ah, bh0, bh1);
                mma_bf16(a2[nt], ah, bl0, bl1);
                mma_bf16(a2[nt], al, bh0, bh1);
            }
        }
    }

    if constexpr (!FINAL) {
        // ---- conv2 epilogue: bias + relu + split -> y planes [l][co] ----
        __nv_bfloat16* yHb = yH + (long)b * yss;
        __nv_bfloat16* yLb = yL + (long)b * yss;
        int row = wm2 * 16 + lg;
        float bb0 = b2s[row], bb1 = b2s[row + 8];
        #pragma unroll
        for (int nt = 0; nt < NT; nt++) {
            int col = ((NT == 2) ? wn2 * 16 + nt * 8 : wn2 * 8) + 2 * lq;
            float v0 = a2[nt][0] + bb0, v1 = a2[nt][1] + bb0;
            float v2 = a2[nt][2] + bb1, v3 = a2[nt][3] + bb1;
            v0 = v0 > 0.f ? v0 : 0.f;  v1 = v1 > 0.f ? v1 : 0.f;
            v2 = v2 > 0.f ? v2 : 0.f;  v3 = v3 > 0.f ? v3 : 0.f;
            __nv_bfloat16 hv, lv;
            split_bf16(v0, hv, lv);
            yHb[(long)(l0 + col) * 32 + row] = hv;       yLb[(long)(l0 + col) * 32 + row] = lv;
            split_bf16(v1, hv, lv);
            yHb[(long)(l0 + col + 1) * 32 + row] = hv;   yLb[(long)(l0 + col + 1) * 32 + row] = lv;
            split_bf16(v2, hv, lv);
            yHb[(long)(l0 + col) * 32 + row + 8] = hv;   yLb[(long)(l0 + col) * 32 + row + 8] = lv;
            split_bf16(v3, hv, lv);
            yHb[(long)(l0 + col + 1) * 32 + row + 8] = hv; yLb[(long)(l0 + col + 1) * 32 + row + 8] = lv;
        }
    } else {
        // ---- FINAL: plane5 -> smem fp32, then 192->1 output conv ----
        __syncthreads();                // all conv2 hs reads done before reuse
        float* ps = (float*)hH;         // [32 co][SF] fp32 plane5 tile
        float* ws = (float*)waB;        // 192 final weights
        {
            int row = wm2 * 16 + lg;
            float bb0 = b2s[row], bb1 = b2s[row + 8];
            #pragma unroll
            for (int nt = 0; nt < NT; nt++) {
                int col = ((NT == 2) ? wn2 * 16 + nt * 8 : wn2 * 8) + 2 * lq;
                float v0 = a2[nt][0] + bb0, v1 = a2[nt][1] + bb0;
                float v2 = a2[nt][2] + bb1, v3 = a2[nt][3] + bb1;
                ps[row * SF + col]           = v0 > 0.f ? v0 : 0.f;
                ps[row * SF + col + 1]       = v1 > 0.f ? v1 : 0.f;
                ps[(row + 8) * SF + col]     = v2 > 0.f ? v2 : 0.f;
                ps[(row + 8) * SF + col + 1] = v3 > 0.f ? v3 : 0.f;
            }
        }
        if (tid < 192) ws[tid] = fcw[(long)cid * 192 + tid];
        __syncthreads();

        if (tid < TIL) {
            int l = tid;
            float s = fcb[cid];
            const __nv_bfloat16* dH = (const __nv_bfloat16*)xHv + (long)b * xss - 4 * PLN;
            const __nv_bfloat16* dL = (const __nv_bfloat16*)xLv + (long)b * xss - 4 * PLN;
            #pragma unroll
            for (int plane = 0; plane < 5; plane++) {
                const unsigned* pH = (const unsigned*)(dH + (long)plane * PLN + (long)(l0 + l) * 32);
                const unsigned* pL = (const unsigned*)(dL + (long)plane * PLN + (long)(l0 + l) * 32);
                #pragma unroll
                for (int w = 0; w < 16; w++) {
                    unsigned uh = pH[w], ul = pL[w];
                    float2 fh = __bfloat1622float2(*(const __nv_bfloat162*)&uh);
                    float2 fl = __bfloat1622float2(*(const __nv_bfloat162*)&ul);
                    s = fmaf(ws[plane * 32 + 2 * w],     fh.x + fl.x, s);
                    s = fmaf(ws[plane * 32 + 2 * w + 1], fh.y + fl.y, s);
                }
            }
            #pragma unroll
            for (int ch = 0; ch < 32; ch++)
                s = fmaf(ws[160 + ch], ps[ch * SF + l], s);
            fout[(long)b * LLEN + l0 + l] = s;
        }
    }
}

// ------------------------------------------------------------------
// compress conv (192 -> 64) + avgpool(2) + nearest-upsample(2), mma, PDL.
// ------------------------------------------------------------------
#define CTILE 64
__global__ void __launch_bounds__(512, 2)
comp_mma_kernel(const __nv_bfloat16* __restrict__ catH, const __nv_bfloat16* __restrict__ catL,
                const float* __restrict__ cb,
                __nv_bfloat16* __restrict__ uH, __nv_bfloat16* __restrict__ uL)
{
    constexpr int SA = 200;

    extern __shared__ __nv_bfloat16 smb[];
    __nv_bfloat16* xtH = smb;                  // [64 l][200]
    __nv_bfloat16* xtL = xtH + 64 * SA;
    __nv_bfloat16* waH = xtL + 64 * SA;        // [64 co][200]
    __nv_bfloat16* waL = waH + 64 * SA;
    float* cbs = (float*)(waL + 64 * SA);

    const int b    = blockIdx.y;
    const int l0   = blockIdx.x * CTILE;
    const int tid  = threadIdx.x;
    const int warp = tid >> 5;
    const int ln   = tid & 31;
    const int lq   = ln & 3;
    const int lg   = ln >> 2;
    const int lr   = ln & 7;
    const int lt   = ln >> 3;
    const int wm   = warp & 3;
    const int wn   = warp >> 2;

    pdl_trigger();

    // weights first (prep outputs — safe pre-wait)
    {
        const char* sH = (const char*)(g_w2H + 73728);
        const char* sL = (const char*)(g_w2L + 73728);
        for (int i = tid; i < 64 * 24 * 2; i += 512) {
            int pl = i / (64 * 24);
            int q  = i - pl * (64 * 24);
            int co = q / 24, ck = q - co * 24;
            unsigned dst = su32((pl ? waL : waH) + co * SA) + ck * 16;
            cpa16(dst, (pl ? sL : sH) + (co * 96 + ck * 4) * 4);
        }
    }
    if (tid < 64) cbs[tid] = cb[tid];

    pdl_wait();

    const char* cbH = (const char*)(catH + (long)b * SS32);
    const char* cbL = (const char*)(catL + (long)b * SS32);
    for (int i = tid; i < 64 * 24 * 2; i += 512) {
        int pl = i / (64 * 24);
        int q  = i - pl * (64 * 24);
        int r  = q / 24, ck = q - r * 24;
        int plane = ck / 4, wi = ck - plane * 4;
        long srcoff = ((long)plane * (PLN / 2) + (long)(l0 + r) * 16 + wi * 4) * 4;
        unsigned dst = su32((pl ? xtL : xtH) + r * SA) + (plane * 16 + wi * 4) * 4;
        cpa16(dst, (pl ? cbL : cbH) + srcoff);
    }
    CP_COMMIT(); CP_WAIT0();
    __syncthreads();

    float acc[2][4];
    #pragma unroll
    for (int nt = 0; nt < 2; nt++)
        #pragma unroll
        for (int q = 0; q < 4; q++) acc[nt][q] = 0.f;

    #pragma unroll
    for (int kc = 0; kc < 12; kc++) {
        unsigned ah[4], al[4];
        {
            int arow = wm * 16 + lr + (lt & 1) * 8;
            int acol = kc * 16 + (lt >> 1) * 8;
            ldsm4(ah, su32(waH + arow * SA + acol));
            ldsm4(al, su32(waL + arow * SA + acol));
        }
        unsigned bh[4], bl[4];
        {
            int brow = wn * 16 + lr + (lt & 1) * 8;
            int bcol = kc * 16 + (lt >> 1) * 8;
            ldsm4(bh, su32(xtH + brow * SA + bcol));
            ldsm4(bl, su32(xtL + brow * SA + bcol));
        }
        #pragma unroll
        for (int nt = 0; nt < 2; nt++) {
            mma_bf16(acc[nt], ah, bh[nt], bh[nt + 2]);
            mma_bf16(acc[nt], ah, bl[nt], bl[nt + 2]);
            mma_bf16(acc[nt], al, bh[nt], bh[nt + 2]);
        }
    }

    __nv_bfloat16* uHb = uH + (long)b * SSU;
    __nv_bfloat16* uLb = uL + (long)b * SSU;
    {
        int m = wm * 16 + lg;
        float bb0 = cbs[m], bb1 = cbs[m + 8];
        #pragma unroll
        for (int nt = 0; nt < 2; nt++) {
            int n = wn * 16 + nt * 8 + 2 * lq;
            float* a = acc[nt];
            float p0 = 0.5f * ((a[0] + bb0) + (a[1] + bb0));
            float p1 = 0.5f * ((a[2] + bb1) + (a[3] + bb1));
            __nv_bfloat16 hv, lv;
            split_bf16(p0, hv, lv);
            uHb[(long)(l0 + n) * 64 + m] = hv;      uHb[(long)(l0 + n + 1) * 64 + m] = hv;
            uLb[(long)(l0 + n) * 64 + m] = lv;      uLb[(long)(l0 + n + 1) * 64 + m] = lv;
            split_bf16(p1, hv, lv);
            uHb[(long)(l0 + n) * 64 + m + 8] = hv;  uHb[(long)(l0 + n + 1) * 64 + m + 8] = hv;
            uLb[(long)(l0 + n) * 64 + m + 8] = lv;  uLb[(long)(l0 + n + 1) * 64 + m + 8] = lv;
        }
    }
}

// ------------------------------------------------------------------
static constexpr int smem_mma(int cin, int dil, int til) {
    bool fold = (cin == 1);
    int cinp = fold ? 16 : cin;
    int sb   = cinp + 8;
    int nbuf = (!fold && cin <= 32) ? 2 : 1;
    int xw   = fold ? til : (til + 4 * dil);
    int elems = 2 * xw * sb + 2 * nbuf * 64 * sb + 2 * 64 * (til + 8) + 2 * 32 * 136;
    return elems * 2 + 160 * 4;
}
static constexpr int SMEM_C = (4 * 64 * 200) * 2 + 256;

template<int CIN, int DIL, int TIL, bool FINAL = false>
static void launch_block(bool pdl,
                         const void* xH, const void* xL, long xss,
                         const __nv_bfloat16* w1H, const __nv_bfloat16* w1L,
                         const __nv_bfloat16* w2H, const __nv_bfloat16* w2L,
                         const float* b1, const float* b2,
                         __nv_bfloat16* yH, __nv_bfloat16* yL, long yss,
                         const int* ids, long w1cs, long b1cs, long w2cs, long b2cs,
                         const float* fcw = nullptr, const float* fcb = nullptr,
                         float* fout = nullptr)
{
    static bool attr_done = false;
    if (!attr_done) {
        cudaFuncSetAttribute(block_mma_kernel<CIN, DIL, TIL, FINAL>,
                             cudaFuncAttributeMaxDynamicSharedMemorySize,
                             smem_mma(CIN, DIL, TIL));
        attr_done = true;
    }
    cudaLaunchConfig_t cfg = {};
    cfg.gridDim = dim3(LLEN / TIL, NB, 1);
    cfg.blockDim = dim3(512, 1, 1);
    cfg.dynamicSmemBytes = smem_mma(CIN, DIL, TIL);
    cfg.stream = 0;
    cudaLaunchAttribute at;
    at.id = cudaLaunchAttributeProgrammaticStreamSerialization;
    at.val.programmaticStreamSerializationAllowed = 1;
    cfg.attrs = &at;
    cfg.numAttrs = pdl ? 1 : 0;
    cudaLaunchKernelEx(&cfg, block_mma_kernel<CIN, DIL, TIL, FINAL>,
                       xH, xL, xss, w1H, w1L, w2H, w2L, b1, b2, yH, yL, yss,
                       ids, w1cs, b1cs, w2cs, b2cs, fcw, fcb, fout);
}

extern "C" void kernel_launch(void* const* d_in, const int* in_sizes, int n_in,
                              void* d_out, int out_size)
{
    const float* x        = (const float*)d_in[0];
    const float* enc0_b1  = (const float*)d_in[2];
    const float* enc0_b2  = (const float*)d_in[4];
    const float* enc_b1   = (const float*)d_in[6];
    const float* enc_b2   = (const float*)d_in[8];
    const float* comp_b   = (const float*)d_in[10];
    const float* decf0_b1 = (const float*)d_in[12];
    const float* decf0_b2 = (const float*)d_in[14];
    const float* decf_b1  = (const float*)d_in[16];
    const float* decf_b2  = (const float*)d_in[18];
    const float* decv_b1  = (const float*)d_in[20];
    const float* decv_b2  = (const float*)d_in[22];
    const float* decv_cw  = (const float*)d_in[23];
    const float* decv_cb  = (const float*)d_in[24];
    float* out = (float*)d_out;

    __nv_bfloat16 *catH, *catL, *decH, *decL, *uH, *uL, *w1H, *w1L, *w2H, *w2L;
    int* idsp;
    cudaGetSymbolAddress((void**)&catH, g_catH);
    cudaGetSymbolAddress((void**)&catL, g_catL);
    cudaGetSymbolAddress((void**)&decH, g_decH);
    cudaGetSymbolAddress((void**)&decL, g_decL);
    cudaGetSymbolAddress((void**)&uH,   g_encUH);
    cudaGetSymbolAddress((void**)&uL,   g_encUL);
    cudaGetSymbolAddress((void**)&w1H,  g_w1H);
    cudaGetSymbolAddress((void**)&w1L,  g_w1L);
    cudaGetSymbolAddress((void**)&w2H,  g_w2H);
    cudaGetSymbolAddress((void**)&w2L,  g_w2L);
    cudaGetSymbolAddress((void**)&idsp, g_ids);

    static bool comp_attr = false;
    if (!comp_attr) {
        cudaFuncSetAttribute(comp_mma_kernel,
                             cudaFuncAttributeMaxDynamicSharedMemorySize, SMEM_C);
        comp_attr = true;
    }

    {
        dim3 g1(160, 18);
        prep_w1<<<g1, 256>>>((const float*)d_in[1], (const float*)d_in[5],
                             (const float*)d_in[11], (const float*)d_in[15],
                             (const float*)d_in[19]);
        dim3 g2(48, 20);
        prep_w2<<<g2, 256>>>((const float*)d_in[3], (const float*)d_in[7],
                             (const float*)d_in[13], (const float*)d_in[17],
                             (const float*)d_in[21], (const float*)d_in[9], x);
    }

    static const int OFF1[18] = {
        0, 10240, 30720, 51200, 71680, 92160, 112640,
        153600, 174080, 194560,
        215040, 235520, 256000, 276480, 296960, 317440, 337920, 358400};

    // ---- encoder (enc0 non-PDL: anchors prep completion) ----
    launch_block<1, 1, 128>(false, x, nullptr, (long)(LLEN + 1),
                            w1H + OFF1[0], w1L + OFF1[0], w2H + 0, w2L + 0,
                            enc0_b1, enc0_b2,
                            catH, catL, SS32, nullptr, 0, 0, 0, 0);
    launch_block<32, 2, 128>(true, catH + 0 * PLN, catL + 0 * PLN, SS32,
                             w1H + OFF1[1], w1L + OFF1[1], w2H + 1 * 4096, w2L + 1 * 4096,
                             enc_b1 + 0 * 128, enc_b2 + 0 * 32,
                             catH + 1 * PLN, catL + 1 * PLN, SS32, nullptr, 0, 0, 0, 0);
    launch_block<32, 4, 128>(true, catH + 1 * PLN, catL + 1 * PLN, SS32,
                             w1H + OFF1[2], w1L + OFF1[2], w2H + 2 * 4096, w2L + 2 * 4096,
                             enc_b1 + 1 * 128, enc_b2 + 1 * 32,
                             catH + 2 * PLN, catL + 2 * PLN, SS32, nullptr, 0, 0, 0, 0);
    launch_block<32, 8, 128>(true, catH + 2 * PLN, catL + 2 * PLN, SS32,
                             w1H + OFF1[3], w1L + OFF1[3], w2H + 3 * 4096, w2L + 3 * 4096,
                             enc_b1 + 2 * 128, enc_b2 + 2 * 32,
                             catH + 3 * PLN, catL + 3 * PLN, SS32, nullptr, 0, 0, 0, 0);
    launch_block<32, 16, 128>(true, catH + 3 * PLN, catL + 3 * PLN, SS32,
                              w1H + OFF1[4], w1L + OFF1[4], w2H + 4 * 4096, w2L + 4 * 4096,
                              enc_b1 + 3 * 128, enc_b2 + 3 * 32,
                              catH + 4 * PLN, catL + 4 * PLN, SS32, nullptr, 0, 0, 0, 0);
    launch_block<32, 32, 64>(true, catH + 4 * PLN, catL + 4 * PLN, SS32,
                             w1H + OFF1[5], w1L + OFF1[5], w2H + 5 * 4096, w2L + 5 * 4096,
                             enc_b1 + 4 * 128, enc_b2 + 4 * 32,
                             catH + 5 * PLN, catL + 5 * PLN, SS32, nullptr, 0, 0, 0, 0);

    // ---- compress + pool + upsample (PDL) ----
    {
        cudaLaunchConfig_t cfg = {};
        cfg.gridDim = dim3(LLEN / CTILE, NB, 1);
        cfg.blockDim = dim3(512, 1, 1);
        cfg.dynamicSmemBytes = SMEM_C;
        cfg.stream = 0;
        cudaLaunchAttribute at;
        at.id = cudaLaunchAttributeProgrammaticStreamSerialization;
        at.val.programmaticStreamSerializationAllowed = 1;
        cfg.attrs = &at;
        cfg.numAttrs = 1;
        cudaLaunchKernelEx(&cfg, comp_mma_kernel,
                           (const __nv_bfloat16*)catH, (const __nv_bfloat16*)catL,
                           comp_b, uH, uL);
    }

    // ---- fixed decoder ----
    launch_block<64, 32, 64>(true, uH, uL, (long)SSU,
                             w1H + OFF1[6], w1L + OFF1[6], w2H + 6 * 4096, w2L + 6 * 4096,
                             decf0_b1, decf0_b2,
                             decH, decL, SS32, nullptr, 0, 0, 0, 0);
    launch_block<32, 16, 128>(true, decH + 0 * PLN, decL + 0 * PLN, SS32,
                              w1H + OFF1[7], w1L + OFF1[7], w2H + 7 * 4096, w2L + 7 * 4096,
                              decf_b1 + 0 * 128, decf_b2 + 0 * 32,
                              decH + 1 * PLN, decL + 1 * PLN, SS32, nullptr, 0, 0, 0, 0);
    launch_block<32, 8, 128>(true, decH + 1 * PLN, decL + 1 * PLN, SS32,
                             w1H + OFF1[8], w1L + OFF1[8], w2H + 8 * 4096, w2L + 8 * 4096,
                             decf_b1 + 1 * 128, decf_b2 + 1 * 32,
                             decH + 2 * PLN, decL + 2 * PLN, SS32, nullptr, 0, 0, 0, 0);
    launch_block<32, 4, 128>(true, decH + 2 * PLN, decL + 2 * PLN, SS32,
                             w1H + OFF1[9], w1L + OFF1[9], w2H + 9 * 4096, w2L + 9 * 4096,
                             decf_b1 + 2 * 128, decf_b2 + 2 * 32,
                             decH + 3 * PLN, decL + 3 * PLN, SS32, nullptr, 0, 0, 0, 0);

    // ---- variable decoder (per-sample weights) ----
    launch_block<32, 2, 128>(true, decH + 3 * PLN, decL + 3 * PLN, SS32,
                             w1H + OFF1[10], w1L + OFF1[10],
                             w2H + 10 * 4096, w2L + 10 * 4096,
                             decv_b1 + 0 * 128, decv_b2 + 0 * 32,
                             decH + 4 * PLN, decL + 4 * PLN, SS32,
                             idsp, 40960, 256, 8192, 64);
    // last decv layer + fused 192->1 output conv
    launch_block<32, 1, 128, true>(true, decH + 4 * PLN, decL + 4 * PLN, SS32,
                                   w1H + OFF1[10] + 20480, w1L + OFF1[10] + 20480,
                                   w2H + 11 * 4096, w2L + 11 * 4096,
                                   decv_b1 + 1 * 128, decv_b2 + 1 * 32,
                                   nullptr, nullptr, 0,
                                   idsp, 40960, 256, 8192, 64,
                                   decv_cw, decv_cb, out);
}

// round 16
// speedup vs baseline: 1.6824x; 1.0505x over previous
#include <cuda_runtime.h>
#include <cuda_bf16.h>

#define LLEN 1024
#define NB   64
#define PLN  (LLEN * 32)          // one 32-ch plane, elems
#define SS32 (6 * PLN)            // cat/dec sample stride (elems)
#define SSU  (LLEN * 64)          // encU sample stride

// ---- device scratch (no allocations allowed) ----
__device__ __nv_bfloat16 g_catH[NB * SS32], g_catL[NB * SS32];
__device__ __nv_bfloat16 g_decH[NB * SS32], g_decL[NB * SS32];
__device__ __nv_bfloat16 g_encUH[NB * SSU], g_encUL[NB * SSU];
__device__ __nv_bfloat16 g_w1H[378880], g_w1L[378880];
__device__ __nv_bfloat16 g_w2H[86016],  g_w2L[86016];
__device__ int g_ids[NB];

__constant__ int c_OFF1[18] = {
    0, 10240, 30720, 51200, 71680, 92160, 112640,
    153600, 174080, 194560,
    215040, 235520, 256000, 276480, 296960, 317440, 337920, 358400};

__device__ __forceinline__ void mma_bf16(float* c, const unsigned* a,
                                         unsigned b0, unsigned b1) {
    asm volatile(
        "mma.sync.aligned.m16n8k16.row.col.f32.bf16.bf16.f32 "
        "{%0,%1,%2,%3}, {%4,%5,%6,%7}, {%8,%9}, {%0,%1,%2,%3};\n"
        : "+f"(c[0]), "+f"(c[1]), "+f"(c[2]), "+f"(c[3])
        : "r"(a[0]), "r"(a[1]), "r"(a[2]), "r"(a[3]), "r"(b0), "r"(b1));
}
__device__ __forceinline__ void ldsm4(unsigned* r, unsigned addr) {
    asm volatile("ldmatrix.sync.aligned.m8n8.x4.shared.b16 {%0,%1,%2,%3}, [%4];\n"
                 : "=r"(r[0]), "=r"(r[1]), "=r"(r[2]), "=r"(r[3]) : "r"(addr));
}
__device__ __forceinline__ void ldsm2(unsigned* r, unsigned addr) {
    asm volatile("ldmatrix.sync.aligned.m8n8.x2.shared.b16 {%0,%1}, [%2];\n"
                 : "=r"(r[0]), "=r"(r[1]) : "r"(addr));
}
__device__ __forceinline__ void ldsm4t(unsigned* r, unsigned addr) {
    asm volatile("ldmatrix.sync.aligned.m8n8.x4.trans.shared.b16 {%0,%1,%2,%3}, [%4];\n"
                 : "=r"(r[0]), "=r"(r[1]), "=r"(r[2]), "=r"(r[3]) : "r"(addr));
}
__device__ __forceinline__ void ldsm2t(unsigned* r, unsigned addr) {
    asm volatile("ldmatrix.sync.aligned.m8n8.x2.trans.shared.b16 {%0,%1}, [%2];\n"
                 : "=r"(r[0]), "=r"(r[1]) : "r"(addr));
}
__device__ __forceinline__ unsigned su32(const void* p) {
    return (unsigned)__cvta_generic_to_shared(p);
}
__device__ __forceinline__ void cpa16(unsigned dst, const void* src) {
    asm volatile("cp.async.ca.shared.global [%0], [%1], 16;\n"
                 :: "r"(dst), "l"(src));
}
__device__ __forceinline__ void cpa16z(unsigned dst, const void* src, int sz) {
    asm volatile("cp.async.ca.shared.global [%0], [%1], 16, %2;\n"
                 :: "r"(dst), "l"(src), "r"(sz));
}
#define CP_COMMIT() asm volatile("cp.async.commit_group;\n" ::: "memory")
#define CP_WAIT0()  asm volatile("cp.async.wait_group 0;\n"  ::: "memory")

// PDL primitives (griddepcontrol)
__device__ __forceinline__ void pdl_trigger() {
    asm volatile("griddepcontrol.launch_dependents;");
}
__device__ __forceinline__ void pdl_wait() {
    asm volatile("griddepcontrol.wait;" ::: "memory");
}
__device__ __forceinline__ void pref_l2(const void* p) {
    asm volatile("prefetch.global.L2 [%0];" :: "l"(p));
}

__device__ __forceinline__ void split_bf16(float v, __nv_bfloat16& hi, __nv_bfloat16& lo) {
    hi = __float2bfloat16(v);
    lo = __float2bfloat16(v - __bfloat162float(hi));
}

// ------------------------------------------------------------------
// prep kernels: split weights into bf16 hi/lo planes, laid out in exact
// m16n8k16 A-fragment order so the mma kernels load them with LDG.128.
// w1 word index: ((((half*taps+t)*NK+kc)*2+wm)*2+mt)*128 + lane*4 + i
//   (taps=1,NK=1 for the folded enc0 layer; else taps=5, NK=CIN/16)
// fragment word (i): rows +8 for i&1, cols +8 for i>>1.
// ------------------------------------------------------------------
__global__ void prep_w1(const float* __restrict__ enc0, const float* __restrict__ enc,
                        const float* __restrict__ decf0, const float* __restrict__ decf,
                        const float* __restrict__ decv)
{
    int L = blockIdx.y;
    int e = blockIdx.x * 256 + threadIdx.x;      // word index within layer
    int cinv = (L == 0) ? 1 : ((L == 6) ? 64 : 32);
    int cinp = (L == 0) ? 16 : cinv;
    int NK   = cinp / 16;
    int taps = (L == 0) ? 1 : 5;
    int words = 2 * taps * NK * 512;
    if (e >= words) return;
    int i    = e & 3;
    int lane = (e >> 2) & 31;
    int blk  = e >> 7;
    int mt = blk & 1; blk >>= 1;
    int wm = blk & 1; blk >>= 1;
    int kc = blk % NK; blk /= NK;
    int t  = blk % taps;
    int half = blk / taps;
    int row  = half * 64 + wm * 32 + mt * 16 + (lane >> 2) + 8 * (i & 1);
    int colp = kc * 16 + 2 * (lane & 3) + 8 * (i >> 1);
    float v0, v1;
    if (L == 0) {
        v0 = (colp     < 5) ? enc0[(long)row * 5 + colp]     : 0.f;
        v1 = (colp + 1 < 5) ? enc0[(long)row * 5 + colp + 1] : 0.f;
    } else {
        const float* src;
        if (L <= 5) src = enc + (L - 1) * 20480;
        else if (L == 6) src = decf0;
        else if (L <= 9) src = decf + (L - 7) * 20480;
        else src = decv + (L - 10) * 20480;
        v0 = src[(long)row * (cinv * 5) + colp * 5 + t];
        v1 = src[(long)row * (cinv * 5) + (colp + 1) * 5 + t];
    }
    __nv_bfloat16 h0, l0, h1, l1;
    split_bf16(v0, h0, l0);
    split_bf16(v1, h1, l1);
    long off = c_OFF1[L] + 2 * (long)e;
    g_w1H[off] = h0;  g_w1H[off + 1] = h1;
    g_w1L[off] = l0;  g_w1L[off + 1] = l1;
}

// w2 (block layers 0..17): fragment order ((half*4+kc)*2+wm2)*128 + lane*4 + i
// L==18 (comp weights): element layout [co][192]. L==19: ids extraction.
__global__ void prep_w2(const float* __restrict__ enc0, const float* __restrict__ enc,
                        const float* __restrict__ decf0, const float* __restrict__ decf,
                        const float* __restrict__ decv, const float* __restrict__ comp,
                        const float* __restrict__ x)
{
    int L = blockIdx.y;
    int e = blockIdx.x * 256 + threadIdx.x;
    if (L == 19) {
        if (blockIdx.x == 0 && e < NB)
            g_ids[e] = (int)x[(long)e * (LLEN + 1) + LLEN];
        return;
    }
    if (L == 18) {
        if (e >= 12288) return;
        __nv_bfloat16 h, l; split_bf16(comp[e], h, l);
        g_w2H[73728 + e] = h;
        g_w2L[73728 + e] = l;
        return;
    }
    if (e >= 2048) return;   // words
    const float* src;
    if (L == 0) src = enc0;
    else if (L <= 5) src = enc + (L - 1) * 4096;
    else if (L == 6) src = decf0;
    else if (L <= 9) src = decf + (L - 7) * 4096;
    else src = decv + (L - 10) * 4096;
    int i    = e & 3;
    int lane = (e >> 2) & 31;
    int blk  = e >> 7;
    int wm2 = blk & 1; blk >>= 1;
    int kc  = blk & 3;
    int half = blk >> 2;
    int row = wm2 * 16 + (lane >> 2) + 8 * (i & 1);
    int col = half * 64 + kc * 16 + 2 * (lane & 3) + 8 * (i >> 1);
    __nv_bfloat16 h0, l0, h1, l1;
    split_bf16(src[row * 128 + col], h0, l0);
    split_bf16(src[row * 128 + col + 1], h1, l1);
    long off = (long)L * 4096 + 2 * e;
    g_w2H[off] = h0;  g_w2H[off + 1] = h1;
    g_w2L[off] = l0;  g_w2L[off + 1] = l1;
}

// ------------------------------------------------------------------
// Fused TCN block. Weights arrive as pre-arranged mma fragments (LDG.128,
// no smem staging, no barriers in the tap loop). x staged via cp.async
// (zero-fill halo). hs in [co][l]; conv2 B via ldmatrix.trans. PDL.
// CIN==1 (FOLD): taps folded into K=16.
// FINAL: last decv layer + fused 192->1 output conv.
// 512 thr = 16 warps, 2 CTAs/SM.
// ------------------------------------------------------------------
template<int CIN, int DIL, int TIL, bool FINAL = false>
__global__ void __launch_bounds__(512, 2)
block_mma_kernel(const void* __restrict__ xHv, const void* __restrict__ xLv, long xss,
                 const __nv_bfloat16* __restrict__ w1Hg, const __nv_bfloat16* __restrict__ w1Lg,
                 const __nv_bfloat16* __restrict__ w2Hg, const __nv_bfloat16* __restrict__ w2Lg,
                 const float* __restrict__ b1, const float* __restrict__ b2,
                 __nv_bfloat16* __restrict__ yH, __nv_bfloat16* __restrict__ yL, long yss,
                 const int* __restrict__ ids,
                 long w1_cs, long b1_cs, long w2_cs, long b2_cs,
                 const float* __restrict__ fcw, const float* __restrict__ fcb,
                 float* __restrict__ fout)
{
    constexpr bool FOLD = (CIN == 1);
    constexpr int CINP = FOLD ? 16 : CIN;
    constexpr int XW   = FOLD ? TIL : (TIL + 4 * DIL);
    constexpr int NK   = CINP / 16;
    constexpr int TAPS = FOLD ? 1 : 5;
    constexpr int SB   = CINP + 8;       // xt row stride (bf16)
    constexpr int SHS  = TIL + 8;        // hs row stride (co-major)
    constexpr int NT   = TIL / 64;
    constexpr int SF   = TIL + 4;        // final fp32 plane5 row stride
    constexpr int W1W  = 2 * TAPS * NK * 512;   // w1 words per layer

    extern __shared__ __nv_bfloat16 smb[];
    __nv_bfloat16* xtH = smb;
    __nv_bfloat16* xtL = xtH + XW * SB;
    __nv_bfloat16* hH  = xtL + XW * SB;        // [64 co][SHS]
    __nv_bfloat16* hL  = hH  + 64 * SHS;
    float* b1s = (float*)(hL + 64 * SHS);      // 128
    float* b2s = b1s + 128;                    // 32
    float* wfs = b2s + 32;                     // 192 (FINAL weights)

    const int b    = blockIdx.y;
    const int l0   = blockIdx.x * TIL;
    const int tid  = threadIdx.x;
    const int warp = tid >> 5;
    const int ln   = tid & 31;
    const int lq   = ln & 3;
    const int lg   = ln >> 2;
    const int lr   = ln & 7;
    const int lt   = ln >> 3;

    const __nv_bfloat16* w1Hp = w1Hg;
    const __nv_bfloat16* w1Lp = w1Lg;
    const __nv_bfloat16* w2Hp = w2Hg;
    const __nv_bfloat16* w2Lp = w2Lg;
    const float* b1p = b1;
    const float* b2p = b2;
    int cid = 0;
    if (ids) {   // g_ids is a prep output (complete before any PDL kernel)
        cid = ids[b];
        w1Hp += (long)cid * w1_cs;  w1Lp += (long)cid * w1_cs;
        w2Hp += (long)cid * w2_cs;  w2Lp += (long)cid * w2_cs;
        b1p  += (long)cid * b1_cs;  b2p  += (long)cid * b2_cs;
    }

    pdl_trigger();

    // ---- pre-wait prologue: biases + L2 prefetch of weight fragments ----
    if (tid < 128) b1s[tid] = b1p[tid];
    if (tid < 32)  b2s[tid] = b2p[tid];
    for (long off = (long)tid * 128; off < (long)W1W * 4; off += 512 * 128) {
        pref_l2((const char*)w1Hp + off);
        pref_l2((const char*)w1Lp + off);
    }
    if (tid < 64) {
        pref_l2((const char*)w2Hp + tid * 128);
        pref_l2((const char*)w2Lp + tid * 128);
    }

    pdl_wait();      // previous layer's activations complete

    // ---- stage x (async; zero-fill halo) ----
    if constexpr (FOLD) {
        const float* xf = (const float*)xHv + (long)b * xss;
        for (int i = tid; i < TIL * 16; i += 512) {
            int r = i >> 4, k = i & 15;
            int pos = l0 - 2 * DIL + r + k * DIL;
            float v = (k < 5 && pos >= 0 && pos < LLEN) ? xf[pos] : 0.f;
            __nv_bfloat16 hv, lv; split_bf16(v, hv, lv);
            xtH[r * SB + k] = hv;
            xtL[r * SB + k] = lv;
        }
    } else {
        constexpr int WR  = CIN / 2;       // words per row
        constexpr int RCH = WR / 4;        // 16B chunks per row
        const char* xbH = (const char*)((const __nv_bfloat16*)xHv + (long)b * xss);
        const char* xbL = (const char*)((const __nv_bfloat16*)xLv + (long)b * xss);
        for (int i = tid; i < XW * RCH * 2; i += 512) {
            int pl = i / (XW * RCH);
            int q  = i - pl * (XW * RCH);
            int r  = q / RCH, ck = q - r * RCH;
            int pos = l0 - 2 * DIL + r;
            bool ok = (pos >= 0 && pos < LLEN);
            const char* src = (pl ? xbL : xbH) + ((long)(ok ? pos : 0) * WR + ck * 4) * 4;
            unsigned dst = su32((pl ? xtL : xtH) + r * SB) + ck * 16;
            cpa16z(dst, src, ok ? 16 : 0);
        }
    }
    CP_COMMIT(); CP_WAIT0();
    __syncthreads();

    const int wm  = warp >> 3;
    const int wn  = warp & 7;
    const int wm2 = warp & 1;
    const int wn2 = warp >> 1;

    const uint4* f1H = (const uint4*)w1Hp;
    const uint4* f1L = (const uint4*)w1Lp;
    const uint4* f2H = (const uint4*)w2Hp;
    const uint4* f2L = (const uint4*)w2Lp;

    float a2[NT][4];
    #pragma unroll
    for (int nt = 0; nt < NT; nt++)
        #pragma unroll
        for (int q = 0; q < 4; q++) a2[nt][q] = 0.f;

    #pragma unroll
    for (int half = 0; half < 2; half++) {
        const int coB = half * 64;

        float acc[2][NT][4];
        #pragma unroll
        for (int mt = 0; mt < 2; mt++)
            #pragma unroll
            for (int nt = 0; nt < NT; nt++)
                #pragma unroll
                for (int q = 0; q < 4; q++) acc[mt][nt][q] = 0.f;

        // ---- conv1: barrier-free fragment mainloop ----
        #pragma unroll
        for (int t = 0; t < TAPS; t++) {
            #pragma unroll
            for (int kc = 0; kc < NK; kc++) {
                const int base = (((half * TAPS + t) * NK + kc) * 2 + wm) * 2;
                uint4 AH0 = f1H[(base + 0) * 32 + ln];
                uint4 AH1 = f1H[(base + 1) * 32 + ln];
                uint4 AL0 = f1L[(base + 0) * 32 + ln];
                uint4 AL1 = f1L[(base + 1) * 32 + ln];
                unsigned bh[4], bl[4];
                if (NT == 2) {
                    int brow = wn * 16 + lr + (lt & 1) * 8 + t * DIL;
                    int bcol = kc * 16 + (lt >> 1) * 8;
                    ldsm4(bh, su32(xtH + brow * SB + bcol));
                    ldsm4(bl, su32(xtL + brow * SB + bcol));
                } else {
                    int brow = wn * 8 + lr + t * DIL;
                    int bcol = kc * 16 + ((ln >> 3) & 1) * 8;
                    ldsm2(bh, su32(xtH + brow * SB + bcol));
                    ldsm2(bl, su32(xtL + brow * SB + bcol));
                }
                #pragma unroll
                for (int nt = 0; nt < NT; nt++) {
                    unsigned bh0 = (NT == 2) ? bh[nt] : bh[0];
                    unsigned bh1 = (NT == 2) ? bh[nt + 2] : bh[1];
                    unsigned bl0 = (NT == 2) ? bl[nt] : bl[0];
                    unsigned bl1 = (NT == 2) ? bl[nt + 2] : bl[1];
                    mma_bf16(acc[0][nt], (unsigned*)&AH0, bh0, bh1);
                    mma_bf16(acc[0][nt], (unsigned*)&AH0, bl0, bl1);
                    mma_bf16(acc[0][nt], (unsigned*)&AL0, bh0, bh1);
                    mma_bf16(acc[1][nt], (unsigned*)&AH1, bh0, bh1);
                    mma_bf16(acc[1][nt], (unsigned*)&AH1, bl0, bl1);
                    mma_bf16(acc[1][nt], (unsigned*)&AL1, bh0, bh1);
                }
            }
        }

        // ---- conv1 epilogue: bias + relu + split -> hs [co][l], packed ----
        if (half == 1) __syncthreads();   // prev half's conv2 hs reads done
        #pragma unroll
        for (int mt = 0; mt < 2; mt++) {
            int m = wm * 32 + mt * 16 + lg;      // local co (0..63)
            float bb0 = b1s[coB + m], bb1 = b1s[coB + m + 8];
            #pragma unroll
            for (int nt = 0; nt < NT; nt++) {
                int n = ((NT == 2) ? wn * 16 + nt * 8 : wn * 8) + 2 * lq;
                float* a = acc[mt][nt];
                float v00 = a[0] + bb0, v01 = a[1] + bb0;
                float v10 = a[2] + bb1, v11 = a[3] + bb1;
                v00 = v00 > 0.f ? v00 : 0.f;  v01 = v01 > 0.f ? v01 : 0.f;
                v10 = v10 > 0.f ? v10 : 0.f;  v11 = v11 > 0.f ? v11 : 0.f;
                __nv_bfloat16 h0, l0h, h1, l1h;
                split_bf16(v00, h0, l0h); split_bf16(v01, h1, l1h);
                *(__nv_bfloat162*)(hH + m * SHS + n) = __halves2bfloat162(h0, h1);
                *(__nv_bfloat162*)(hL + m * SHS + n) = __halves2bfloat162(l0h, l1h);
                split_bf16(v10, h0, l0h); split_bf16(v11, h1, l1h);
                *(__nv_bfloat162*)(hH + (m + 8) * SHS + n) = __halves2bfloat162(h0, h1);
                *(__nv_bfloat162*)(hL + (m + 8) * SHS + n) = __halves2bfloat162(l0h, l1h);
            }
        }
        __syncthreads();

        // ---- conv2 partial: A fragments via LDG, B via ldmatrix.trans ----
        #pragma unroll
        for (int kc = 0; kc < 4; kc++) {
            const int bi = (half * 4 + kc) * 2 + wm2;
            uint4 AH = f2H[bi * 32 + ln];
            uint4 AL = f2L[bi * 32 + ln];
            unsigned bh[4], bl[4];
            if (NT == 2) {
                int brow = kc * 16 + (lt & 1) * 8 + lr;     // k (local co)
                int bcol = wn2 * 16 + (lt >> 1) * 8;        // n (l)
                ldsm4t(bh, su32(hH + brow * SHS + bcol));
                ldsm4t(bl, su32(hL + brow * SHS + bcol));
            } else {
                int brow = kc * 16 + ((ln >> 3) & 1) * 8 + lr;
                int bcol = wn2 * 8;
                ldsm2t(bh, su32(hH + brow * SHS + bcol));
                ldsm2t(bl, su32(hL + brow * SHS + bcol));
            }
            #pragma unroll
            for (int nt = 0; nt < NT; nt++) {
                unsigned bh0 = (NT == 2) ? bh[2 * nt]     : bh[0];
                unsigned bh1 = (NT == 2) ? bh[2 * nt + 1] : bh[1];
                unsigned bl0 = (NT == 2) ? bl[2 * nt]     : bl[0];
                unsigned bl1 = (NT == 2) ? bl[2 * nt + 1] : bl[1];
                mma_bf16(a2[nt], (unsigned*)&AH, bh0, bh1);
                mma_bf16(a2[nt], (unsigned*)&AH, bl0, bl1);
                mma_bf16(a2[nt], (unsigned*)&AL, bh0, bh1);
            }
        }
    }

    if constexpr (!FINAL) {
        // ---- conv2 epilogue: bias + relu + split -> y planes [l][co] ----
        __nv_bfloat16* yHb = yH + (long)b * yss;
        __nv_bfloat16* yLb = yL + (long)b * yss;
        int row = wm2 * 16 + lg;
        float bb0 = b2s[row], bb1 = b2s[row + 8];
        #pragma unroll
        for (int nt = 0; nt < NT; nt++) {
            int col = ((NT == 2) ? wn2 * 16 + nt * 8 : wn2 * 8) + 2 * lq;
            float v0 = a2[nt][0] + bb0, v1 = a2[nt][1] + bb0;
            float v2 = a2[nt][2] + bb1, v3 = a2[nt][3] + bb1;
            v0 = v0 > 0.f ? v0 : 0.f;  v1 = v1 > 0.f ? v1 : 0.f;
            v2 = v2 > 0.f ? v2 : 0.f;  v3 = v3 > 0.f ? v3 : 0.f;
            __nv_bfloat16 hv, lv;
            split_bf16(v0, hv, lv);
            yHb[(long)(l0 + col) * 32 + row] = hv;       yLb[(long)(l0 + col) * 32 + row] = lv;
            split_bf16(v1, hv, lv);
            yHb[(long)(l0 + col + 1) * 32 + row] = hv;   yLb[(long)(l0 + col + 1) * 32 + row] = lv;
            split_bf16(v2, hv, lv);
            yHb[(long)(l0 + col) * 32 + row + 8] = hv;   yLb[(long)(l0 + col) * 32 + row + 8] = lv;
            split_bf16(v3, hv, lv);
            yHb[(long)(l0 + col + 1) * 32 + row + 8] = hv; yLb[(long)(l0 + col + 1) * 32 + row + 8] = lv;
        }
    } else {
        // ---- FINAL: plane5 -> smem fp32, then 192->1 output conv ----
        __syncthreads();                // conv2 hs reads done before reuse
        float* ps = (float*)hH;         // [32 co][SF] fp32 plane5 tile
        {
            int row = wm2 * 16 + lg;
            float bb0 = b2s[row], bb1 = b2s[row + 8];
            #pragma unroll
            for (int nt = 0; nt < NT; nt++) {
                int col = ((NT == 2) ? wn2 * 16 + nt * 8 : wn2 * 8) + 2 * lq;
                float v0 = a2[nt][0] + bb0, v1 = a2[nt][1] + bb0;
                float v2 = a2[nt][2] + bb1, v3 = a2[nt][3] + bb1;
                ps[row * SF + col]           = v0 > 0.f ? v0 : 0.f;
                ps[row * SF + col + 1]       = v1 > 0.f ? v1 : 0.f;
                ps[(row + 8) * SF + col]     = v2 > 0.f ? v2 : 0.f;
                ps[(row + 8) * SF + col + 1] = v3 > 0.f ? v3 : 0.f;
            }
        }
        if (tid < 192) wfs[tid] = fcw[(long)cid * 192 + tid];
        __syncthreads();

        if (tid < TIL) {
            int l = tid;
            float s = fcb[cid];
            const __nv_bfloat16* dH = (const __nv_bfloat16*)xHv + (long)b * xss - 4 * PLN;
            const __nv_bfloat16* dL = (const __nv_bfloat16*)xLv + (long)b * xss - 4 * PLN;
            #pragma unroll
            for (int plane = 0; plane < 5; plane++) {
                const unsigned* pH = (const unsigned*)(dH + (long)plane * PLN + (long)(l0 + l) * 32);
                const unsigned* pL = (const unsigned*)(dL + (long)plane * PLN + (long)(l0 + l) * 32);
                #pragma unroll
                for (int w = 0; w < 16; w++) {
                    unsigned uh = pH[w], ul = pL[w];
                    float2 fh = __bfloat1622float2(*(const __nv_bfloat162*)&uh);
                    float2 fl = __bfloat1622float2(*(const __nv_bfloat162*)&ul);
                    s = fmaf(wfs[plane * 32 + 2 * w],     fh.x + fl.x, s);
                    s = fmaf(wfs[plane * 32 + 2 * w + 1], fh.y + fl.y, s);
                }
            }
            #pragma unroll
            for (int ch = 0; ch < 32; ch++)
                s = fmaf(wfs[160 + ch], ps[ch * SF + l], s);
            fout[(long)b * LLEN + l0 + l] = s;
        }
    }
}

// ------------------------------------------------------------------
// compress conv (192 -> 64) + avgpool(2) + nearest-upsample(2), mma, PDL.
// ------------------------------------------------------------------
#define CTILE 64
__global__ void __launch_bounds__(512, 2)
comp_mma_kernel(const __nv_bfloat16* __restrict__ catH, const __nv_bfloat16* __restrict__ catL,
                const float* __restrict__ cb,
                __nv_bfloat16* __restrict__ uH, __nv_bfloat16* __restrict__ uL)
{
    constexpr int SA = 200;

    extern __shared__ __nv_bfloat16 smb[];
    __nv_bfloat16* xtH = smb;                  // [64 l][200]
    __nv_bfloat16* xtL = xtH + 64 * SA;
    __nv_bfloat16* waH = xtL + 64 * SA;        // [64 co][200]
    __nv_bfloat16* waL = waH + 64 * SA;
    float* cbs = (float*)(waL + 64 * SA);

    const int b    = blockIdx.y;
    const int l0   = blockIdx.x * CTILE;
    const int tid  = threadIdx.x;
    const int warp = tid >> 5;
    const int ln   = tid & 31;
    const int lq   = ln & 3;
    const int lg   = ln >> 2;
    const int lr   = ln & 7;
    const int lt   = ln >> 3;
    const int wm   = warp & 3;
    const int wn   = warp >> 2;

    pdl_trigger();

    // weights first (prep outputs — safe pre-wait)
    {
        const char* sH = (const char*)(g_w2H + 73728);
        const char* sL = (const char*)(g_w2L + 73728);
        for (int i = tid; i < 64 * 24 * 2; i += 512) {
            int pl = i / (64 * 24);
            int q  = i - pl * (64 * 24);
            int co = q / 24, ck = q - co * 24;
            unsigned dst = su32((pl ? waL : waH) + co * SA) + ck * 16;
            cpa16(dst, (pl ? sL : sH) + (co * 96 + ck * 4) * 4);
        }
    }
    if (tid < 64) cbs[tid] = cb[tid];

    pdl_wait();

    const char* cbH = (const char*)(catH + (long)b * SS32);
    const char* cbL = (const char*)(catL + (long)b * SS32);
    for (int i = tid; i < 64 * 24 * 2; i += 512) {
        int pl = i / (64 * 24);
        int q  = i - pl * (64 * 24);
        int r  = q / 24, ck = q - r * 24;
        int plane = ck / 4, wi = ck - plane * 4;
        long srcoff = ((long)plane * (PLN / 2) + (long)(l0 + r) * 16 + wi * 4) * 4;
        unsigned dst = su32((pl ? xtL : xtH) + r * SA) + (plane * 16 + wi * 4) * 4;
        cpa16(dst, (pl ? cbL : cbH) + srcoff);
    }
    CP_COMMIT(); CP_WAIT0();
    __syncthreads();

    float acc[2][4];
    #pragma unroll
    for (int nt = 0; nt < 2; nt++)
        #pragma unroll
        for (int q = 0; q < 4; q++) acc[nt][q] = 0.f;

    #pragma unroll
    for (int kc = 0; kc < 12; kc++) {
        unsigned ah[4], al[4];
        {
            int arow = wm * 16 + lr + (lt & 1) * 8;
            int acol = kc * 16 + (lt >> 1) * 8;
            ldsm4(ah, su32(waH + arow * SA + acol));
            ldsm4(al, su32(waL + arow * SA + acol));
        }
        unsigned bh[4], bl[4];
        {
            int brow = wn * 16 + lr + (lt & 1) * 8;
            int bcol = kc * 16 + (lt >> 1) * 8;
            ldsm4(bh, su32(xtH + brow * SA + bcol));
            ldsm4(bl, su32(xtL + brow * SA + bcol));
        }
        #pragma unroll
        for (int nt = 0; nt < 2; nt++) {
            mma_bf16(acc[nt], ah, bh[nt], bh[nt + 2]);
            mma_bf16(acc[nt], ah, bl[nt], bl[nt + 2]);
            mma_bf16(acc[nt], al, bh[nt], bh[nt + 2]);
        }
    }

    __nv_bfloat16* uHb = uH + (long)b * SSU;
    __nv_bfloat16* uLb = uL + (long)b * SSU;
    {
        int m = wm * 16 + lg;
        float bb0 = cbs[m], bb1 = cbs[m + 8];
        #pragma unroll
        for (int nt = 0; nt < 2; nt++) {
            int n = wn * 16 + nt * 8 + 2 * lq;
            float* a = acc[nt];
            float p0 = 0.5f * ((a[0] + bb0) + (a[1] + bb0));
            float p1 = 0.5f * ((a[2] + bb1) + (a[3] + bb1));
            __nv_bfloat16 hv, lv;
            split_bf16(p0, hv, lv);
            uHb[(long)(l0 + n) * 64 + m] = hv;      uHb[(long)(l0 + n + 1) * 64 + m] = hv;
            uLb[(long)(l0 + n) * 64 + m] = lv;      uLb[(long)(l0 + n + 1) * 64 + m] = lv;
            split_bf16(p1, hv, lv);
            uHb[(long)(l0 + n) * 64 + m + 8] = hv;  uHb[(long)(l0 + n + 1) * 64 + m + 8] = hv;
            uLb[(long)(l0 + n) * 64 + m + 8] = lv;  uLb[(long)(l0 + n + 1) * 64 + m + 8] = lv;
        }
    }
}

// ------------------------------------------------------------------
static constexpr int smem_mma(int cin, int dil, int til) {
    bool fold = (cin == 1);
    int cinp = fold ? 16 : cin;
    int sb   = cinp + 8;
    int xw   = fold ? til : (til + 4 * dil);
    int elems = 2 * xw * sb + 2 * 64 * (til + 8);
    return elems * 2 + (160 + 192) * 4;
}
static constexpr int SMEM_C = (4 * 64 * 200) * 2 + 256;

template<int CIN, int DIL, int TIL, bool FINAL = false>
static void launch_block(bool pdl,
                         const void* xH, const void* xL, long xss,
                         const __nv_bfloat16* w1H, const __nv_bfloat16* w1L,
                         const __nv_bfloat16* w2H, const __nv_bfloat16* w2L,
                         const float* b1, const float* b2,
                         __nv_bfloat16* yH, __nv_bfloat16* yL, long yss,
                         const int* ids, long w1cs, long b1cs, long w2cs, long b2cs,
                         const float* fcw = nullptr, const float* fcb = nullptr,
                         float* fout = nullptr)
{
    static bool attr_done = false;
    if (!attr_done) {
        cudaFuncSetAttribute(block_mma_kernel<CIN, DIL, TIL, FINAL>,
                             cudaFuncAttributeMaxDynamicSharedMemorySize,
                             smem_mma(CIN, DIL, TIL));
        attr_done = true;
    }
    cudaLaunchConfig_t cfg = {};
    cfg.gridDim = dim3(LLEN / TIL, NB, 1);
    cfg.blockDim = dim3(512, 1, 1);
    cfg.dynamicSmemBytes = smem_mma(CIN, DIL, TIL);
    cfg.stream = 0;
    cudaLaunchAttribute at;
    at.id = cudaLaunchAttributeProgrammaticStreamSerialization;
    at.val.programmaticStreamSerializationAllowed = 1;
    cfg.attrs = &at;
    cfg.numAttrs = pdl ? 1 : 0;
    cudaLaunchKernelEx(&cfg, block_mma_kernel<CIN, DIL, TIL, FINAL>,
                       xH, xL, xss, w1H, w1L, w2H, w2L, b1, b2, yH, yL, yss,
                       ids, w1cs, b1cs, w2cs, b2cs, fcw, fcb, fout);
}

extern "C" void kernel_launch(void* const* d_in, const int* in_sizes, int n_in,
                              void* d_out, int out_size)
{
    const float* x        = (const float*)d_in[0];
    const float* enc0_b1  = (const float*)d_in[2];
    const float* enc0_b2  = (const float*)d_in[4];
    const float* enc_b1   = (const float*)d_in[6];
    const float* enc_b2   = (const float*)d_in[8];
    const float* comp_b   = (const float*)d_in[10];
    const float* decf0_b1 = (const float*)d_in[12];
    const float* decf0_b2 = (const float*)d_in[14];
    const float* decf_b1  = (const float*)d_in[16];
    const float* decf_b2  = (const float*)d_in[18];
    const float* decv_b1  = (const float*)d_in[20];
    const float* decv_b2  = (const float*)d_in[22];
    const float* decv_cw  = (const float*)d_in[23];
    const float* decv_cb  = (const float*)d_in[24];
    float* out = (float*)d_out;

    __nv_bfloat16 *catH, *catL, *decH, *decL, *uH, *uL, *w1H, *w1L, *w2H, *w2L;
    int* idsp;
    cudaGetSymbolAddress((void**)&catH, g_catH);
    cudaGetSymbolAddress((void**)&catL, g_catL);
    cudaGetSymbolAddress((void**)&decH, g_decH);
    cudaGetSymbolAddress((void**)&decL, g_decL);
    cudaGetSymbolAddress((void**)&uH,   g_encUH);
    cudaGetSymbolAddress((void**)&uL,   g_encUL);
    cudaGetSymbolAddress((void**)&w1H,  g_w1H);
    cudaGetSymbolAddress((void**)&w1L,  g_w1L);
    cudaGetSymbolAddress((void**)&w2H,  g_w2H);
    cudaGetSymbolAddress((void**)&w2L,  g_w2L);
    cudaGetSymbolAddress((void**)&idsp, g_ids);

    static bool comp_attr = false;
    if (!comp_attr) {
        cudaFuncSetAttribute(comp_mma_kernel,
                             cudaFuncAttributeMaxDynamicSharedMemorySize, SMEM_C);
        comp_attr = true;
    }

    {
        dim3 g1(160, 18);
        prep_w1<<<g1, 256>>>((const float*)d_in[1], (const float*)d_in[5],
                             (const float*)d_in[11], (const float*)d_in[15],
                             (const float*)d_in[19]);
        dim3 g2(48, 20);
        prep_w2<<<g2, 256>>>((const float*)d_in[3], (const float*)d_in[7],
                             (const float*)d_in[13], (const float*)d_in[17],
                             (const float*)d_in[21], (const float*)d_in[9], x);
    }

    static const int OFF1[18] = {
        0, 10240, 30720, 51200, 71680, 92160, 112640,
        153600, 174080, 194560,
        215040, 235520, 256000, 276480, 296960, 317440, 337920, 358400};

    // ---- encoder (enc0 non-PDL: anchors prep completion) ----
    launch_block<1, 1, 128>(false, x, nullptr, (long)(LLEN + 1),
                            w1H + OFF1[0], w1L + OFF1[0], w2H + 0, w2L + 0,
                            enc0_b1, enc0_b2,
                            catH, catL, SS32, nullptr, 0, 0, 0, 0);
    launch_block<32, 2, 128>(true, catH + 0 * PLN, catL + 0 * PLN, SS32,
                             w1H + OFF1[1], w1L + OFF1[1], w2H + 1 * 4096, w2L + 1 * 4096,
                             enc_b1 + 0 * 128, enc_b2 + 0 * 32,
                             catH + 1 * PLN, catL + 1 * PLN, SS32, nullptr, 0, 0, 0, 0);
    launch_block<32, 4, 128>(true, catH + 1 * PLN, catL + 1 * PLN, SS32,
                             w1H + OFF1[2], w1L + OFF1[2], w2H + 2 * 4096, w2L + 2 * 4096,
                             enc_b1 + 1 * 128, enc_b2 + 1 * 32,
                             catH + 2 * PLN, catL + 2 * PLN, SS32, nullptr, 0, 0, 0, 0);
    launch_block<32, 8, 128>(true, catH + 2 * PLN, catL + 2 * PLN, SS32,
                             w1H + OFF1[3], w1L + OFF1[3], w2H + 3 * 4096, w2L + 3 * 4096,
                             enc_b1 + 2 * 128, enc_b2 + 2 * 32,
                             catH + 3 * PLN, catL + 3 * PLN, SS32, nullptr, 0, 0, 0, 0);
    launch_block<32, 16, 128>(true, catH + 3 * PLN, catL + 3 * PLN, SS32,
                              w1H + OFF1[4], w1L + OFF1[4], w2H + 4 * 4096, w2L + 4 * 4096,
                              enc_b1 + 3 * 128, enc_b2 + 3 * 32,
                              catH + 4 * PLN, catL + 4 * PLN, SS32, nullptr, 0, 0, 0, 0);
    launch_block<32, 32, 64>(true, catH + 4 * PLN, catL + 4 * PLN, SS32,
                             w1H + OFF1[5], w1L + OFF1[5], w2H + 5 * 4096, w2L + 5 * 4096,
                             enc_b1 + 4 * 128, enc_b2 + 4 * 32,
                             catH + 5 * PLN, catL + 5 * PLN, SS32, nullptr, 0, 0, 0, 0);

    // ---- compress + pool + upsample (PDL) ----
    {
        cudaLaunchConfig_t cfg = {};
        cfg.gridDim = dim3(LLEN / CTILE, NB, 1);
        cfg.blockDim = dim3(512, 1, 1);
        cfg.dynamicSmemBytes = SMEM_C;
        cfg.stream = 0;
        cudaLaunchAttribute at;
        at.id = cudaLaunchAttributeProgrammaticStreamSerialization;
        at.val.programmaticStreamSerializationAllowed = 1;
        cfg.attrs = &at;
        cfg.numAttrs = 1;
        cudaLaunchKernelEx(&cfg, comp_mma_kernel,
                           (const __nv_bfloat16*)catH, (const __nv_bfloat16*)catL,
                           comp_b, uH, uL);
    }

    // ---- fixed decoder ----
    launch_block<64, 32, 64>(true, uH, uL, (long)SSU,
                             w1H + OFF1[6], w1L + OFF1[6], w2H + 6 * 4096, w2L + 6 * 4096,
                             decf0_b1, decf0_b2,
                             decH, decL, SS32, nullptr, 0, 0, 0, 0);
    launch_block<32, 16, 128>(true, decH + 0 * PLN, decL + 0 * PLN, SS32,
                              w1H + OFF1[7], w1L + OFF1[7], w2H + 7 * 4096, w2L + 7 * 4096,
                              decf_b1 + 0 * 128, decf_b2 + 0 * 32,
                              decH + 1 * PLN, decL + 1 * PLN, SS32, nullptr, 0, 0, 0, 0);
    launch_block<32, 8, 128>(true, decH + 1 * PLN, decL + 1 * PLN, SS32,
                             w1H + OFF1[8], w1L + OFF1[8], w2H + 8 * 4096, w2L + 8 * 4096,
                             decf_b1 + 1 * 128, decf_b2 + 1 * 32,
                             decH + 2 * PLN, decL + 2 * PLN, SS32, nullptr, 0, 0, 0, 0);
    launch_block<32, 4, 128>(true, decH + 2 * PLN, decL + 2 * PLN, SS32,
                             w1H + OFF1[9], w1L + OFF1[9], w2H + 9 * 4096, w2L + 9 * 4096,
                             decf_b1 + 2 * 128, decf_b2 + 2 * 32,
                             decH + 3 * PLN, decL + 3 * PLN, SS32, nullptr, 0, 0, 0, 0);

    // ---- variable decoder (per-sample weights) ----
    launch_block<32, 2, 128>(true, decH + 3 * PLN, decL + 3 * PLN, SS32,
                             w1H + OFF1[10], w1L + OFF1[10],
                             w2H + 10 * 4096, w2L + 10 * 4096,
                             decv_b1 + 0 * 128, decv_b2 + 0 * 32,
                             decH + 4 * PLN, decL + 4 * PLN, SS32,
                             idsp, 40960, 256, 8192, 64);
    // last decv layer + fused 192->1 output conv
    launch_block<32, 1, 128, true>(true, decH + 4 * PLN, decL + 4 * PLN, SS32,
                                   w1H + OFF1[10] + 20480, w1L + OFF1[10] + 20480,
                                   w2H + 11 * 4096, w2L + 11 * 4096,
                                   decv_b1 + 1 * 128, decv_b2 + 1 * 32,
                                   nullptr, nullptr, 0,
                                   idsp, 40960, 256, 8192, 64,
                                   decv_cw, decv_cb, out);
}